// round 1
// baseline (speedup 1.0000x reference)
#include <cuda_runtime.h>
#include <math.h>

#define D_MODEL 1024
#define BATCH   4
#define SEQ     1024
#define NHEADS  16
#define HDIM    64
#define HMLP    4096
#define ROWS    (BATCH*SEQ)     // 4096

// ---------------- scratch (device globals; no allocs allowed) ----------------
__device__ float g_ln   [ROWS * D_MODEL];          // layernorm output (reused ln1/ln2)
__device__ float g_qkv  [ROWS * 3 * D_MODEL];      // qkv projection
__device__ float g_kv   [ROWS * 2 * D_MODEL];      // kv projection (from z)
__device__ float g_attn [ROWS * D_MODEL];          // self-attn context (pre-W_o)
__device__ float g_q    [ROWS * D_MODEL];          // q = x + self_mha(ln1(x))
__device__ float g_cross[ROWS * D_MODEL];          // cross-attn output
__device__ float g_mlp  [ROWS * HMLP];             // gelu(h@w_m1+b_m1)
__device__ float g_scores[(size_t)BATCH * NHEADS * SEQ * SEQ];  // 268MB, reused

// ---------------- helpers ----------------
__device__ __forceinline__ float gelu_tanh(float c) {
    // JAX default: approximate=True (tanh form)
    float t = 0.7978845608028654f * (c + 0.044715f * c * c * c);
    return 0.5f * c * (1.0f + tanhf(t));
}

// ---------------- layernorm: one block per row ----------------
__global__ void ln_kernel(const float* __restrict__ x, const float* __restrict__ g,
                          const float* __restrict__ b, float* __restrict__ out) {
    int row = blockIdx.x;
    const float* xr = x + (size_t)row * D_MODEL;
    float* orow = out + (size_t)row * D_MODEL;
    int tid = threadIdx.x;
    float s = 0.f, s2 = 0.f;
    for (int i = tid; i < D_MODEL; i += 256) {
        float v = xr[i]; s += v; s2 += v * v;
    }
    __shared__ float red[256], red2[256];
    red[tid] = s; red2[tid] = s2; __syncthreads();
    for (int o = 128; o > 0; o >>= 1) {
        if (tid < o) { red[tid] += red[tid + o]; red2[tid] += red2[tid + o]; }
        __syncthreads();
    }
    float mu  = red[0]  * (1.0f / D_MODEL);
    float var = red2[0] * (1.0f / D_MODEL) - mu * mu;
    float inv = rsqrtf(var + 1e-5f);
    for (int i = tid; i < D_MODEL; i += 256)
        orow[i] = (xr[i] - mu) * inv * g[i] + b[i];
}

// ---------------- SGEMM 128x128x8, 256 threads, 8x8 per thread ----------------
// C[M,N] = A[M,K] @ B[K,N] + bias[N]; act: 0=none, 1=gelu; res: optional residual add
__global__ void gemm128(const float* __restrict__ A, const float* __restrict__ B,
                        const float* __restrict__ bias, const float* __restrict__ res,
                        float* __restrict__ C, int M, int N, int K, int act) {
    __shared__ float As[8][128];
    __shared__ float Bs[8][128];

    int tid = threadIdx.x;
    int n0 = blockIdx.x * 128;
    int m0 = blockIdx.y * 128;

    int ar = tid >> 1;               // 0..127
    int ac = (tid & 1) * 4;          // 0 or 4
    int br = tid >> 5;               // 0..7
    int bc = (tid & 31) * 4;         // 0..124

    const float* Ap = A + (size_t)(m0 + ar) * K + ac;
    const float* Bp = B + (size_t)br * N + n0 + bc;

    float acc[8][8];
    #pragma unroll
    for (int i = 0; i < 8; i++)
        #pragma unroll
        for (int j = 0; j < 8; j++) acc[i][j] = 0.f;

    int ty = tid >> 4, tx = tid & 15;

    for (int k0 = 0; k0 < K; k0 += 8) {
        float4 a4 = *(const float4*)(Ap + k0);
        As[ac + 0][ar] = a4.x; As[ac + 1][ar] = a4.y;
        As[ac + 2][ar] = a4.z; As[ac + 3][ar] = a4.w;
        float4 b4 = *(const float4*)(Bp + (size_t)k0 * N);
        *(float4*)&Bs[br][bc] = b4;
        __syncthreads();
        #pragma unroll
        for (int k = 0; k < 8; k++) {
            float a[8], bb[8];
            float4 t0 = *(float4*)&As[k][ty * 8];
            float4 t1 = *(float4*)&As[k][ty * 8 + 4];
            a[0]=t0.x; a[1]=t0.y; a[2]=t0.z; a[3]=t0.w;
            a[4]=t1.x; a[5]=t1.y; a[6]=t1.z; a[7]=t1.w;
            float4 u0 = *(float4*)&Bs[k][tx * 8];
            float4 u1 = *(float4*)&Bs[k][tx * 8 + 4];
            bb[0]=u0.x; bb[1]=u0.y; bb[2]=u0.z; bb[3]=u0.w;
            bb[4]=u1.x; bb[5]=u1.y; bb[6]=u1.z; bb[7]=u1.w;
            #pragma unroll
            for (int i = 0; i < 8; i++)
                #pragma unroll
                for (int j = 0; j < 8; j++)
                    acc[i][j] = fmaf(a[i], bb[j], acc[i][j]);
        }
        __syncthreads();
    }

    #pragma unroll
    for (int i = 0; i < 8; i++) {
        int m = m0 + ty * 8 + i;
        #pragma unroll
        for (int j = 0; j < 8; j++) {
            int n = n0 + tx * 8 + j;
            float c = acc[i][j] + bias[n];
            if (act == 1) c = gelu_tanh(c);
            if (res)      c += res[(size_t)m * N + n];
            C[(size_t)m * N + n] = c;
        }
    }
}

// ---------------- batched attention scores: C = scale * A @ B^T ----------------
// A rows strided by lda (with batch/head offsets), B rows strided by ldb.
// C contiguous [batch*nh, SEQ, SEQ]. 64x64 tiles, 256 threads, 4x4/thread.
__global__ void attn_scores(const float* __restrict__ Abase, const float* __restrict__ Bbase,
                            float* __restrict__ Cbase, int K, int lda, int ldb,
                            long sAb, long sAh, long sBb, long sBh, int nh, float scale) {
    int z = blockIdx.z;
    int b = z / nh, h = z - b * nh;
    const float* A = Abase + (size_t)b * sAb + (size_t)h * sAh;
    const float* Bp = Bbase + (size_t)b * sBb + (size_t)h * sBh;
    float* C = Cbase + (size_t)z * SEQ * SEQ;

    int m0 = blockIdx.y * 64, n0 = blockIdx.x * 64;
    __shared__ float As[16][64];
    __shared__ float Bs[16][64];
    float acc[4][4] = {};
    int tid = threadIdx.x;
    int ty = tid >> 4, tx = tid & 15;

    for (int k0 = 0; k0 < K; k0 += 16) {
        #pragma unroll
        for (int u = 0; u < 4; u++) {
            int idx = tid * 4 + u;
            int r = idx >> 4, kk = idx & 15;
            As[kk][r] = A [(size_t)(m0 + r) * lda + k0 + kk];
            Bs[kk][r] = Bp[(size_t)(n0 + r) * ldb + k0 + kk];
        }
        __syncthreads();
        #pragma unroll
        for (int k = 0; k < 16; k++) {
            float a[4], bb[4];
            #pragma unroll
            for (int i = 0; i < 4; i++) { a[i] = As[k][ty * 4 + i]; bb[i] = Bs[k][tx * 4 + i]; }
            #pragma unroll
            for (int i = 0; i < 4; i++)
                #pragma unroll
                for (int j = 0; j < 4; j++)
                    acc[i][j] = fmaf(a[i], bb[j], acc[i][j]);
        }
        __syncthreads();
    }
    #pragma unroll
    for (int i = 0; i < 4; i++)
        #pragma unroll
        for (int j = 0; j < 4; j++)
            C[(size_t)(m0 + ty * 4 + i) * SEQ + n0 + tx * 4 + j] = acc[i][j] * scale;
}

// ---------------- row softmax, in place ----------------
__global__ void softmax_rows(float* __restrict__ S, int cols) {
    float* row = S + (size_t)blockIdx.x * cols;
    int tid = threadIdx.x;
    __shared__ float red[256];
    float mx = -1e30f;
    for (int i = tid; i < cols; i += 256) mx = fmaxf(mx, row[i]);
    red[tid] = mx; __syncthreads();
    for (int o = 128; o > 0; o >>= 1) {
        if (tid < o) red[tid] = fmaxf(red[tid], red[tid + o]);
        __syncthreads();
    }
    mx = red[0]; __syncthreads();
    float s = 0.f;
    for (int i = tid; i < cols; i += 256) { float e = expf(row[i] - mx); row[i] = e; s += e; }
    red[tid] = s; __syncthreads();
    for (int o = 128; o > 0; o >>= 1) {
        if (tid < o) red[tid] += red[tid + o];
        __syncthreads();
    }
    float inv = 1.0f / red[0];
    for (int i = tid; i < cols; i += 256) row[i] *= inv;
}

// ---------------- batched P @ V ----------------
// P contiguous [batch*nh, SEQ, SEQ]; V strided; O strided. K = SEQ.
__global__ void attn_pv(const float* __restrict__ P, const float* __restrict__ Vbase,
                        float* __restrict__ Obase, int N, int ldv, int ldo,
                        long sVb, long sVh, long sOb, long sOh, int nh) {
    int z = blockIdx.z;
    int b = z / nh, h = z - b * nh;
    const float* Pp = P + (size_t)z * SEQ * SEQ;
    const float* V  = Vbase + (size_t)b * sVb + (size_t)h * sVh;
    float* O        = Obase + (size_t)b * sOb + (size_t)h * sOh;

    int m0 = blockIdx.y * 64, n0 = blockIdx.x * 64;
    __shared__ float Ps[16][64];
    __shared__ float Vs[16][64];
    float acc[4][4] = {};
    int tid = threadIdx.x;
    int ty = tid >> 4, tx = tid & 15;
    int vr = (tid * 4) >> 6, vc = (tid * 4) & 63;

    for (int k0 = 0; k0 < SEQ; k0 += 16) {
        #pragma unroll
        for (int u = 0; u < 4; u++) {
            int idx = tid * 4 + u;
            int r = idx >> 4, kk = idx & 15;
            Ps[kk][r] = Pp[(size_t)(m0 + r) * SEQ + k0 + kk];
        }
        {
            float4 v4 = *(const float4*)(V + (size_t)(k0 + vr) * ldv + n0 + vc);
            *(float4*)&Vs[vr][vc] = v4;
        }
        __syncthreads();
        #pragma unroll
        for (int k = 0; k < 16; k++) {
            float a[4], bb[4];
            #pragma unroll
            for (int i = 0; i < 4; i++) { a[i] = Ps[k][ty * 4 + i]; bb[i] = Vs[k][tx * 4 + i]; }
            #pragma unroll
            for (int i = 0; i < 4; i++)
                #pragma unroll
                for (int j = 0; j < 4; j++)
                    acc[i][j] = fmaf(a[i], bb[j], acc[i][j]);
        }
        __syncthreads();
    }
    #pragma unroll
    for (int i = 0; i < 4; i++)
        #pragma unroll
        for (int j = 0; j < 4; j++)
            O[(size_t)(m0 + ty * 4 + i) * ldo + n0 + tx * 4 + j] = acc[i][j];
}

// ---------------- host launch ----------------
extern "C" void kernel_launch(void* const* d_in, const int* in_sizes, int n_in,
                              void* d_out, int out_size) {
    const float* x     = (const float*)d_in[0];
    const float* zin   = (const float*)d_in[1];
    const float* g1    = (const float*)d_in[2];
    const float* b1    = (const float*)d_in[3];
    const float* w_qkv = (const float*)d_in[4];
    const float* b_qkv = (const float*)d_in[5];
    const float* w_o   = (const float*)d_in[6];
    const float* b_o   = (const float*)d_in[7];
    const float* w_kv  = (const float*)d_in[8];
    const float* b_kv  = (const float*)d_in[9];
    const float* g2    = (const float*)d_in[10];
    const float* b2    = (const float*)d_in[11];
    const float* w_m1  = (const float*)d_in[12];
    const float* b_m1  = (const float*)d_in[13];
    const float* w_m2  = (const float*)d_in[14];
    const float* b_m2  = (const float*)d_in[15];
    float* out = (float*)d_out;

    float *ln, *qkv, *kv, *attn, *q, *cross, *mlp, *scores;
    cudaGetSymbolAddress((void**)&ln,     g_ln);
    cudaGetSymbolAddress((void**)&qkv,    g_qkv);
    cudaGetSymbolAddress((void**)&kv,     g_kv);
    cudaGetSymbolAddress((void**)&attn,   g_attn);
    cudaGetSymbolAddress((void**)&q,      g_q);
    cudaGetSymbolAddress((void**)&cross,  g_cross);
    cudaGetSymbolAddress((void**)&mlp,    g_mlp);
    cudaGetSymbolAddress((void**)&scores, g_scores);

    // 1) ln1(x)
    ln_kernel<<<ROWS, 256>>>(x, g1, b1, ln);

    // 2) qkv = ln1 @ w_qkv + b_qkv   [4096, 3072]
    gemm128<<<dim3(3 * D_MODEL / 128, ROWS / 128), 256>>>(ln, w_qkv, b_qkv, nullptr, qkv,
                                                          ROWS, 3 * D_MODEL, D_MODEL, 0);

    // 3) self-attn scores: per (b,h): Q @ K^T / 8
    attn_scores<<<dim3(SEQ / 64, SEQ / 64, BATCH * NHEADS), 256>>>(
        qkv, qkv + D_MODEL, scores, HDIM, 3 * D_MODEL, 3 * D_MODEL,
        (long)SEQ * 3 * D_MODEL, HDIM, (long)SEQ * 3 * D_MODEL, HDIM,
        NHEADS, 0.125f);

    // 4) softmax over 64*1024 rows of 1024
    softmax_rows<<<BATCH * NHEADS * SEQ, 256>>>(scores, SEQ);

    // 5) self-attn P @ V -> g_attn [B,S,D]
    attn_pv<<<dim3(1, SEQ / 64, BATCH * NHEADS), 256>>>(
        scores, qkv + 2 * D_MODEL, attn, HDIM, 3 * D_MODEL, D_MODEL,
        (long)SEQ * 3 * D_MODEL, HDIM, (long)SEQ * D_MODEL, HDIM, NHEADS);

    // 6) q = x + attn @ w_o + b_o
    gemm128<<<dim3(D_MODEL / 128, ROWS / 128), 256>>>(attn, w_o, b_o, x, q,
                                                      ROWS, D_MODEL, D_MODEL, 0);

    // 7) kv = z @ w_kv + b_kv   [4096, 2048]
    gemm128<<<dim3(2 * D_MODEL / 128, ROWS / 128), 256>>>(zin, w_kv, b_kv, nullptr, kv,
                                                          ROWS, 2 * D_MODEL, D_MODEL, 0);

    // 8) cross scores: per batch: q @ k^T / 32
    attn_scores<<<dim3(SEQ / 64, SEQ / 64, BATCH), 256>>>(
        q, kv, scores, D_MODEL, D_MODEL, 2 * D_MODEL,
        (long)SEQ * D_MODEL, 0L, (long)SEQ * 2 * D_MODEL, 0L,
        1, 0.03125f);

    // 9) softmax over 4*1024 rows
    softmax_rows<<<BATCH * SEQ, 256>>>(scores, SEQ);

    // 10) cross P @ V -> g_cross
    attn_pv<<<dim3(D_MODEL / 64, SEQ / 64, BATCH), 256>>>(
        scores, kv + D_MODEL, cross, D_MODEL, 2 * D_MODEL, D_MODEL,
        (long)SEQ * 2 * D_MODEL, 0L, (long)SEQ * D_MODEL, 0L, 1);

    // 11) ln2(cross)
    ln_kernel<<<ROWS, 256>>>(cross, g2, b2, ln);

    // 12) mlp hidden = gelu(ln2 @ w_m1 + b_m1)   [4096, 4096]
    gemm128<<<dim3(HMLP / 128, ROWS / 128), 256>>>(ln, w_m1, b_m1, nullptr, mlp,
                                                   ROWS, HMLP, D_MODEL, 1);

    // 13) out = cross + mlp @ w_m2 + b_m2
    gemm128<<<dim3(D_MODEL / 128, ROWS / 128), 256>>>(mlp, w_m2, b_m2, cross, out,
                                                      ROWS, D_MODEL, HMLP, 0);
}

// round 2
// speedup vs baseline: 1.1358x; 1.1358x over previous
#include <cuda_runtime.h>
#include <math.h>

#define D_MODEL 1024
#define BATCH   4
#define SEQ     1024
#define NHEADS  16
#define HDIM    64
#define HMLP    4096
#define ROWS    (BATCH*SEQ)     // 4096

// ---------------- scratch (device globals; no allocs allowed) ----------------
__device__ float g_ln   [ROWS * D_MODEL];
__device__ float g_qkv  [ROWS * 3 * D_MODEL];
__device__ float g_kv   [ROWS * 2 * D_MODEL];
__device__ float g_attn [ROWS * D_MODEL];
__device__ float g_q    [ROWS * D_MODEL];
__device__ float g_cross[ROWS * D_MODEL];
__device__ float g_mlp  [ROWS * HMLP];
__device__ float g_scores[(size_t)BATCH * NHEADS * SEQ * SEQ];  // 268MB, reused

// ---------------- packed f32x2 helpers ----------------
typedef unsigned long long ull;

__device__ __forceinline__ ull pack2(float lo, float hi) {
    ull r; asm("mov.b64 %0, {%1, %2};" : "=l"(r) : "f"(lo), "f"(hi)); return r;
}
__device__ __forceinline__ void unpack2(ull v, float& lo, float& hi) {
    asm("mov.b64 {%0, %1}, %2;" : "=f"(lo), "=f"(hi) : "l"(v));
}
__device__ __forceinline__ void ffma2(ull& acc, ull a, ull b) {
    asm("fma.rn.f32x2 %0, %1, %2, %0;" : "+l"(acc) : "l"(a), "l"(b));
}

__device__ __forceinline__ float gelu_tanh(float c) {
    float t = 0.7978845608028654f * (c + 0.044715f * c * c * c);
    return 0.5f * c * (1.0f + tanhf(t));
}

// ---------------- layernorm: one block per row ----------------
__global__ void ln_kernel(const float* __restrict__ x, const float* __restrict__ g,
                          const float* __restrict__ b, float* __restrict__ out) {
    int row = blockIdx.x;
    const float* xr = x + (size_t)row * D_MODEL;
    float* orow = out + (size_t)row * D_MODEL;
    int tid = threadIdx.x;
    float s = 0.f, s2 = 0.f;
    for (int i = tid; i < D_MODEL; i += 256) {
        float v = xr[i]; s += v; s2 += v * v;
    }
    __shared__ float red[256], red2[256];
    red[tid] = s; red2[tid] = s2; __syncthreads();
    for (int o = 128; o > 0; o >>= 1) {
        if (tid < o) { red[tid] += red[tid + o]; red2[tid] += red2[tid + o]; }
        __syncthreads();
    }
    float mu  = red[0]  * (1.0f / D_MODEL);
    float var = red2[0] * (1.0f / D_MODEL) - mu * mu;
    float inv = rsqrtf(var + 1e-5f);
    for (int i = tid; i < D_MODEL; i += 256)
        orow[i] = (xr[i] - mu) * inv * g[i] + b[i];
}

// ---------------- one-pass softmax: 256 threads, 1024 cols, row in registers ----
__global__ void softmax_rows(float* __restrict__ S) {
    float* row = S + (size_t)blockIdx.x * 1024;
    int tid = threadIdx.x;
    float4 v = *(float4*)(row + tid * 4);
    float mx = fmaxf(fmaxf(v.x, v.y), fmaxf(v.z, v.w));
    __shared__ float red[32];
    // warp max
    for (int o = 16; o > 0; o >>= 1) mx = fmaxf(mx, __shfl_xor_sync(0xffffffff, mx, o));
    if ((tid & 31) == 0) red[tid >> 5] = mx;
    __syncthreads();
    if (tid < 32) {
        float m = (tid < 8) ? red[tid] : -1e30f;
        for (int o = 4; o > 0; o >>= 1) m = fmaxf(m, __shfl_xor_sync(0xffffffff, m, o));
        red[0] = m;   // lane0 valid; all lanes<32 wrote through shuffle though
    }
    __syncthreads();
    mx = red[0];
    v.x = expf(v.x - mx); v.y = expf(v.y - mx); v.z = expf(v.z - mx); v.w = expf(v.w - mx);
    float s = v.x + v.y + v.z + v.w;
    for (int o = 16; o > 0; o >>= 1) s += __shfl_xor_sync(0xffffffff, s, o);
    __syncthreads();
    if ((tid & 31) == 0) red[tid >> 5] = s;
    __syncthreads();
    if (tid < 32) {
        float t = (tid < 8) ? red[tid] : 0.f;
        for (int o = 4; o > 0; o >>= 1) t += __shfl_xor_sync(0xffffffff, t, o);
        red[0] = t;
    }
    __syncthreads();
    float inv = 1.0f / red[0];
    v.x *= inv; v.y *= inv; v.z *= inv; v.w *= inv;
    *(float4*)(row + tid * 4) = v;
}

// ---------------- batched NN GEMM 128x128x8, FFMA2, 8x8 per thread ----------------
// C = A@B (+bias)(+res), per-z base offsets. act: 0=none, 1=gelu
__global__ void __launch_bounds__(256, 2)
gemm128(const float* __restrict__ Abase, const float* __restrict__ Bbase,
        const float* __restrict__ bias, const float* __restrict__ resbase,
        float* __restrict__ Cbase, int N, int K,
        int lda, int ldb, int ldc, long sA, long sB, long sC, int act) {
    int z = blockIdx.z;
    const float* A = Abase + (size_t)z * sA;
    const float* B = Bbase + (size_t)z * sB;
    float* C = Cbase + (size_t)z * sC;
    const float* res = resbase ? resbase + (size_t)z * sC : nullptr;

    __shared__ float As[8][128];
    __shared__ float Bs[8][128];

    int tid = threadIdx.x;
    int n0 = blockIdx.x * 128;
    int m0 = blockIdx.y * 128;

    int ar = tid >> 1;               // 0..127
    int ac = (tid & 1) * 4;          // 0 or 4
    int br = tid >> 5;               // 0..7
    int bc = (tid & 31) * 4;         // 0..124

    const float* Ap = A + (size_t)(m0 + ar) * lda + ac;
    const float* Bp = B + (size_t)br * ldb + n0 + bc;

    ull acc2[8][4];
    #pragma unroll
    for (int i = 0; i < 8; i++)
        #pragma unroll
        for (int j = 0; j < 4; j++) acc2[i][j] = 0ull;

    int ty = tid >> 4, tx = tid & 15;

    for (int k0 = 0; k0 < K; k0 += 8) {
        float4 a4 = *(const float4*)(Ap + k0);
        As[ac + 0][ar] = a4.x; As[ac + 1][ar] = a4.y;
        As[ac + 2][ar] = a4.z; As[ac + 3][ar] = a4.w;
        float4 b4 = *(const float4*)(Bp + (size_t)k0 * ldb);
        *(float4*)&Bs[br][bc] = b4;
        __syncthreads();
        #pragma unroll
        for (int k = 0; k < 8; k++) {
            float4 t0 = *(float4*)&As[k][ty * 8];
            float4 t1 = *(float4*)&As[k][ty * 8 + 4];
            ull ad[8];
            ad[0]=pack2(t0.x,t0.x); ad[1]=pack2(t0.y,t0.y); ad[2]=pack2(t0.z,t0.z); ad[3]=pack2(t0.w,t0.w);
            ad[4]=pack2(t1.x,t1.x); ad[5]=pack2(t1.y,t1.y); ad[6]=pack2(t1.z,t1.z); ad[7]=pack2(t1.w,t1.w);
            float4 u0 = *(float4*)&Bs[k][tx * 8];
            float4 u1 = *(float4*)&Bs[k][tx * 8 + 4];
            ull bp[4];
            bp[0]=pack2(u0.x,u0.y); bp[1]=pack2(u0.z,u0.w);
            bp[2]=pack2(u1.x,u1.y); bp[3]=pack2(u1.z,u1.w);
            #pragma unroll
            for (int i = 0; i < 8; i++)
                #pragma unroll
                for (int j = 0; j < 4; j++)
                    ffma2(acc2[i][j], ad[i], bp[j]);
        }
        __syncthreads();
    }

    #pragma unroll
    for (int i = 0; i < 8; i++) {
        int m = m0 + ty * 8 + i;
        #pragma unroll
        for (int j = 0; j < 4; j++) {
            float c0, c1;
            unpack2(acc2[i][j], c0, c1);
            int n = n0 + tx * 8 + j * 2;
            if (bias) { c0 += bias[n]; c1 += bias[n + 1]; }
            if (act == 1) { c0 = gelu_tanh(c0); c1 = gelu_tanh(c1); }
            if (res) { c0 += res[(size_t)m * ldc + n]; c1 += res[(size_t)m * ldc + n + 1]; }
            C[(size_t)m * ldc + n]     = c0;
            C[(size_t)m * ldc + n + 1] = c1;
        }
    }
}

// ---------------- batched NT scores: C = scale * A @ B^T, 128x128 tiles ----------------
__global__ void __launch_bounds__(256, 2)
gemmNT(const float* __restrict__ Abase, const float* __restrict__ Bbase,
       float* __restrict__ Cbase, int K, int lda, int ldb,
       long sAb, long sAh, long sBb, long sBh, int nh, float scale) {
    int z = blockIdx.z;
    int b = z / nh, h = z - b * nh;
    const float* A = Abase + (size_t)b * sAb + (size_t)h * sAh;
    const float* B = Bbase + (size_t)b * sBb + (size_t)h * sBh;
    float* C = Cbase + (size_t)z * SEQ * SEQ;

    __shared__ float As[8][128];
    __shared__ float Bs[8][128];

    int tid = threadIdx.x;
    int n0 = blockIdx.x * 128;
    int m0 = blockIdx.y * 128;

    int ar = tid >> 1;               // 0..127
    int ac = (tid & 1) * 4;          // 0 or 4

    const float* Ap = A + (size_t)(m0 + ar) * lda + ac;
    const float* Bp = B + (size_t)(n0 + ar) * ldb + ac;

    ull acc2[8][4];
    #pragma unroll
    for (int i = 0; i < 8; i++)
        #pragma unroll
        for (int j = 0; j < 4; j++) acc2[i][j] = 0ull;

    int ty = tid >> 4, tx = tid & 15;

    for (int k0 = 0; k0 < K; k0 += 8) {
        float4 a4 = *(const float4*)(Ap + k0);
        As[ac + 0][ar] = a4.x; As[ac + 1][ar] = a4.y;
        As[ac + 2][ar] = a4.z; As[ac + 3][ar] = a4.w;
        float4 b4 = *(const float4*)(Bp + k0);
        Bs[ac + 0][ar] = b4.x; Bs[ac + 1][ar] = b4.y;
        Bs[ac + 2][ar] = b4.z; Bs[ac + 3][ar] = b4.w;
        __syncthreads();
        #pragma unroll
        for (int k = 0; k < 8; k++) {
            float4 t0 = *(float4*)&As[k][ty * 8];
            float4 t1 = *(float4*)&As[k][ty * 8 + 4];
            ull ad[8];
            ad[0]=pack2(t0.x,t0.x); ad[1]=pack2(t0.y,t0.y); ad[2]=pack2(t0.z,t0.z); ad[3]=pack2(t0.w,t0.w);
            ad[4]=pack2(t1.x,t1.x); ad[5]=pack2(t1.y,t1.y); ad[6]=pack2(t1.z,t1.z); ad[7]=pack2(t1.w,t1.w);
            float4 u0 = *(float4*)&Bs[k][tx * 8];
            float4 u1 = *(float4*)&Bs[k][tx * 8 + 4];
            ull bp[4];
            bp[0]=pack2(u0.x,u0.y); bp[1]=pack2(u0.z,u0.w);
            bp[2]=pack2(u1.x,u1.y); bp[3]=pack2(u1.z,u1.w);
            #pragma unroll
            for (int i = 0; i < 8; i++)
                #pragma unroll
                for (int j = 0; j < 4; j++)
                    ffma2(acc2[i][j], ad[i], bp[j]);
        }
        __syncthreads();
    }

    #pragma unroll
    for (int i = 0; i < 8; i++) {
        int m = m0 + ty * 8 + i;
        #pragma unroll
        for (int j = 0; j < 4; j++) {
            float c0, c1;
            unpack2(acc2[i][j], c0, c1);
            int n = n0 + tx * 8 + j * 2;
            C[(size_t)m * SEQ + n]     = c0 * scale;
            C[(size_t)m * SEQ + n + 1] = c1 * scale;
        }
    }
}

// ---------------- self-attn P@V: 128x64 tile (N=64 per head), 8x4 per thread ------
__global__ void __launch_bounds__(256, 2)
pv64(const float* __restrict__ P, const float* __restrict__ Vbase,
     float* __restrict__ Obase, int ldv, int ldo,
     long sVb, long sVh, long sOb, long sOh, int nh) {
    int z = blockIdx.z;
    int b = z / nh, h = z - b * nh;
    const float* Pp = P + (size_t)z * SEQ * SEQ;
    const float* V  = Vbase + (size_t)b * sVb + (size_t)h * sVh;
    float* O        = Obase + (size_t)b * sOb + (size_t)h * sOh;

    int m0 = blockIdx.y * 128;
    __shared__ float Ps[8][128];
    __shared__ float Vs[8][64];

    int tid = threadIdx.x;
    int ar = tid >> 1;
    int ac = (tid & 1) * 4;

    ull acc2[8][2];
    #pragma unroll
    for (int i = 0; i < 8; i++) { acc2[i][0] = 0ull; acc2[i][1] = 0ull; }

    int ty = tid >> 4, tx = tid & 15;

    for (int k0 = 0; k0 < SEQ; k0 += 8) {
        float4 a4 = *(const float4*)(Pp + (size_t)(m0 + ar) * SEQ + k0 + ac);
        Ps[ac + 0][ar] = a4.x; Ps[ac + 1][ar] = a4.y;
        Ps[ac + 2][ar] = a4.z; Ps[ac + 3][ar] = a4.w;
        if (tid < 128) {
            int br = tid >> 4;            // 0..7
            int bc = (tid & 15) * 4;      // 0..60
            float4 v4 = *(const float4*)(V + (size_t)(k0 + br) * ldv + bc);
            *(float4*)&Vs[br][bc] = v4;
        }
        __syncthreads();
        #pragma unroll
        for (int k = 0; k < 8; k++) {
            float4 t0 = *(float4*)&Ps[k][ty * 8];
            float4 t1 = *(float4*)&Ps[k][ty * 8 + 4];
            ull ad[8];
            ad[0]=pack2(t0.x,t0.x); ad[1]=pack2(t0.y,t0.y); ad[2]=pack2(t0.z,t0.z); ad[3]=pack2(t0.w,t0.w);
            ad[4]=pack2(t1.x,t1.x); ad[5]=pack2(t1.y,t1.y); ad[6]=pack2(t1.z,t1.z); ad[7]=pack2(t1.w,t1.w);
            float4 u = *(float4*)&Vs[k][tx * 4];
            ull bp[2];
            bp[0]=pack2(u.x,u.y); bp[1]=pack2(u.z,u.w);
            #pragma unroll
            for (int i = 0; i < 8; i++) {
                ffma2(acc2[i][0], ad[i], bp[0]);
                ffma2(acc2[i][1], ad[i], bp[1]);
            }
        }
        __syncthreads();
    }

    #pragma unroll
    for (int i = 0; i < 8; i++) {
        int m = m0 + ty * 8 + i;
        #pragma unroll
        for (int j = 0; j < 2; j++) {
            float c0, c1;
            unpack2(acc2[i][j], c0, c1);
            int n = tx * 4 + j * 2;
            O[(size_t)m * ldo + n]     = c0;
            O[(size_t)m * ldo + n + 1] = c1;
        }
    }
}

// ---------------- host launch ----------------
extern "C" void kernel_launch(void* const* d_in, const int* in_sizes, int n_in,
                              void* d_out, int out_size) {
    const float* x     = (const float*)d_in[0];
    const float* zin   = (const float*)d_in[1];
    const float* g1    = (const float*)d_in[2];
    const float* b1    = (const float*)d_in[3];
    const float* w_qkv = (const float*)d_in[4];
    const float* b_qkv = (const float*)d_in[5];
    const float* w_o   = (const float*)d_in[6];
    const float* b_o   = (const float*)d_in[7];
    const float* w_kv  = (const float*)d_in[8];
    const float* b_kv  = (const float*)d_in[9];
    const float* g2    = (const float*)d_in[10];
    const float* b2    = (const float*)d_in[11];
    const float* w_m1  = (const float*)d_in[12];
    const float* b_m1  = (const float*)d_in[13];
    const float* w_m2  = (const float*)d_in[14];
    const float* b_m2  = (const float*)d_in[15];
    float* out = (float*)d_out;

    float *ln, *qkv, *kv, *attn, *q, *cross, *mlp, *scores;
    cudaGetSymbolAddress((void**)&ln,     g_ln);
    cudaGetSymbolAddress((void**)&qkv,    g_qkv);
    cudaGetSymbolAddress((void**)&kv,     g_kv);
    cudaGetSymbolAddress((void**)&attn,   g_attn);
    cudaGetSymbolAddress((void**)&q,      g_q);
    cudaGetSymbolAddress((void**)&cross,  g_cross);
    cudaGetSymbolAddress((void**)&mlp,    g_mlp);
    cudaGetSymbolAddress((void**)&scores, g_scores);

    // 1) ln1(x)
    ln_kernel<<<ROWS, 256>>>(x, g1, b1, ln);

    // 2) qkv = ln1 @ w_qkv + b_qkv   [4096, 3072]
    gemm128<<<dim3(3 * D_MODEL / 128, ROWS / 128, 1), 256>>>(
        ln, w_qkv, b_qkv, nullptr, qkv, 3 * D_MODEL, D_MODEL,
        D_MODEL, 3 * D_MODEL, 3 * D_MODEL, 0, 0, 0, 0);

    // 3) self-attn scores: per (b,h): Q @ K^T / 8
    gemmNT<<<dim3(SEQ / 128, SEQ / 128, BATCH * NHEADS), 256>>>(
        qkv, qkv + D_MODEL, scores, HDIM, 3 * D_MODEL, 3 * D_MODEL,
        (long)SEQ * 3 * D_MODEL, HDIM, (long)SEQ * 3 * D_MODEL, HDIM,
        NHEADS, 0.125f);

    // 4) softmax over 64*1024 rows of 1024
    softmax_rows<<<BATCH * NHEADS * SEQ, 256>>>(scores);

    // 5) self-attn P @ V -> attn [B,S,D]
    pv64<<<dim3(1, SEQ / 128, BATCH * NHEADS), 256>>>(
        scores, qkv + 2 * D_MODEL, attn, 3 * D_MODEL, D_MODEL,
        (long)SEQ * 3 * D_MODEL, HDIM, (long)SEQ * D_MODEL, HDIM, NHEADS);

    // 6) q = x + attn @ w_o + b_o
    gemm128<<<dim3(D_MODEL / 128, ROWS / 128, 1), 256>>>(
        attn, w_o, b_o, x, q, D_MODEL, D_MODEL,
        D_MODEL, D_MODEL, D_MODEL, 0, 0, 0, 0);

    // 7) kv = z @ w_kv + b_kv   [4096, 2048]
    gemm128<<<dim3(2 * D_MODEL / 128, ROWS / 128, 1), 256>>>(
        zin, w_kv, b_kv, nullptr, kv, 2 * D_MODEL, D_MODEL,
        D_MODEL, 2 * D_MODEL, 2 * D_MODEL, 0, 0, 0, 0);

    // 8) cross scores: per batch: q @ k^T / 32
    gemmNT<<<dim3(SEQ / 128, SEQ / 128, BATCH), 256>>>(
        q, kv, scores, D_MODEL, D_MODEL, 2 * D_MODEL,
        (long)SEQ * D_MODEL, 0L, (long)SEQ * 2 * D_MODEL, 0L,
        1, 0.03125f);

    // 9) softmax over 4*1024 rows
    softmax_rows<<<BATCH * SEQ, 256>>>(scores);

    // 10) cross P @ V -> cross  (batched NN: per batch 1024x1024x1024)
    gemm128<<<dim3(D_MODEL / 128, SEQ / 128, BATCH), 256>>>(
        scores, kv + D_MODEL, nullptr, nullptr, cross, D_MODEL, SEQ,
        SEQ, 2 * D_MODEL, D_MODEL,
        (long)SEQ * SEQ, (long)SEQ * 2 * D_MODEL, (long)SEQ * D_MODEL, 0);

    // 11) ln2(cross)
    ln_kernel<<<ROWS, 256>>>(cross, g2, b2, ln);

    // 12) mlp hidden = gelu(ln2 @ w_m1 + b_m1)   [4096, 4096]
    gemm128<<<dim3(HMLP / 128, ROWS / 128, 1), 256>>>(
        ln, w_m1, b_m1, nullptr, mlp, HMLP, D_MODEL,
        D_MODEL, HMLP, HMLP, 0, 0, 0, 1);

    // 13) out = cross + mlp @ w_m2 + b_m2
    gemm128<<<dim3(D_MODEL / 128, ROWS / 128, 1), 256>>>(
        mlp, w_m2, b_m2, cross, out, D_MODEL, HMLP,
        HMLP, D_MODEL, D_MODEL, 0, 0, 0, 0);
}

// round 4
// speedup vs baseline: 2.1151x; 1.8622x over previous
#include <cuda_runtime.h>
#include <math.h>
#include <stdint.h>

#define D_MODEL 1024
#define BATCH   4
#define SEQ     1024
#define NHEADS  16
#define HDIM    64
#define HMLP    4096
#define ROWS    (BATCH*SEQ)     // 4096

// ---------------- scratch (device globals; no allocs allowed) ----------------
__device__ float g_ln   [ROWS * D_MODEL];
__device__ float g_qkv  [ROWS * 3 * D_MODEL];
__device__ float g_kv   [ROWS * 2 * D_MODEL];
__device__ float g_attn [ROWS * D_MODEL];
__device__ float g_q    [ROWS * D_MODEL];
__device__ float g_cross[ROWS * D_MODEL];
__device__ float g_mlp  [ROWS * HMLP];
__device__ float g_scores[(size_t)BATCH * NHEADS * SEQ * SEQ];  // 268MB
// transposed operands (all GEMMs NT: B stored [N][K] row-major)
__device__ float g_wt_qkv[3 * D_MODEL * D_MODEL];
__device__ float g_wt_o  [D_MODEL * D_MODEL];
__device__ float g_wt_kv [2 * D_MODEL * D_MODEL];
__device__ float g_wt_m1 [HMLP * D_MODEL];
__device__ float g_wt_m2 [D_MODEL * HMLP];
__device__ float g_vt_self [BATCH * NHEADS * HDIM * SEQ];
__device__ float g_vt_cross[(size_t)BATCH * D_MODEL * SEQ];

__device__ __forceinline__ uint32_t f2tf32(float x) {
    uint32_t r; asm("cvt.rna.tf32.f32 %0, %1;" : "=r"(r) : "f"(x)); return r;
}
__device__ __forceinline__ float gelu_tanh(float c) {
    float t = 0.7978845608028654f * (c + 0.044715f * c * c * c);
    return 0.5f * c * (1.0f + tanhf(t));
}
__device__ __forceinline__ void mma_tf32(float* d, const uint32_t* a, const uint32_t* b) {
    asm volatile("mma.sync.aligned.m16n8k8.row.col.f32.tf32.tf32.f32 "
        "{%0,%1,%2,%3}, {%4,%5,%6,%7}, {%8,%9}, {%0,%1,%2,%3};"
        : "+f"(d[0]), "+f"(d[1]), "+f"(d[2]), "+f"(d[3])
        : "r"(a[0]), "r"(a[1]), "r"(a[2]), "r"(a[3]), "r"(b[0]), "r"(b[1]));
}

// ---------------- layernorm ----------------
__global__ void ln_kernel(const float* __restrict__ x, const float* __restrict__ g,
                          const float* __restrict__ b, float* __restrict__ out) {
    int row = blockIdx.x;
    const float* xr = x + (size_t)row * D_MODEL;
    float* orow = out + (size_t)row * D_MODEL;
    int tid = threadIdx.x;
    float s = 0.f, s2 = 0.f;
    for (int i = tid; i < D_MODEL; i += 256) {
        float v = xr[i]; s += v; s2 += v * v;
    }
    __shared__ float red[256], red2[256];
    red[tid] = s; red2[tid] = s2; __syncthreads();
    for (int o = 128; o > 0; o >>= 1) {
        if (tid < o) { red[tid] += red[tid + o]; red2[tid] += red2[tid + o]; }
        __syncthreads();
    }
    float mu  = red[0]  * (1.0f / D_MODEL);
    float var = red2[0] * (1.0f / D_MODEL) - mu * mu;
    float inv = rsqrtf(var + 1e-5f);
    for (int i = tid; i < D_MODEL; i += 256)
        orow[i] = (xr[i] - mu) * inv * g[i] + b[i];
}

// ---------------- one-pass softmax (1024 cols) ----------------
__global__ void softmax_rows(float* __restrict__ S) {
    float* row = S + (size_t)blockIdx.x * 1024;
    int tid = threadIdx.x;
    float4 v = *(float4*)(row + tid * 4);
    float mx = fmaxf(fmaxf(v.x, v.y), fmaxf(v.z, v.w));
    __shared__ float red[32];
    for (int o = 16; o > 0; o >>= 1) mx = fmaxf(mx, __shfl_xor_sync(0xffffffff, mx, o));
    if ((tid & 31) == 0) red[tid >> 5] = mx;
    __syncthreads();
    if (tid < 32) {
        float m = (tid < 8) ? red[tid] : -1e30f;
        for (int o = 4; o > 0; o >>= 1) m = fmaxf(m, __shfl_xor_sync(0xffffffff, m, o));
        red[0] = m;
    }
    __syncthreads();
    mx = red[0];
    v.x = expf(v.x - mx); v.y = expf(v.y - mx); v.z = expf(v.z - mx); v.w = expf(v.w - mx);
    float s = v.x + v.y + v.z + v.w;
    for (int o = 16; o > 0; o >>= 1) s += __shfl_xor_sync(0xffffffff, s, o);
    __syncthreads();
    if ((tid & 31) == 0) red[tid >> 5] = s;
    __syncthreads();
    if (tid < 32) {
        float t = (tid < 8) ? red[tid] : 0.f;
        for (int o = 4; o > 0; o >>= 1) t += __shfl_xor_sync(0xffffffff, t, o);
        red[0] = t;
    }
    __syncthreads();
    float inv = 1.0f / red[0];
    v.x *= inv; v.y *= inv; v.z *= inv; v.w *= inv;
    *(float4*)(row + tid * 4) = v;
}

// ---------------- batched transpose ----------------
__global__ void transpose_k(const float* __restrict__ srcb, float* __restrict__ dstb,
                            int lds, int ldd, long sSb, long sSh, long sDb, long sDh, int nh) {
    int z = blockIdx.z, b = z / nh, h = z - b * nh;
    const float* src = srcb + (size_t)b * sSb + (size_t)h * sSh;
    float* dst = dstb + (size_t)b * sDb + (size_t)h * sDh;
    __shared__ float tile[32][33];
    int x = blockIdx.x * 32, y = blockIdx.y * 32;
    int tx = threadIdx.x, ty = threadIdx.y;
    #pragma unroll
    for (int i = ty; i < 32; i += 8)
        tile[i][tx] = src[(size_t)(y + i) * lds + x + tx];
    __syncthreads();
    #pragma unroll
    for (int i = ty; i < 32; i += 8)
        dst[(size_t)(x + i) * ldd + y + tx] = tile[tx][i];
}

// ============ tf32 mma.sync GEMM: C[M,N] = scale * A[M,K] @ B[N,K]^T (+bias)(+gelu)(+res)
// TM=128 x TN, KB=32, 8 warps, double-buffered SMEM with k-pair-permuted layout.
// SMEM row stride 36 floats; element k-offset j (within 8-group g) stored at g*8 + 2*(j&3)+(j>>2).
#define LDSROW 36

template <int TN>
__global__ void __launch_bounds__(256)
mm_tf32(const float* __restrict__ Abase, const float* __restrict__ Bbase,
        const float* __restrict__ bias, const float* __restrict__ resbase,
        float* __restrict__ Cbase, int K, int lda, int ldb, int ldc,
        long sAb, long sAh, long sBb, long sBh, long sCb, long sCh,
        int nh, float scale, int act) {
    constexpr int TM = 128;
    constexpr int WX = (TN == 128) ? 4 : 2;   // warps along n
    constexpr int WY = 8 / WX;                // warps along m
    constexpr int WNT = TN / WX;              // 32
    constexpr int WMT = TM / WY;              // 64 or 32
    constexpr int MI = WMT / 16;
    constexpr int NI = WNT / 8;
    constexpr int NA = TM * 32 / (256 * 4);   // float4s per thread for A (4)
    constexpr int NB = TN * 32 / (256 * 4);   // for B (4 or 2)

    extern __shared__ float sm[];
    float* Ast[2] = { sm, sm + TM * LDSROW };
    float* Bst[2] = { sm + 2 * TM * LDSROW, sm + 2 * TM * LDSROW + TN * LDSROW };

    int tid = threadIdx.x, lane = tid & 31, warp = tid >> 5;
    int wy = warp % WY, wx = warp / WY;
    int z = blockIdx.z, b = z / nh, h = z - b * nh;
    const float* A = Abase + (size_t)b * sAb + (size_t)h * sAh + (size_t)blockIdx.y * TM * lda;
    const float* B = Bbase + (size_t)b * sBb + (size_t)h * sBh + (size_t)blockIdx.x * TN * ldb;
    float* C = Cbase + (size_t)b * sCb + (size_t)h * sCh;
    const float* res = resbase ? resbase + (size_t)b * sCb + (size_t)h * sCh : nullptr;
    int m0 = blockIdx.y * TM, n0 = blockIdx.x * TN;

    float acc[MI][NI][4];
    #pragma unroll
    for (int mi = 0; mi < MI; mi++)
        #pragma unroll
        for (int ni = 0; ni < NI; ni++)
            #pragma unroll
            for (int c = 0; c < 4; c++) acc[mi][ni][c] = 0.f;

    // store a float4 (global k-offset kq*4 within KB) into permuted smem
    auto sts_perm = [&](float* stg, int row, int kq, float4 v) {
        int g = kq >> 1, c = kq & 1;
        float* p = stg + row * LDSROW + g * 8 + c;
        p[0] = __uint_as_float(f2tf32(v.x));
        p[2] = __uint_as_float(f2tf32(v.y));
        p[4] = __uint_as_float(f2tf32(v.z));
        p[6] = __uint_as_float(f2tf32(v.w));
    };

    int nkb = K >> 5;
    // prologue: stage 0
    {
        #pragma unroll
        for (int i = 0; i < NA; i++) {
            int f = i * 256 + tid, row = f >> 3, kq = f & 7;
            sts_perm(Ast[0], row, kq, *(const float4*)(A + (size_t)row * lda + kq * 4));
        }
        #pragma unroll
        for (int i = 0; i < NB; i++) {
            int f = i * 256 + tid, row = f >> 3, kq = f & 7;
            sts_perm(Bst[0], row, kq, *(const float4*)(B + (size_t)row * ldb + kq * 4));
        }
    }
    __syncthreads();

    for (int kb = 0; kb < nkb; kb++) {
        int cur = kb & 1;
        float4 pa[NA], pb[NB];
        if (kb + 1 < nkb) {
            int koff = (kb + 1) * 32;
            #pragma unroll
            for (int i = 0; i < NA; i++) {
                int f = i * 256 + tid, row = f >> 3, kq = f & 7;
                pa[i] = *(const float4*)(A + (size_t)row * lda + koff + kq * 4);
            }
            #pragma unroll
            for (int i = 0; i < NB; i++) {
                int f = i * 256 + tid, row = f >> 3, kq = f & 7;
                pb[i] = *(const float4*)(B + (size_t)row * ldb + koff + kq * 4);
            }
        }
        const float* Ac = Ast[cur];
        const float* Bc = Bst[cur];
        #pragma unroll
        for (int kk = 0; kk < 4; kk++) {
            uint32_t afr[MI][4], bfr[NI][2];
            #pragma unroll
            for (int mi = 0; mi < MI; mi++) {
                int r = wy * WMT + mi * 16 + (lane >> 2);
                float2 lo = *(const float2*)&Ac[r * LDSROW + kk * 8 + 2 * (lane & 3)];
                float2 hi = *(const float2*)&Ac[(r + 8) * LDSROW + kk * 8 + 2 * (lane & 3)];
                afr[mi][0] = __float_as_uint(lo.x);
                afr[mi][1] = __float_as_uint(hi.x);
                afr[mi][2] = __float_as_uint(lo.y);
                afr[mi][3] = __float_as_uint(hi.y);
            }
            #pragma unroll
            for (int ni = 0; ni < NI; ni++) {
                int rn = wx * WNT + ni * 8 + (lane >> 2);
                float2 bb = *(const float2*)&Bc[rn * LDSROW + kk * 8 + 2 * (lane & 3)];
                bfr[ni][0] = __float_as_uint(bb.x);
                bfr[ni][1] = __float_as_uint(bb.y);
            }
            #pragma unroll
            for (int mi = 0; mi < MI; mi++)
                #pragma unroll
                for (int ni = 0; ni < NI; ni++)
                    mma_tf32(acc[mi][ni], afr[mi], bfr[ni]);
        }
        if (kb + 1 < nkb) {
            int nxt = cur ^ 1;
            #pragma unroll
            for (int i = 0; i < NA; i++) {
                int f = i * 256 + tid, row = f >> 3, kq = f & 7;
                sts_perm(Ast[nxt], row, kq, pa[i]);
            }
            #pragma unroll
            for (int i = 0; i < NB; i++) {
                int f = i * 256 + tid, row = f >> 3, kq = f & 7;
                sts_perm(Bst[nxt], row, kq, pb[i]);
            }
            __syncthreads();
        }
    }

    // epilogue
    #pragma unroll
    for (int mi = 0; mi < MI; mi++) {
        #pragma unroll
        for (int ni = 0; ni < NI; ni++) {
            int col = n0 + wx * WNT + ni * 8 + 2 * (lane & 3);
            #pragma unroll
            for (int half = 0; half < 2; half++) {
                int row = m0 + wy * WMT + mi * 16 + (lane >> 2) + half * 8;
                float c0 = acc[mi][ni][2 * half]     * scale;
                float c1 = acc[mi][ni][2 * half + 1] * scale;
                if (bias) { c0 += bias[col]; c1 += bias[col + 1]; }
                if (act == 1) { c0 = gelu_tanh(c0); c1 = gelu_tanh(c1); }
                if (res) {
                    float2 rv = *(const float2*)(res + (size_t)row * ldc + col);
                    c0 += rv.x; c1 += rv.y;
                }
                float2 o; o.x = c0; o.y = c1;
                *(float2*)(C + (size_t)row * ldc + col) = o;
            }
        }
    }
}

#define SMEMB(TN) ((2 * 128 * LDSROW + 2 * (TN) * LDSROW) * 4)

// ---------------- host launch ----------------
extern "C" void kernel_launch(void* const* d_in, const int* in_sizes, int n_in,
                              void* d_out, int out_size) {
    const float* x     = (const float*)d_in[0];
    const float* zin   = (const float*)d_in[1];
    const float* g1    = (const float*)d_in[2];
    const float* b1    = (const float*)d_in[3];
    const float* w_qkv = (const float*)d_in[4];
    const float* b_qkv = (const float*)d_in[5];
    const float* w_o   = (const float*)d_in[6];
    const float* b_o   = (const float*)d_in[7];
    const float* w_kv  = (const float*)d_in[8];
    const float* b_kv  = (const float*)d_in[9];
    const float* g2    = (const float*)d_in[10];
    const float* b2    = (const float*)d_in[11];
    const float* w_m1  = (const float*)d_in[12];
    const float* b_m1  = (const float*)d_in[13];
    const float* w_m2  = (const float*)d_in[14];
    const float* b_m2  = (const float*)d_in[15];
    float* out = (float*)d_out;

    float *ln, *qkv, *kv, *attn, *q, *cross, *mlp, *scores;
    float *wtqkv, *wto, *wtkv, *wtm1, *wtm2, *vts, *vtc;
    cudaGetSymbolAddress((void**)&ln,     g_ln);
    cudaGetSymbolAddress((void**)&qkv,    g_qkv);
    cudaGetSymbolAddress((void**)&kv,     g_kv);
    cudaGetSymbolAddress((void**)&attn,   g_attn);
    cudaGetSymbolAddress((void**)&q,      g_q);
    cudaGetSymbolAddress((void**)&cross,  g_cross);
    cudaGetSymbolAddress((void**)&mlp,    g_mlp);
    cudaGetSymbolAddress((void**)&scores, g_scores);
    cudaGetSymbolAddress((void**)&wtqkv,  g_wt_qkv);
    cudaGetSymbolAddress((void**)&wto,    g_wt_o);
    cudaGetSymbolAddress((void**)&wtkv,   g_wt_kv);
    cudaGetSymbolAddress((void**)&wtm1,   g_wt_m1);
    cudaGetSymbolAddress((void**)&wtm2,   g_wt_m2);
    cudaGetSymbolAddress((void**)&vts,    g_vt_self);
    cudaGetSymbolAddress((void**)&vtc,    g_vt_cross);

    cudaFuncSetAttribute(mm_tf32<128>, cudaFuncAttributeMaxDynamicSharedMemorySize, SMEMB(128));
    cudaFuncSetAttribute(mm_tf32<64>,  cudaFuncAttributeMaxDynamicSharedMemorySize, SMEMB(64));

    dim3 tb(32, 8);

    // weight transposes ([K][N] -> [N][K])
    transpose_k<<<dim3(3 * D_MODEL / 32, D_MODEL / 32, 1), tb>>>(w_qkv, wtqkv, 3 * D_MODEL, D_MODEL, 0, 0, 0, 0, 1);
    transpose_k<<<dim3(D_MODEL / 32, D_MODEL / 32, 1), tb>>>(w_o, wto, D_MODEL, D_MODEL, 0, 0, 0, 0, 1);
    transpose_k<<<dim3(2 * D_MODEL / 32, D_MODEL / 32, 1), tb>>>(w_kv, wtkv, 2 * D_MODEL, D_MODEL, 0, 0, 0, 0, 1);
    transpose_k<<<dim3(HMLP / 32, D_MODEL / 32, 1), tb>>>(w_m1, wtm1, HMLP, D_MODEL, 0, 0, 0, 0, 1);
    transpose_k<<<dim3(D_MODEL / 32, HMLP / 32, 1), tb>>>(w_m2, wtm2, D_MODEL, HMLP, 0, 0, 0, 0, 1);

    // 1) ln1(x)
    ln_kernel<<<ROWS, 256>>>(x, g1, b1, ln);

    // 2) qkv = ln1 @ w_qkv + b_qkv
    mm_tf32<128><<<dim3(24, 32, 1), 256, SMEMB(128)>>>(
        ln, wtqkv, b_qkv, nullptr, qkv, D_MODEL, D_MODEL, D_MODEL, 3 * D_MODEL,
        0, 0, 0, 0, 0, 0, 1, 1.0f, 0);

    // transpose self V: per (b,h): [S,64] -> [64,S]
    transpose_k<<<dim3(2, 32, BATCH * NHEADS), tb>>>(
        qkv + 2 * D_MODEL, vts, 3 * D_MODEL, SEQ,
        (long)SEQ * 3 * D_MODEL, HDIM, (long)NHEADS * HDIM * SEQ, (long)HDIM * SEQ, NHEADS);

    // 3) self scores = Q @ K^T / 8
    mm_tf32<128><<<dim3(8, 8, BATCH * NHEADS), 256, SMEMB(128)>>>(
        qkv, qkv + D_MODEL, nullptr, nullptr, scores, HDIM, 3 * D_MODEL, 3 * D_MODEL, SEQ,
        (long)SEQ * 3 * D_MODEL, HDIM, (long)SEQ * 3 * D_MODEL, HDIM,
        (long)NHEADS * SEQ * SEQ, (long)SEQ * SEQ, NHEADS, 0.125f, 0);

    // 4) softmax
    softmax_rows<<<BATCH * NHEADS * SEQ, 256>>>(scores);

    // 5) self P @ V
    mm_tf32<64><<<dim3(1, 8, BATCH * NHEADS), 256, SMEMB(64)>>>(
        scores, vts, nullptr, nullptr, attn, SEQ, SEQ, SEQ, D_MODEL,
        (long)NHEADS * SEQ * SEQ, (long)SEQ * SEQ,
        (long)NHEADS * HDIM * SEQ, (long)HDIM * SEQ,
        (long)SEQ * D_MODEL, (long)HDIM, NHEADS, 1.0f, 0);

    // 6) q = x + attn @ w_o + b_o
    mm_tf32<128><<<dim3(8, 32, 1), 256, SMEMB(128)>>>(
        attn, wto, b_o, x, q, D_MODEL, D_MODEL, D_MODEL, D_MODEL,
        0, 0, 0, 0, 0, 0, 1, 1.0f, 0);

    // 7) kv = z @ w_kv + b_kv
    mm_tf32<128><<<dim3(16, 32, 1), 256, SMEMB(128)>>>(
        zin, wtkv, b_kv, nullptr, kv, D_MODEL, D_MODEL, D_MODEL, 2 * D_MODEL,
        0, 0, 0, 0, 0, 0, 1, 1.0f, 0);

    // transpose cross V: per b: [S,D] -> [D,S]
    transpose_k<<<dim3(32, 32, BATCH), tb>>>(
        kv + D_MODEL, vtc, 2 * D_MODEL, SEQ,
        (long)SEQ * 2 * D_MODEL, 0, (long)D_MODEL * SEQ, 0, 1);

    // 8) cross scores = q @ k^T / 32
    mm_tf32<128><<<dim3(8, 8, BATCH), 256, SMEMB(128)>>>(
        q, kv, nullptr, nullptr, scores, D_MODEL, D_MODEL, 2 * D_MODEL, SEQ,
        (long)SEQ * D_MODEL, 0, (long)SEQ * 2 * D_MODEL, 0,
        (long)SEQ * SEQ, 0, 1, 0.03125f, 0);

    // 9) softmax
    softmax_rows<<<BATCH * SEQ, 256>>>(scores);

    // 10) cross P @ V
    mm_tf32<128><<<dim3(8, 8, BATCH), 256, SMEMB(128)>>>(
        scores, vtc, nullptr, nullptr, cross, SEQ, SEQ, SEQ, D_MODEL,
        (long)SEQ * SEQ, 0, (long)D_MODEL * SEQ, 0, (long)SEQ * D_MODEL, 0,
        1, 1.0f, 0);

    // 11) ln2
    ln_kernel<<<ROWS, 256>>>(cross, g2, b2, ln);

    // 12) mlp hidden = gelu(ln2 @ w_m1 + b_m1)
    mm_tf32<128><<<dim3(32, 32, 1), 256, SMEMB(128)>>>(
        ln, wtm1, b_m1, nullptr, mlp, D_MODEL, D_MODEL, D_MODEL, HMLP,
        0, 0, 0, 0, 0, 0, 1, 1.0f, 1);

    // 13) out = cross + mlp @ w_m2 + b_m2
    mm_tf32<128><<<dim3(8, 32, 1), 256, SMEMB(128)>>>(
        mlp, wtm2, b_m2, cross, out, HMLP, HMLP, HMLP, D_MODEL,
        0, 0, 0, 0, 0, 0, 1, 1.0f, 0);
}

// round 5
// speedup vs baseline: 3.1453x; 1.4870x over previous
#include <cuda_runtime.h>
#include <cuda_fp16.h>
#include <math.h>
#include <stdint.h>

#define D_MODEL 1024
#define BATCH   4
#define SEQ     1024
#define NHEADS  16
#define HDIM    64
#define HMLP    4096
#define ROWS    (BATCH*SEQ)     // 4096

// ---------------- scratch (device globals; no allocs allowed) ----------------
__device__ float g_ln   [ROWS * D_MODEL];
__device__ float g_qkv  [ROWS * 3 * D_MODEL];
__device__ float g_kv   [ROWS * 2 * D_MODEL];
__device__ float g_attn [ROWS * D_MODEL];
__device__ float g_q    [ROWS * D_MODEL];
__device__ float g_cross[ROWS * D_MODEL];
__device__ float g_mlp  [ROWS * HMLP];
__device__ float g_scores[(size_t)BATCH * NHEADS * SEQ * SEQ];  // 268MB
// transposed operands (all GEMMs NT: B stored [N][K] row-major)
__device__ float g_wt_qkv[3 * D_MODEL * D_MODEL];
__device__ float g_wt_o  [D_MODEL * D_MODEL];
__device__ float g_wt_kv [2 * D_MODEL * D_MODEL];
__device__ float g_wt_m1 [HMLP * D_MODEL];
__device__ float g_wt_m2 [D_MODEL * HMLP];
__device__ float g_vt_self [BATCH * NHEADS * HDIM * SEQ];
__device__ float g_vt_cross[(size_t)BATCH * D_MODEL * SEQ];

__device__ __forceinline__ float gelu_tanh(float c) {
    float t = 0.7978845608028654f * (c + 0.044715f * c * c * c);
    return 0.5f * c * (1.0f + tanhf(t));
}
__device__ __forceinline__ void mma_f16(float* d, const uint32_t* a, const uint32_t* b) {
    asm volatile("mma.sync.aligned.m16n8k16.row.col.f32.f16.f16.f32 "
        "{%0,%1,%2,%3}, {%4,%5,%6,%7}, {%8,%9}, {%0,%1,%2,%3};"
        : "+f"(d[0]), "+f"(d[1]), "+f"(d[2]), "+f"(d[3])
        : "r"(a[0]), "r"(a[1]), "r"(a[2]), "r"(a[3]), "r"(b[0]), "r"(b[1]));
}

// ---------------- layernorm ----------------
__global__ void ln_kernel(const float* __restrict__ x, const float* __restrict__ g,
                          const float* __restrict__ b, float* __restrict__ out) {
    int row = blockIdx.x;
    const float* xr = x + (size_t)row * D_MODEL;
    float* orow = out + (size_t)row * D_MODEL;
    int tid = threadIdx.x;
    float s = 0.f, s2 = 0.f;
    for (int i = tid; i < D_MODEL; i += 256) {
        float v = xr[i]; s += v; s2 += v * v;
    }
    __shared__ float red[256], red2[256];
    red[tid] = s; red2[tid] = s2; __syncthreads();
    for (int o = 128; o > 0; o >>= 1) {
        if (tid < o) { red[tid] += red[tid + o]; red2[tid] += red2[tid + o]; }
        __syncthreads();
    }
    float mu  = red[0]  * (1.0f / D_MODEL);
    float var = red2[0] * (1.0f / D_MODEL) - mu * mu;
    float inv = rsqrtf(var + 1e-5f);
    for (int i = tid; i < D_MODEL; i += 256)
        orow[i] = (xr[i] - mu) * inv * g[i] + b[i];
}

// ---------------- one-pass softmax (1024 cols) ----------------
__global__ void softmax_rows(float* __restrict__ S) {
    float* row = S + (size_t)blockIdx.x * 1024;
    int tid = threadIdx.x;
    float4 v = *(float4*)(row + tid * 4);
    float mx = fmaxf(fmaxf(v.x, v.y), fmaxf(v.z, v.w));
    __shared__ float red[32];
    for (int o = 16; o > 0; o >>= 1) mx = fmaxf(mx, __shfl_xor_sync(0xffffffff, mx, o));
    if ((tid & 31) == 0) red[tid >> 5] = mx;
    __syncthreads();
    if (tid < 32) {
        float m = (tid < 8) ? red[tid] : -1e30f;
        for (int o = 4; o > 0; o >>= 1) m = fmaxf(m, __shfl_xor_sync(0xffffffff, m, o));
        red[0] = m;
    }
    __syncthreads();
    mx = red[0];
    v.x = expf(v.x - mx); v.y = expf(v.y - mx); v.z = expf(v.z - mx); v.w = expf(v.w - mx);
    float s = v.x + v.y + v.z + v.w;
    for (int o = 16; o > 0; o >>= 1) s += __shfl_xor_sync(0xffffffff, s, o);
    __syncthreads();
    if ((tid & 31) == 0) red[tid >> 5] = s;
    __syncthreads();
    if (tid < 32) {
        float t = (tid < 8) ? red[tid] : 0.f;
        for (int o = 4; o > 0; o >>= 1) t += __shfl_xor_sync(0xffffffff, t, o);
        red[0] = t;
    }
    __syncthreads();
    float inv = 1.0f / red[0];
    v.x *= inv; v.y *= inv; v.z *= inv; v.w *= inv;
    *(float4*)(row + tid * 4) = v;
}

// ---------------- batched transpose ----------------
__global__ void transpose_k(const float* __restrict__ srcb, float* __restrict__ dstb,
                            int lds, int ldd, long sSb, long sSh, long sDb, long sDh, int nh) {
    int z = blockIdx.z, b = z / nh, h = z - b * nh;
    const float* src = srcb + (size_t)b * sSb + (size_t)h * sSh;
    float* dst = dstb + (size_t)b * sDb + (size_t)h * sDh;
    __shared__ float tile[32][33];
    int x = blockIdx.x * 32, y = blockIdx.y * 32;
    int tx = threadIdx.x, ty = threadIdx.y;
    #pragma unroll
    for (int i = ty; i < 32; i += 8)
        tile[i][tx] = src[(size_t)(y + i) * lds + x + tx];
    __syncthreads();
    #pragma unroll
    for (int i = ty; i < 32; i += 8)
        dst[(size_t)(x + i) * ldd + y + tx] = tile[tx][i];
}

// ============ fp16 mma.sync GEMM: C[M,N] = scale * A[M,K] @ B[N,K]^T (+bias)(+gelu)(+res)
// TM=128 x TN, KB=32 (= 2 x k16), 8 warps, double-buffered half SMEM.
// Row = 16 b32 words (32 halves), padded to LDSROW=24 words (stride mod 32 = 24
// -> rows land at bank offsets {0,24,16,8}: conflict-free LDS.64 fragment loads).
// Word permutation within each 8-word k16 group: slot(j) = 2*(j&3) + (j>>2), so
// thread c's needed words {c, c+4} sit at slots {2c, 2c+1} -> one ld.shared.v2.b32.
#define LDSROW 24

template <int TN>
__global__ void __launch_bounds__(256)
mm_f16(const float* __restrict__ Abase, const float* __restrict__ Bbase,
       const float* __restrict__ bias, const float* __restrict__ resbase,
       float* __restrict__ Cbase, int K, int lda, int ldb, int ldc,
       long sAb, long sAh, long sBb, long sBh, long sCb, long sCh,
       int nh, float scale, int act) {
    constexpr int TM = 128;
    constexpr int WX = (TN == 128) ? 4 : 2;   // warps along n
    constexpr int WY = 8 / WX;                // warps along m
    constexpr int WNT = TN / WX;              // 32
    constexpr int WMT = TM / WY;              // 64 or 32
    constexpr int MI = WMT / 16;
    constexpr int NI = WNT / 8;
    constexpr int NA = TM * 32 / (256 * 4);   // float4s per thread for A (4)
    constexpr int NB = TN * 32 / (256 * 4);   // for B (4 or 2)

    extern __shared__ uint32_t sm[];
    uint32_t* Ast[2] = { sm, sm + TM * LDSROW };
    uint32_t* Bst[2] = { sm + 2 * TM * LDSROW, sm + 2 * TM * LDSROW + TN * LDSROW };

    int tid = threadIdx.x, lane = tid & 31, warp = tid >> 5;
    int wy = warp % WY, wx = warp / WY;
    int z = blockIdx.z, b = z / nh, h = z - b * nh;
    const float* A = Abase + (size_t)b * sAb + (size_t)h * sAh + (size_t)blockIdx.y * TM * lda;
    const float* B = Bbase + (size_t)b * sBb + (size_t)h * sBh + (size_t)blockIdx.x * TN * ldb;
    float* C = Cbase + (size_t)b * sCb + (size_t)h * sCh;
    const float* res = resbase ? resbase + (size_t)b * sCb + (size_t)h * sCh : nullptr;
    int m0 = blockIdx.y * TM, n0 = blockIdx.x * TN;

    float acc[MI][NI][4];
    #pragma unroll
    for (int mi = 0; mi < MI; mi++)
        #pragma unroll
        for (int ni = 0; ni < NI; ni++)
            #pragma unroll
            for (int c = 0; c < 4; c++) acc[mi][ni][c] = 0.f;

    // store float4 at k-offset kq*4 (kq=0..7) within KB, converted to f16x2 pairs
    auto sts_perm = [&](uint32_t* stg, int row, int kq, float4 v) {
        __half2 w0 = __floats2half2_rn(v.x, v.y);
        __half2 w1 = __floats2half2_rn(v.z, v.w);
        int g = kq >> 2;                 // k16 group (0 or 1)
        int j0 = 2 * (kq & 3);           // word index within group
        int s0 = 2 * (j0 & 3) + (j0 >> 2);
        int j1 = j0 + 1;
        int s1 = 2 * (j1 & 3) + (j1 >> 2);
        uint32_t* p = stg + row * LDSROW + g * 8;
        p[s0] = *(uint32_t*)&w0;
        p[s1] = *(uint32_t*)&w1;
    };

    int nkb = K >> 5;
    // prologue: stage 0
    {
        #pragma unroll
        for (int i = 0; i < NA; i++) {
            int f = i * 256 + tid, row = f >> 3, kq = f & 7;
            sts_perm(Ast[0], row, kq, *(const float4*)(A + (size_t)row * lda + kq * 4));
        }
        #pragma unroll
        for (int i = 0; i < NB; i++) {
            int f = i * 256 + tid, row = f >> 3, kq = f & 7;
            sts_perm(Bst[0], row, kq, *(const float4*)(B + (size_t)row * ldb + kq * 4));
        }
    }
    __syncthreads();

    for (int kb = 0; kb < nkb; kb++) {
        int cur = kb & 1;
        float4 pa[NA], pb[NB];
        if (kb + 1 < nkb) {
            int koff = (kb + 1) * 32;
            #pragma unroll
            for (int i = 0; i < NA; i++) {
                int f = i * 256 + tid, row = f >> 3, kq = f & 7;
                pa[i] = *(const float4*)(A + (size_t)row * lda + koff + kq * 4);
            }
            #pragma unroll
            for (int i = 0; i < NB; i++) {
                int f = i * 256 + tid, row = f >> 3, kq = f & 7;
                pb[i] = *(const float4*)(B + (size_t)row * ldb + koff + kq * 4);
            }
        }
        const uint32_t* Ac = Ast[cur];
        const uint32_t* Bc = Bst[cur];
        #pragma unroll
        for (int kk = 0; kk < 2; kk++) {            // two k16 steps per KB=32
            int g8 = kk * 8;
            int co = 2 * (lane & 3);
            uint32_t afr[MI][4], bfr[NI][2];
            #pragma unroll
            for (int mi = 0; mi < MI; mi++) {
                int r = wy * WMT + mi * 16 + (lane >> 2);
                uint2 lo = *(const uint2*)&Ac[r * LDSROW + g8 + co];        // (a0, a2)
                uint2 hi = *(const uint2*)&Ac[(r + 8) * LDSROW + g8 + co];  // (a1, a3)
                afr[mi][0] = lo.x; afr[mi][1] = hi.x;
                afr[mi][2] = lo.y; afr[mi][3] = hi.y;
            }
            #pragma unroll
            for (int ni = 0; ni < NI; ni++) {
                int rn = wx * WNT + ni * 8 + (lane >> 2);
                uint2 bb = *(const uint2*)&Bc[rn * LDSROW + g8 + co];       // (b0, b1)
                bfr[ni][0] = bb.x; bfr[ni][1] = bb.y;
            }
            #pragma unroll
            for (int mi = 0; mi < MI; mi++)
                #pragma unroll
                for (int ni = 0; ni < NI; ni++)
                    mma_f16(acc[mi][ni], afr[mi], bfr[ni]);
        }
        if (kb + 1 < nkb) {
            int nxt = cur ^ 1;
            __syncthreads();
            #pragma unroll
            for (int i = 0; i < NA; i++) {
                int f = i * 256 + tid, row = f >> 3, kq = f & 7;
                sts_perm(Ast[nxt], row, kq, pa[i]);
            }
            #pragma unroll
            for (int i = 0; i < NB; i++) {
                int f = i * 256 + tid, row = f >> 3, kq = f & 7;
                sts_perm(Bst[nxt], row, kq, pb[i]);
            }
            __syncthreads();
        }
    }

    // epilogue
    #pragma unroll
    for (int mi = 0; mi < MI; mi++) {
        #pragma unroll
        for (int ni = 0; ni < NI; ni++) {
            int col = n0 + wx * WNT + ni * 8 + 2 * (lane & 3);
            #pragma unroll
            for (int half = 0; half < 2; half++) {
                int row = m0 + wy * WMT + mi * 16 + (lane >> 2) + half * 8;
                float c0 = acc[mi][ni][2 * half]     * scale;
                float c1 = acc[mi][ni][2 * half + 1] * scale;
                if (bias) { c0 += bias[col]; c1 += bias[col + 1]; }
                if (act == 1) { c0 = gelu_tanh(c0); c1 = gelu_tanh(c1); }
                if (res) {
                    float2 rv = *(const float2*)(res + (size_t)row * ldc + col);
                    c0 += rv.x; c1 += rv.y;
                }
                float2 o; o.x = c0; o.y = c1;
                *(float2*)(C + (size_t)row * ldc + col) = o;
            }
        }
    }
}

#define SMEMB(TN) ((2 * 128 * LDSROW + 2 * (TN) * LDSROW) * 4)

// ---------------- host launch ----------------
extern "C" void kernel_launch(void* const* d_in, const int* in_sizes, int n_in,
                              void* d_out, int out_size) {
    const float* x     = (const float*)d_in[0];
    const float* zin   = (const float*)d_in[1];
    const float* g1    = (const float*)d_in[2];
    const float* b1    = (const float*)d_in[3];
    const float* w_qkv = (const float*)d_in[4];
    const float* b_qkv = (const float*)d_in[5];
    const float* w_o   = (const float*)d_in[6];
    const float* b_o   = (const float*)d_in[7];
    const float* w_kv  = (const float*)d_in[8];
    const float* b_kv  = (const float*)d_in[9];
    const float* g2    = (const float*)d_in[10];
    const float* b2    = (const float*)d_in[11];
    const float* w_m1  = (const float*)d_in[12];
    const float* b_m1  = (const float*)d_in[13];
    const float* w_m2  = (const float*)d_in[14];
    const float* b_m2  = (const float*)d_in[15];
    float* out = (float*)d_out;

    float *ln, *qkv, *kv, *attn, *q, *cross, *mlp, *scores;
    float *wtqkv, *wto, *wtkv, *wtm1, *wtm2, *vts, *vtc;
    cudaGetSymbolAddress((void**)&ln,     g_ln);
    cudaGetSymbolAddress((void**)&qkv,    g_qkv);
    cudaGetSymbolAddress((void**)&kv,     g_kv);
    cudaGetSymbolAddress((void**)&attn,   g_attn);
    cudaGetSymbolAddress((void**)&q,      g_q);
    cudaGetSymbolAddress((void**)&cross,  g_cross);
    cudaGetSymbolAddress((void**)&mlp,    g_mlp);
    cudaGetSymbolAddress((void**)&scores, g_scores);
    cudaGetSymbolAddress((void**)&wtqkv,  g_wt_qkv);
    cudaGetSymbolAddress((void**)&wto,    g_wt_o);
    cudaGetSymbolAddress((void**)&wtkv,   g_wt_kv);
    cudaGetSymbolAddress((void**)&wtm1,   g_wt_m1);
    cudaGetSymbolAddress((void**)&wtm2,   g_wt_m2);
    cudaGetSymbolAddress((void**)&vts,    g_vt_self);
    cudaGetSymbolAddress((void**)&vtc,    g_vt_cross);

    cudaFuncSetAttribute(mm_f16<128>, cudaFuncAttributeMaxDynamicSharedMemorySize, SMEMB(128));
    cudaFuncSetAttribute(mm_f16<64>,  cudaFuncAttributeMaxDynamicSharedMemorySize, SMEMB(64));

    dim3 tb(32, 8);

    // weight transposes ([K][N] -> [N][K])
    transpose_k<<<dim3(3 * D_MODEL / 32, D_MODEL / 32, 1), tb>>>(w_qkv, wtqkv, 3 * D_MODEL, D_MODEL, 0, 0, 0, 0, 1);
    transpose_k<<<dim3(D_MODEL / 32, D_MODEL / 32, 1), tb>>>(w_o, wto, D_MODEL, D_MODEL, 0, 0, 0, 0, 1);
    transpose_k<<<dim3(2 * D_MODEL / 32, D_MODEL / 32, 1), tb>>>(w_kv, wtkv, 2 * D_MODEL, D_MODEL, 0, 0, 0, 0, 1);
    transpose_k<<<dim3(HMLP / 32, D_MODEL / 32, 1), tb>>>(w_m1, wtm1, HMLP, D_MODEL, 0, 0, 0, 0, 1);
    transpose_k<<<dim3(D_MODEL / 32, HMLP / 32, 1), tb>>>(w_m2, wtm2, D_MODEL, HMLP, 0, 0, 0, 0, 1);

    // 1) ln1(x)
    ln_kernel<<<ROWS, 256>>>(x, g1, b1, ln);

    // 2) qkv = ln1 @ w_qkv + b_qkv
    mm_f16<128><<<dim3(24, 32, 1), 256, SMEMB(128)>>>(
        ln, wtqkv, b_qkv, nullptr, qkv, D_MODEL, D_MODEL, D_MODEL, 3 * D_MODEL,
        0, 0, 0, 0, 0, 0, 1, 1.0f, 0);

    // transpose self V: per (b,h): [S,64] -> [64,S]
    transpose_k<<<dim3(2, 32, BATCH * NHEADS), tb>>>(
        qkv + 2 * D_MODEL, vts, 3 * D_MODEL, SEQ,
        (long)SEQ * 3 * D_MODEL, HDIM, (long)NHEADS * HDIM * SEQ, (long)HDIM * SEQ, NHEADS);

    // 3) self scores = Q @ K^T / 8
    mm_f16<128><<<dim3(8, 8, BATCH * NHEADS), 256, SMEMB(128)>>>(
        qkv, qkv + D_MODEL, nullptr, nullptr, scores, HDIM, 3 * D_MODEL, 3 * D_MODEL, SEQ,
        (long)SEQ * 3 * D_MODEL, HDIM, (long)SEQ * 3 * D_MODEL, HDIM,
        (long)NHEADS * SEQ * SEQ, (long)SEQ * SEQ, NHEADS, 0.125f, 0);

    // 4) softmax
    softmax_rows<<<BATCH * NHEADS * SEQ, 256>>>(scores);

    // 5) self P @ V
    mm_f16<64><<<dim3(1, 8, BATCH * NHEADS), 256, SMEMB(64)>>>(
        scores, vts, nullptr, nullptr, attn, SEQ, SEQ, SEQ, D_MODEL,
        (long)NHEADS * SEQ * SEQ, (long)SEQ * SEQ,
        (long)NHEADS * HDIM * SEQ, (long)HDIM * SEQ,
        (long)SEQ * D_MODEL, (long)HDIM, NHEADS, 1.0f, 0);

    // 6) q = x + attn @ w_o + b_o
    mm_f16<128><<<dim3(8, 32, 1), 256, SMEMB(128)>>>(
        attn, wto, b_o, x, q, D_MODEL, D_MODEL, D_MODEL, D_MODEL,
        0, 0, 0, 0, 0, 0, 1, 1.0f, 0);

    // 7) kv = z @ w_kv + b_kv
    mm_f16<128><<<dim3(16, 32, 1), 256, SMEMB(128)>>>(
        zin, wtkv, b_kv, nullptr, kv, D_MODEL, D_MODEL, D_MODEL, 2 * D_MODEL,
        0, 0, 0, 0, 0, 0, 1, 1.0f, 0);

    // transpose cross V: per b: [S,D] -> [D,S]
    transpose_k<<<dim3(32, 32, BATCH), tb>>>(
        kv + D_MODEL, vtc, 2 * D_MODEL, SEQ,
        (long)SEQ * 2 * D_MODEL, 0, (long)D_MODEL * SEQ, 0, 1);

    // 8) cross scores = q @ k^T / 32
    mm_f16<128><<<dim3(8, 8, BATCH), 256, SMEMB(128)>>>(
        q, kv, nullptr, nullptr, scores, D_MODEL, D_MODEL, 2 * D_MODEL, SEQ,
        (long)SEQ * D_MODEL, 0, (long)SEQ * 2 * D_MODEL, 0,
        (long)SEQ * SEQ, 0, 1, 0.03125f, 0);

    // 9) softmax
    softmax_rows<<<BATCH * SEQ, 256>>>(scores);

    // 10) cross P @ V
    mm_f16<128><<<dim3(8, 8, BATCH), 256, SMEMB(128)>>>(
        scores, vtc, nullptr, nullptr, cross, SEQ, SEQ, SEQ, D_MODEL,
        (long)SEQ * SEQ, 0, (long)D_MODEL * SEQ, 0, (long)SEQ * D_MODEL, 0,
        1, 1.0f, 0);

    // 11) ln2
    ln_kernel<<<ROWS, 256>>>(cross, g2, b2, ln);

    // 12) mlp hidden = gelu(ln2 @ w_m1 + b_m1)
    mm_f16<128><<<dim3(32, 32, 1), 256, SMEMB(128)>>>(
        ln, wtm1, b_m1, nullptr, mlp, D_MODEL, D_MODEL, D_MODEL, HMLP,
        0, 0, 0, 0, 0, 0, 1, 1.0f, 1);

    // 13) out = cross + mlp @ w_m2 + b_m2
    mm_f16<128><<<dim3(8, 32, 1), 256, SMEMB(128)>>>(
        mlp, wtm2, b_m2, cross, out, HMLP, HMLP, HMLP, D_MODEL,
        0, 0, 0, 0, 0, 0, 1, 1.0f, 0);
}

// round 6
// speedup vs baseline: 3.4263x; 1.0894x over previous
#include <cuda_runtime.h>
#include <cuda_fp16.h>
#include <math.h>
#include <stdint.h>

#define D_MODEL 1024
#define BATCH   4
#define SEQ     1024
#define NHEADS  16
#define HDIM    64
#define HMLP    4096
#define ROWS    (BATCH*SEQ)     // 4096

// ---------------- scratch (device globals; no allocs allowed) ----------------
__device__ __half h_ln   [ROWS * D_MODEL];
__device__ __half h_qkv  [ROWS * 3 * D_MODEL];
__device__ __half h_kv   [ROWS * 2 * D_MODEL];
__device__ __half h_attn [ROWS * D_MODEL];
__device__ __half h_q    [ROWS * D_MODEL];
__device__ float  g_cross[ROWS * D_MODEL];
__device__ __half h_mlp  [ROWS * HMLP];
__device__ __half h_scores[(size_t)BATCH * NHEADS * SEQ * SEQ];  // 134MB self
__device__ float  g_xs   [(size_t)BATCH * SEQ * SEQ];            // cross logits fp32
__device__ __half h_p    [(size_t)BATCH * SEQ * SEQ];            // cross P fp16
__device__ __half h_z    [ROWS * D_MODEL];
__device__ __half h_wt_qkv[3 * D_MODEL * D_MODEL];
__device__ __half h_wt_o  [D_MODEL * D_MODEL];
__device__ __half h_wt_kv [2 * D_MODEL * D_MODEL];
__device__ __half h_wt_m1 [HMLP * D_MODEL];
__device__ __half h_wt_m2 [D_MODEL * HMLP];
__device__ __half h_vt_self [BATCH * NHEADS * HDIM * SEQ];
__device__ __half h_vt_cross[(size_t)BATCH * D_MODEL * SEQ];

__device__ __forceinline__ float gelu_tanh(float c) {
    float t = 0.7978845608028654f * (c + 0.044715f * c * c * c);
    return 0.5f * c * (1.0f + tanhf(t));
}
__device__ __forceinline__ void mma_f16(float* d, const uint32_t* a, const uint32_t* b) {
    asm volatile("mma.sync.aligned.m16n8k16.row.col.f32.f16.f16.f32 "
        "{%0,%1,%2,%3}, {%4,%5,%6,%7}, {%8,%9}, {%0,%1,%2,%3};"
        : "+f"(d[0]), "+f"(d[1]), "+f"(d[2]), "+f"(d[3])
        : "r"(a[0]), "r"(a[1]), "r"(a[2]), "r"(a[3]), "r"(b[0]), "r"(b[1]));
}
__device__ __forceinline__ void store2(__half* p, float a, float b) {
    *(__half2*)p = __floats2half2_rn(a, b);
}
__device__ __forceinline__ void store2(float* p, float a, float b) {
    float2 v; v.x = a; v.y = b; *(float2*)p = v;
}

// ---------------- layernorm (fp32 in -> fp16 out) ----------------
__global__ void ln_kernel(const float* __restrict__ x, const float* __restrict__ g,
                          const float* __restrict__ b, __half* __restrict__ out) {
    int row = blockIdx.x;
    const float* xr = x + (size_t)row * D_MODEL;
    __half* orow = out + (size_t)row * D_MODEL;
    int tid = threadIdx.x;
    float s = 0.f, s2 = 0.f;
    for (int i = tid; i < D_MODEL; i += 256) {
        float v = xr[i]; s += v; s2 += v * v;
    }
    __shared__ float red[256], red2[256];
    red[tid] = s; red2[tid] = s2; __syncthreads();
    for (int o = 128; o > 0; o >>= 1) {
        if (tid < o) { red[tid] += red[tid + o]; red2[tid] += red2[tid + o]; }
        __syncthreads();
    }
    float mu  = red[0]  * (1.0f / D_MODEL);
    float var = red2[0] * (1.0f / D_MODEL) - mu * mu;
    float inv = rsqrtf(var + 1e-5f);
    for (int i = tid; i < D_MODEL; i += 512) {
        float v0 = (xr[i] - mu) * inv * g[i] + b[i];
        float v1 = (xr[i + 256] - mu) * inv * g[i + 256] + b[i + 256];
        orow[i] = __float2half(v0);
        orow[i + 256] = __float2half(v1);
    }
}

// ---------------- one-pass softmax, fp16 in/out (1024 cols) ----------------
__global__ void softmax_h(__half* __restrict__ S) {
    __half* row = S + (size_t)blockIdx.x * 1024;
    int tid = threadIdx.x;
    __half2 h2[2];
    *(uint2*)h2 = *(const uint2*)(row + tid * 4);
    float2 f0 = __half22float2(h2[0]);
    float2 f1 = __half22float2(h2[1]);
    float mx = fmaxf(fmaxf(f0.x, f0.y), fmaxf(f1.x, f1.y));
    __shared__ float red[32];
    for (int o = 16; o > 0; o >>= 1) mx = fmaxf(mx, __shfl_xor_sync(0xffffffff, mx, o));
    if ((tid & 31) == 0) red[tid >> 5] = mx;
    __syncthreads();
    if (tid < 32) {
        float m = (tid < 8) ? red[tid] : -1e30f;
        for (int o = 4; o > 0; o >>= 1) m = fmaxf(m, __shfl_xor_sync(0xffffffff, m, o));
        red[0] = m;
    }
    __syncthreads();
    mx = red[0];
    f0.x = expf(f0.x - mx); f0.y = expf(f0.y - mx);
    f1.x = expf(f1.x - mx); f1.y = expf(f1.y - mx);
    float s = f0.x + f0.y + f1.x + f1.y;
    for (int o = 16; o > 0; o >>= 1) s += __shfl_xor_sync(0xffffffff, s, o);
    __syncthreads();
    if ((tid & 31) == 0) red[tid >> 5] = s;
    __syncthreads();
    if (tid < 32) {
        float t = (tid < 8) ? red[tid] : 0.f;
        for (int o = 4; o > 0; o >>= 1) t += __shfl_xor_sync(0xffffffff, t, o);
        red[0] = t;
    }
    __syncthreads();
    float inv = 1.0f / red[0];
    h2[0] = __floats2half2_rn(f0.x * inv, f0.y * inv);
    h2[1] = __floats2half2_rn(f1.x * inv, f1.y * inv);
    *(uint2*)(row + tid * 4) = *(uint2*)h2;
}

// ---------------- softmax fp32 in -> fp16 out ----------------
__global__ void softmax_f2h(const float* __restrict__ S, __half* __restrict__ P) {
    const float* row = S + (size_t)blockIdx.x * 1024;
    __half* prow = P + (size_t)blockIdx.x * 1024;
    int tid = threadIdx.x;
    float4 v = *(const float4*)(row + tid * 4);
    float mx = fmaxf(fmaxf(v.x, v.y), fmaxf(v.z, v.w));
    __shared__ float red[32];
    for (int o = 16; o > 0; o >>= 1) mx = fmaxf(mx, __shfl_xor_sync(0xffffffff, mx, o));
    if ((tid & 31) == 0) red[tid >> 5] = mx;
    __syncthreads();
    if (tid < 32) {
        float m = (tid < 8) ? red[tid] : -1e30f;
        for (int o = 4; o > 0; o >>= 1) m = fmaxf(m, __shfl_xor_sync(0xffffffff, m, o));
        red[0] = m;
    }
    __syncthreads();
    mx = red[0];
    v.x = expf(v.x - mx); v.y = expf(v.y - mx); v.z = expf(v.z - mx); v.w = expf(v.w - mx);
    float s = v.x + v.y + v.z + v.w;
    for (int o = 16; o > 0; o >>= 1) s += __shfl_xor_sync(0xffffffff, s, o);
    __syncthreads();
    if ((tid & 31) == 0) red[tid >> 5] = s;
    __syncthreads();
    if (tid < 32) {
        float t = (tid < 8) ? red[tid] : 0.f;
        for (int o = 4; o > 0; o >>= 1) t += __shfl_xor_sync(0xffffffff, t, o);
        red[0] = t;
    }
    __syncthreads();
    float inv = 1.0f / red[0];
    __half2 h2[2];
    h2[0] = __floats2half2_rn(v.x * inv, v.y * inv);
    h2[1] = __floats2half2_rn(v.z * inv, v.w * inv);
    *(uint2*)(prow + tid * 4) = *(uint2*)h2;
}

// ---------------- batched transpose (TS in -> half out) ----------------
template <typename TS>
__global__ void transpose_h(const TS* __restrict__ srcb, __half* __restrict__ dstb,
                            int lds, int ldd, long sSb, long sSh, long sDb, long sDh, int nh) {
    int z = blockIdx.z, b = z / nh, h = z - b * nh;
    const TS* src = srcb + (size_t)b * sSb + (size_t)h * sSh;
    __half* dst = dstb + (size_t)b * sDb + (size_t)h * sDh;
    __shared__ __half tile[32][34];
    int x = blockIdx.x * 32, y = blockIdx.y * 32;
    int tx = threadIdx.x, ty = threadIdx.y;
    #pragma unroll
    for (int i = ty; i < 32; i += 8)
        tile[i][tx] = __float2half((float)src[(size_t)(y + i) * lds + x + tx]);
    __syncthreads();
    #pragma unroll
    for (int i = ty; i < 32; i += 8)
        dst[(size_t)(x + i) * ldd + y + tx] = tile[tx][i];
}

// ---------------- fp32 -> fp16 elementwise ----------------
__global__ void cvt_f2h(const float* __restrict__ src, __half* __restrict__ dst, int n8) {
    int i = blockIdx.x * 256 + threadIdx.x;
    if (i < n8) {
        float4 a = *(const float4*)(src + (size_t)i * 8);
        float4 b = *(const float4*)(src + (size_t)i * 8 + 4);
        __half2 h[4];
        h[0] = __floats2half2_rn(a.x, a.y); h[1] = __floats2half2_rn(a.z, a.w);
        h[2] = __floats2half2_rn(b.x, b.y); h[3] = __floats2half2_rn(b.z, b.w);
        *(uint4*)(dst + (size_t)i * 8) = *(uint4*)h;
    }
}

// ============ fp16 mma.sync GEMM: C[M,N] = scale * A[M,K] @ B[N,K]^T (+bias)(+gelu)(+res)
// A, B fp16 gmem; C is CT (half or float); res/bias fp32.
// TM=128 x TN, KB=32, 8 warps, double-buffered SMEM (row = 16 b32 words pad LDSROW=24).
#define LDSROW 24

template <int TN, typename CT>
__global__ void __launch_bounds__(256)
mm_h(const __half* __restrict__ Abase, const __half* __restrict__ Bbase,
     const float* __restrict__ bias, const float* __restrict__ resbase,
     CT* __restrict__ Cbase, int K, int lda, int ldb, int ldc,
     long sAb, long sAh, long sBb, long sBh, long sCb, long sCh,
     int nh, float scale, int act) {
    constexpr int TM = 128;
    constexpr int WX = (TN == 128) ? 4 : 2;
    constexpr int WY = 8 / WX;
    constexpr int WNT = TN / WX;              // 32
    constexpr int WMT = TM / WY;              // 64 or 32
    constexpr int MI = WMT / 16;
    constexpr int NI = WNT / 8;
    constexpr int NA = TM * 4 / 256;          // uint4 loads per thread for A (2)
    constexpr int NB = TN * 4 / 256;          // for B (2 or 1)

    extern __shared__ uint32_t sm[];
    uint32_t* Ast[2] = { sm, sm + TM * LDSROW };
    uint32_t* Bst[2] = { sm + 2 * TM * LDSROW, sm + 2 * TM * LDSROW + TN * LDSROW };

    int tid = threadIdx.x, lane = tid & 31, warp = tid >> 5;
    int wy = warp % WY, wx = warp / WY;
    int z = blockIdx.z, b = z / nh, h = z - b * nh;
    const __half* A = Abase + (size_t)b * sAb + (size_t)h * sAh + (size_t)blockIdx.y * TM * lda;
    const __half* B = Bbase + (size_t)b * sBb + (size_t)h * sBh + (size_t)blockIdx.x * TN * ldb;
    CT* C = Cbase + (size_t)b * sCb + (size_t)h * sCh;
    const float* res = resbase ? resbase + (size_t)b * sCb + (size_t)h * sCh : nullptr;
    int m0 = blockIdx.y * TM, n0 = blockIdx.x * TN;

    float acc[MI][NI][4];
    #pragma unroll
    for (int mi = 0; mi < MI; mi++)
        #pragma unroll
        for (int ni = 0; ni < NI; ni++)
            #pragma unroll
            for (int c = 0; c < 4; c++) acc[mi][ni][c] = 0.f;

    // store uint4 (words 4q..4q+3 of this row's KB) into permuted smem
    auto sts_q = [&](uint32_t* stg, int row, int q, uint4 v) {
        int g = q >> 1, hh = q & 1;
        uint32_t* p = stg + row * LDSROW + g * 8 + hh;
        p[0] = v.x; p[2] = v.y; p[4] = v.z; p[6] = v.w;
    };

    int nkb = K >> 5;
    {
        #pragma unroll
        for (int i = 0; i < NA; i++) {
            int f = i * 256 + tid, row = f >> 2, q = f & 3;
            sts_q(Ast[0], row, q, *(const uint4*)(A + (size_t)row * lda + q * 8));
        }
        #pragma unroll
        for (int i = 0; i < NB; i++) {
            int f = i * 256 + tid, row = f >> 2, q = f & 3;
            sts_q(Bst[0], row, q, *(const uint4*)(B + (size_t)row * ldb + q * 8));
        }
    }
    __syncthreads();

    for (int kb = 0; kb < nkb; kb++) {
        int cur = kb & 1;
        uint4 pa[NA], pb[NB];
        if (kb + 1 < nkb) {
            int koff = (kb + 1) * 32;
            #pragma unroll
            for (int i = 0; i < NA; i++) {
                int f = i * 256 + tid, row = f >> 2, q = f & 3;
                pa[i] = *(const uint4*)(A + (size_t)row * lda + koff + q * 8);
            }
            #pragma unroll
            for (int i = 0; i < NB; i++) {
                int f = i * 256 + tid, row = f >> 2, q = f & 3;
                pb[i] = *(const uint4*)(B + (size_t)row * ldb + koff + q * 8);
            }
        }
        const uint32_t* Ac = Ast[cur];
        const uint32_t* Bc = Bst[cur];
        #pragma unroll
        for (int kk = 0; kk < 2; kk++) {
            int g8 = kk * 8;
            int co = 2 * (lane & 3);
            uint32_t afr[MI][4], bfr[NI][2];
            #pragma unroll
            for (int mi = 0; mi < MI; mi++) {
                int r = wy * WMT + mi * 16 + (lane >> 2);
                uint2 lo = *(const uint2*)&Ac[r * LDSROW + g8 + co];
                uint2 hi = *(const uint2*)&Ac[(r + 8) * LDSROW + g8 + co];
                afr[mi][0] = lo.x; afr[mi][1] = hi.x;
                afr[mi][2] = lo.y; afr[mi][3] = hi.y;
            }
            #pragma unroll
            for (int ni = 0; ni < NI; ni++) {
                int rn = wx * WNT + ni * 8 + (lane >> 2);
                uint2 bb = *(const uint2*)&Bc[rn * LDSROW + g8 + co];
                bfr[ni][0] = bb.x; bfr[ni][1] = bb.y;
            }
            #pragma unroll
            for (int mi = 0; mi < MI; mi++)
                #pragma unroll
                for (int ni = 0; ni < NI; ni++)
                    mma_f16(acc[mi][ni], afr[mi], bfr[ni]);
        }
        if (kb + 1 < nkb) {
            int nxt = cur ^ 1;
            __syncthreads();
            #pragma unroll
            for (int i = 0; i < NA; i++) {
                int f = i * 256 + tid, row = f >> 2, q = f & 3;
                sts_q(Ast[nxt], row, q, pa[i]);
            }
            #pragma unroll
            for (int i = 0; i < NB; i++) {
                int f = i * 256 + tid, row = f >> 2, q = f & 3;
                sts_q(Bst[nxt], row, q, pb[i]);
            }
            __syncthreads();
        }
    }

    // epilogue
    #pragma unroll
    for (int mi = 0; mi < MI; mi++) {
        #pragma unroll
        for (int ni = 0; ni < NI; ni++) {
            int col = n0 + wx * WNT + ni * 8 + 2 * (lane & 3);
            #pragma unroll
            for (int half = 0; half < 2; half++) {
                int row = m0 + wy * WMT + mi * 16 + (lane >> 2) + half * 8;
                float c0 = acc[mi][ni][2 * half]     * scale;
                float c1 = acc[mi][ni][2 * half + 1] * scale;
                if (bias) { c0 += bias[col]; c1 += bias[col + 1]; }
                if (act == 1) { c0 = gelu_tanh(c0); c1 = gelu_tanh(c1); }
                if (res) {
                    float2 rv = *(const float2*)(res + (size_t)row * ldc + col);
                    c0 += rv.x; c1 += rv.y;
                }
                store2(C + (size_t)row * ldc + col, c0, c1);
            }
        }
    }
}

#define SMEMB(TN) ((2 * 128 * LDSROW + 2 * (TN) * LDSROW) * 4)

// ---------------- host launch ----------------
extern "C" void kernel_launch(void* const* d_in, const int* in_sizes, int n_in,
                              void* d_out, int out_size) {
    const float* x     = (const float*)d_in[0];
    const float* zin   = (const float*)d_in[1];
    const float* g1    = (const float*)d_in[2];
    const float* b1    = (const float*)d_in[3];
    const float* w_qkv = (const float*)d_in[4];
    const float* b_qkv = (const float*)d_in[5];
    const float* w_o   = (const float*)d_in[6];
    const float* b_o   = (const float*)d_in[7];
    const float* w_kv  = (const float*)d_in[8];
    const float* b_kv  = (const float*)d_in[9];
    const float* g2    = (const float*)d_in[10];
    const float* b2    = (const float*)d_in[11];
    const float* w_m1  = (const float*)d_in[12];
    const float* b_m1  = (const float*)d_in[13];
    const float* w_m2  = (const float*)d_in[14];
    const float* b_m2  = (const float*)d_in[15];
    float* out = (float*)d_out;

    __half *ln, *qkv, *kv, *attn, *q, *mlp, *scores, *p, *z16;
    __half *wtqkv, *wto, *wtkv, *wtm1, *wtm2, *vts, *vtc;
    float *cross, *xs;
    cudaGetSymbolAddress((void**)&ln,     h_ln);
    cudaGetSymbolAddress((void**)&qkv,    h_qkv);
    cudaGetSymbolAddress((void**)&kv,     h_kv);
    cudaGetSymbolAddress((void**)&attn,   h_attn);
    cudaGetSymbolAddress((void**)&q,      h_q);
    cudaGetSymbolAddress((void**)&cross,  g_cross);
    cudaGetSymbolAddress((void**)&mlp,    h_mlp);
    cudaGetSymbolAddress((void**)&scores, h_scores);
    cudaGetSymbolAddress((void**)&xs,     g_xs);
    cudaGetSymbolAddress((void**)&p,      h_p);
    cudaGetSymbolAddress((void**)&z16,    h_z);
    cudaGetSymbolAddress((void**)&wtqkv,  h_wt_qkv);
    cudaGetSymbolAddress((void**)&wto,    h_wt_o);
    cudaGetSymbolAddress((void**)&wtkv,   h_wt_kv);
    cudaGetSymbolAddress((void**)&wtm1,   h_wt_m1);
    cudaGetSymbolAddress((void**)&wtm2,   h_wt_m2);
    cudaGetSymbolAddress((void**)&vts,    h_vt_self);
    cudaGetSymbolAddress((void**)&vtc,    h_vt_cross);

    cudaFuncSetAttribute(mm_h<128, __half>, cudaFuncAttributeMaxDynamicSharedMemorySize, SMEMB(128));
    cudaFuncSetAttribute(mm_h<128, float>,  cudaFuncAttributeMaxDynamicSharedMemorySize, SMEMB(128));
    cudaFuncSetAttribute(mm_h<64, __half>,  cudaFuncAttributeMaxDynamicSharedMemorySize, SMEMB(64));

    dim3 tb(32, 8);

    // weight transposes + fp16 convert ([K][N] -> [N][K])
    transpose_h<float><<<dim3(3 * D_MODEL / 32, D_MODEL / 32, 1), tb>>>(w_qkv, wtqkv, 3 * D_MODEL, D_MODEL, 0, 0, 0, 0, 1);
    transpose_h<float><<<dim3(D_MODEL / 32, D_MODEL / 32, 1), tb>>>(w_o, wto, D_MODEL, D_MODEL, 0, 0, 0, 0, 1);
    transpose_h<float><<<dim3(2 * D_MODEL / 32, D_MODEL / 32, 1), tb>>>(w_kv, wtkv, 2 * D_MODEL, D_MODEL, 0, 0, 0, 0, 1);
    transpose_h<float><<<dim3(HMLP / 32, D_MODEL / 32, 1), tb>>>(w_m1, wtm1, HMLP, D_MODEL, 0, 0, 0, 0, 1);
    transpose_h<float><<<dim3(D_MODEL / 32, HMLP / 32, 1), tb>>>(w_m2, wtm2, D_MODEL, HMLP, 0, 0, 0, 0, 1);

    // z -> fp16
    cvt_f2h<<<ROWS * D_MODEL / 8 / 256, 256>>>(zin, z16, ROWS * D_MODEL / 8);

    // 1) ln1(x) -> fp16
    ln_kernel<<<ROWS, 256>>>(x, g1, b1, ln);

    // 2) qkv = ln1 @ w_qkv + b_qkv  (fp16 out)
    mm_h<128, __half><<<dim3(24, 32, 1), 256, SMEMB(128)>>>(
        ln, wtqkv, b_qkv, nullptr, qkv, D_MODEL, D_MODEL, D_MODEL, 3 * D_MODEL,
        0, 0, 0, 0, 0, 0, 1, 1.0f, 0);

    // transpose self V: per (b,h): [S,64] -> [64,S]
    transpose_h<__half><<<dim3(2, 32, BATCH * NHEADS), tb>>>(
        qkv + 2 * D_MODEL, vts, 3 * D_MODEL, SEQ,
        (long)SEQ * 3 * D_MODEL, HDIM, (long)NHEADS * HDIM * SEQ, (long)HDIM * SEQ, NHEADS);

    // 3) self scores = Q @ K^T / 8  (fp16 out)
    mm_h<128, __half><<<dim3(8, 8, BATCH * NHEADS), 256, SMEMB(128)>>>(
        qkv, qkv + D_MODEL, nullptr, nullptr, scores, HDIM, 3 * D_MODEL, 3 * D_MODEL, SEQ,
        (long)SEQ * 3 * D_MODEL, HDIM, (long)SEQ * 3 * D_MODEL, HDIM,
        (long)NHEADS * SEQ * SEQ, (long)SEQ * SEQ, NHEADS, 0.125f, 0);

    // 4) softmax (fp16)
    softmax_h<<<BATCH * NHEADS * SEQ, 256>>>(scores);

    // 5) self P @ V -> attn (fp16)
    mm_h<64, __half><<<dim3(1, 8, BATCH * NHEADS), 256, SMEMB(64)>>>(
        scores, vts, nullptr, nullptr, attn, SEQ, SEQ, SEQ, D_MODEL,
        (long)NHEADS * SEQ * SEQ, (long)SEQ * SEQ,
        (long)NHEADS * HDIM * SEQ, (long)HDIM * SEQ,
        (long)SEQ * D_MODEL, (long)HDIM, NHEADS, 1.0f, 0);

    // 6) q = x + attn @ w_o + b_o  (fp16 out)
    mm_h<128, __half><<<dim3(8, 32, 1), 256, SMEMB(128)>>>(
        attn, wto, b_o, x, q, D_MODEL, D_MODEL, D_MODEL, D_MODEL,
        0, 0, 0, 0, 0, 0, 1, 1.0f, 0);

    // 7) kv = z @ w_kv + b_kv  (fp16 out)
    mm_h<128, __half><<<dim3(16, 32, 1), 256, SMEMB(128)>>>(
        z16, wtkv, b_kv, nullptr, kv, D_MODEL, D_MODEL, D_MODEL, 2 * D_MODEL,
        0, 0, 0, 0, 0, 0, 1, 1.0f, 0);

    // transpose cross V: per b: [S,D] -> [D,S]
    transpose_h<__half><<<dim3(32, 32, BATCH), tb>>>(
        kv + D_MODEL, vtc, 2 * D_MODEL, SEQ,
        (long)SEQ * 2 * D_MODEL, 0, (long)D_MODEL * SEQ, 0, 1);

    // 8) cross scores = q @ k^T / 32  (fp32 out for precision)
    mm_h<128, float><<<dim3(8, 8, BATCH), 256, SMEMB(128)>>>(
        q, kv, nullptr, nullptr, xs, D_MODEL, D_MODEL, 2 * D_MODEL, SEQ,
        (long)SEQ * D_MODEL, 0, (long)SEQ * 2 * D_MODEL, 0,
        (long)SEQ * SEQ, 0, 1, 0.03125f, 0);

    // 9) softmax fp32 -> fp16 P
    softmax_f2h<<<BATCH * SEQ, 256>>>(xs, p);

    // 10) cross P @ V -> cross (fp32)
    mm_h<128, float><<<dim3(8, 8, BATCH), 256, SMEMB(128)>>>(
        p, vtc, nullptr, nullptr, cross, SEQ, SEQ, SEQ, D_MODEL,
        (long)SEQ * SEQ, 0, (long)D_MODEL * SEQ, 0, (long)SEQ * D_MODEL, 0,
        1, 1.0f, 0);

    // 11) ln2(cross) -> fp16
    ln_kernel<<<ROWS, 256>>>(cross, g2, b2, ln);

    // 12) mlp hidden = gelu(ln2 @ w_m1 + b_m1)  (fp16 out)
    mm_h<128, __half><<<dim3(32, 32, 1), 256, SMEMB(128)>>>(
        ln, wtm1, b_m1, nullptr, mlp, D_MODEL, D_MODEL, D_MODEL, HMLP,
        0, 0, 0, 0, 0, 0, 1, 1.0f, 1);

    // 13) out = cross + mlp @ w_m2 + b_m2  (fp32 out)
    mm_h<128, float><<<dim3(8, 32, 1), 256, SMEMB(128)>>>(
        mlp, wtm2, b_m2, cross, out, HMLP, HMLP, HMLP, D_MODEL,
        0, 0, 0, 0, 0, 0, 1, 1.0f, 0);
}

// round 7
// speedup vs baseline: 3.9431x; 1.1508x over previous
#include <cuda_runtime.h>
#include <cuda_fp16.h>
#include <math.h>
#include <stdint.h>

#define D_MODEL 1024
#define BATCH   4
#define SEQ     1024
#define NHEADS  16
#define HDIM    64
#define HMLP    4096
#define ROWS    (BATCH*SEQ)     // 4096

// ---------------- scratch (device globals; no allocs allowed) ----------------
__device__ __half h_ln   [ROWS * D_MODEL];
__device__ __half h_qkv  [ROWS * 3 * D_MODEL];
__device__ __half h_kv   [ROWS * 2 * D_MODEL];
__device__ __half h_attn [ROWS * D_MODEL];
__device__ __half h_q    [ROWS * D_MODEL];
__device__ float  g_cross[ROWS * D_MODEL];
__device__ __half h_mlp  [ROWS * HMLP];
__device__ float  g_xs   [(size_t)BATCH * SEQ * SEQ];            // cross logits fp32
__device__ __half h_p    [(size_t)BATCH * SEQ * SEQ];            // cross P fp16
__device__ __half h_z    [ROWS * D_MODEL];
__device__ __half h_wt_qkv[3 * D_MODEL * D_MODEL];
__device__ __half h_wt_o  [D_MODEL * D_MODEL];
__device__ __half h_wt_kv [2 * D_MODEL * D_MODEL];
__device__ __half h_wt_m1 [HMLP * D_MODEL];
__device__ __half h_wt_m2 [D_MODEL * HMLP];
__device__ __half h_vt_self [BATCH * NHEADS * HDIM * SEQ];
__device__ __half h_vt_cross[(size_t)BATCH * D_MODEL * SEQ];

__device__ __forceinline__ float gelu_tanh(float c) {
    float t = 0.7978845608028654f * (c + 0.044715f * c * c * c);
    return 0.5f * c * (1.0f + tanhf(t));
}
__device__ __forceinline__ void mma_f16(float* d, const uint32_t* a, const uint32_t* b) {
    asm volatile("mma.sync.aligned.m16n8k16.row.col.f32.f16.f16.f32 "
        "{%0,%1,%2,%3}, {%4,%5,%6,%7}, {%8,%9}, {%0,%1,%2,%3};"
        : "+f"(d[0]), "+f"(d[1]), "+f"(d[2]), "+f"(d[3])
        : "r"(a[0]), "r"(a[1]), "r"(a[2]), "r"(a[3]), "r"(b[0]), "r"(b[1]));
}
__device__ __forceinline__ void store2(__half* p, float a, float b) {
    *(__half2*)p = __floats2half2_rn(a, b);
}
__device__ __forceinline__ void store2(float* p, float a, float b) {
    float2 v; v.x = a; v.y = b; *(float2*)p = v;
}
__device__ __forceinline__ uint32_t packh2(float a, float b) {
    __half2 h = __floats2half2_rn(a, b);
    return *(uint32_t*)&h;
}

// ---------------- layernorm (fp32 in -> fp16 out) ----------------
__global__ void ln_kernel(const float* __restrict__ x, const float* __restrict__ g,
                          const float* __restrict__ b, __half* __restrict__ out) {
    int row = blockIdx.x;
    const float* xr = x + (size_t)row * D_MODEL;
    __half* orow = out + (size_t)row * D_MODEL;
    int tid = threadIdx.x;
    float s = 0.f, s2 = 0.f;
    for (int i = tid; i < D_MODEL; i += 256) {
        float v = xr[i]; s += v; s2 += v * v;
    }
    __shared__ float red[256], red2[256];
    red[tid] = s; red2[tid] = s2; __syncthreads();
    for (int o = 128; o > 0; o >>= 1) {
        if (tid < o) { red[tid] += red[tid + o]; red2[tid] += red2[tid + o]; }
        __syncthreads();
    }
    float mu  = red[0]  * (1.0f / D_MODEL);
    float var = red2[0] * (1.0f / D_MODEL) - mu * mu;
    float inv = rsqrtf(var + 1e-5f);
    for (int i = tid; i < D_MODEL; i += 512) {
        float v0 = (xr[i] - mu) * inv * g[i] + b[i];
        float v1 = (xr[i + 256] - mu) * inv * g[i + 256] + b[i + 256];
        orow[i] = __float2half(v0);
        orow[i + 256] = __float2half(v1);
    }
}

// ---------------- softmax fp32 in -> fp16 out (cross) ----------------
__global__ void softmax_f2h(const float* __restrict__ S, __half* __restrict__ P) {
    const float* row = S + (size_t)blockIdx.x * 1024;
    __half* prow = P + (size_t)blockIdx.x * 1024;
    int tid = threadIdx.x;
    float4 v = *(const float4*)(row + tid * 4);
    float mx = fmaxf(fmaxf(v.x, v.y), fmaxf(v.z, v.w));
    __shared__ float red[32];
    for (int o = 16; o > 0; o >>= 1) mx = fmaxf(mx, __shfl_xor_sync(0xffffffff, mx, o));
    if ((tid & 31) == 0) red[tid >> 5] = mx;
    __syncthreads();
    if (tid < 32) {
        float m = (tid < 8) ? red[tid] : -1e30f;
        for (int o = 4; o > 0; o >>= 1) m = fmaxf(m, __shfl_xor_sync(0xffffffff, m, o));
        red[0] = m;
    }
    __syncthreads();
    mx = red[0];
    v.x = expf(v.x - mx); v.y = expf(v.y - mx); v.z = expf(v.z - mx); v.w = expf(v.w - mx);
    float s = v.x + v.y + v.z + v.w;
    for (int o = 16; o > 0; o >>= 1) s += __shfl_xor_sync(0xffffffff, s, o);
    __syncthreads();
    if ((tid & 31) == 0) red[tid >> 5] = s;
    __syncthreads();
    if (tid < 32) {
        float t = (tid < 8) ? red[tid] : 0.f;
        for (int o = 4; o > 0; o >>= 1) t += __shfl_xor_sync(0xffffffff, t, o);
        red[0] = t;
    }
    __syncthreads();
    float inv = 1.0f / red[0];
    __half2 h2[2];
    h2[0] = __floats2half2_rn(v.x * inv, v.y * inv);
    h2[1] = __floats2half2_rn(v.z * inv, v.w * inv);
    *(uint2*)(prow + tid * 4) = *(uint2*)h2;
}

// ---------------- batched transpose (TS in -> half out) ----------------
template <typename TS>
__global__ void transpose_h(const TS* __restrict__ srcb, __half* __restrict__ dstb,
                            int lds, int ldd, long sSb, long sSh, long sDb, long sDh, int nh) {
    int z = blockIdx.z, b = z / nh, h = z - b * nh;
    const TS* src = srcb + (size_t)b * sSb + (size_t)h * sSh;
    __half* dst = dstb + (size_t)b * sDb + (size_t)h * sDh;
    __shared__ __half tile[32][34];
    int x = blockIdx.x * 32, y = blockIdx.y * 32;
    int tx = threadIdx.x, ty = threadIdx.y;
    #pragma unroll
    for (int i = ty; i < 32; i += 8)
        tile[i][tx] = __float2half((float)src[(size_t)(y + i) * lds + x + tx]);
    __syncthreads();
    #pragma unroll
    for (int i = ty; i < 32; i += 8)
        dst[(size_t)(x + i) * ldd + y + tx] = tile[tx][i];
}

// ---------------- fp32 -> fp16 elementwise ----------------
__global__ void cvt_f2h(const float* __restrict__ src, __half* __restrict__ dst, int n8) {
    int i = blockIdx.x * 256 + threadIdx.x;
    if (i < n8) {
        float4 a = *(const float4*)(src + (size_t)i * 8);
        float4 b = *(const float4*)(src + (size_t)i * 8 + 4);
        __half2 h[4];
        h[0] = __floats2half2_rn(a.x, a.y); h[1] = __floats2half2_rn(a.z, a.w);
        h[2] = __floats2half2_rn(b.x, b.y); h[3] = __floats2half2_rn(b.z, b.w);
        *(uint4*)(dst + (size_t)i * 8) = *(uint4*)h;
    }
}

// ================= flash self-attention =================
// grid (8 qblocks, 64 bh), 256 threads (8 warps x 16 q-rows).
// K tile + V^T tile staged in permuted SMEM (row = 32 words + pad -> stride 40).
#define FROW 40

__device__ __forceinline__ void sts_q40(uint32_t* stg, int row, int q, uint4 v) {
    // words 4q..4q+3 (q=0..7) of a 32-word row; permute within 8-word groups
    int g = q >> 1, hh = q & 1;
    uint32_t* p = stg + row * FROW + g * 8 + hh;
    p[0] = v.x; p[2] = v.y; p[4] = v.z; p[6] = v.w;
}

__global__ void __launch_bounds__(256)
flash_self(const __half* __restrict__ qkvg, const __half* __restrict__ vtsg,
           __half* __restrict__ attng) {
    __shared__ uint32_t Qs[128 * FROW];
    __shared__ uint32_t Ks[64 * FROW];
    __shared__ uint32_t Vs[64 * FROW];

    int tid = threadIdx.x, lane = tid & 31, warp = tid >> 5;
    int bh = blockIdx.y, b = bh >> 4, h = bh & 15;
    const __half* Qg = qkvg + (size_t)b * SEQ * 3 * D_MODEL
                     + (size_t)blockIdx.x * 128 * 3 * D_MODEL + h * HDIM;
    const __half* Kg = qkvg + (size_t)b * SEQ * 3 * D_MODEL + D_MODEL + h * HDIM;
    const __half* Vt = vtsg + (size_t)bh * HDIM * SEQ;   // [64][SEQ]
    __half* Og = attng + (size_t)b * SEQ * D_MODEL
               + (size_t)blockIdx.x * 128 * D_MODEL + h * HDIM;

    // stage Q tile (128 rows x 64 halves)
    #pragma unroll
    for (int i = 0; i < 4; i++) {
        int f = i * 256 + tid, row = f >> 3, q = f & 7;
        sts_q40(Qs, row, q, *(const uint4*)(Qg + (size_t)row * 3 * D_MODEL + q * 8));
    }
    __syncthreads();

    // Q fragments in registers: 4 k-steps x 4 regs
    uint32_t qa[4][4];
    {
        int r = warp * 16 + (lane >> 2);
        int co = 2 * (lane & 3);
        #pragma unroll
        for (int kk = 0; kk < 4; kk++) {
            uint2 lo = *(const uint2*)&Qs[r * FROW + kk * 8 + co];
            uint2 hi = *(const uint2*)&Qs[(r + 8) * FROW + kk * 8 + co];
            qa[kk][0] = lo.x; qa[kk][1] = hi.x; qa[kk][2] = lo.y; qa[kk][3] = hi.y;
        }
    }

    float oacc[8][4];
    #pragma unroll
    for (int ni = 0; ni < 8; ni++)
        #pragma unroll
        for (int c = 0; c < 4; c++) oacc[ni][c] = 0.f;
    float m0 = -1e30f, m1 = -1e30f, l0 = 0.f, l1 = 0.f;

    for (int kb = 0; kb < 16; kb++) {
        __syncthreads();
        #pragma unroll
        for (int i = 0; i < 2; i++) {
            int f = i * 256 + tid, row = f >> 3, q = f & 7;
            sts_q40(Ks, row, q, *(const uint4*)(Kg + (size_t)(kb * 64 + row) * 3 * D_MODEL + q * 8));
            sts_q40(Vs, row, q, *(const uint4*)(Vt + (size_t)row * SEQ + kb * 64 + q * 8));
        }
        __syncthreads();

        // S = Q @ K^T  (16 x 64 per warp)
        float sacc[8][4];
        #pragma unroll
        for (int ni = 0; ni < 8; ni++)
            #pragma unroll
            for (int c = 0; c < 4; c++) sacc[ni][c] = 0.f;
        int co = 2 * (lane & 3);
        #pragma unroll
        for (int kk = 0; kk < 4; kk++) {
            #pragma unroll
            for (int ni = 0; ni < 8; ni++) {
                int rn = ni * 8 + (lane >> 2);
                uint2 bb = *(const uint2*)&Ks[rn * FROW + kk * 8 + co];
                uint32_t bfr[2] = { bb.x, bb.y };
                mma_f16(sacc[ni], qa[kk], bfr);
            }
        }

        // online softmax (scale 0.125 folded into exp domain)
        float mx0 = -1e30f, mx1 = -1e30f;
        #pragma unroll
        for (int ni = 0; ni < 8; ni++) {
            mx0 = fmaxf(mx0, fmaxf(sacc[ni][0], sacc[ni][1]));
            mx1 = fmaxf(mx1, fmaxf(sacc[ni][2], sacc[ni][3]));
        }
        mx0 = fmaxf(mx0, __shfl_xor_sync(0xffffffff, mx0, 1));
        mx0 = fmaxf(mx0, __shfl_xor_sync(0xffffffff, mx0, 2));
        mx1 = fmaxf(mx1, __shfl_xor_sync(0xffffffff, mx1, 1));
        mx1 = fmaxf(mx1, __shfl_xor_sync(0xffffffff, mx1, 2));
        float nm0 = fmaxf(m0, mx0 * 0.125f);
        float nm1 = fmaxf(m1, mx1 * 0.125f);
        float a0 = __expf(m0 - nm0);
        float a1 = __expf(m1 - nm1);
        m0 = nm0; m1 = nm1;

        uint32_t pw0[8], pw1[8];
        float s0 = 0.f, s1 = 0.f;
        #pragma unroll
        for (int ni = 0; ni < 8; ni++) {
            float p0 = __expf(sacc[ni][0] * 0.125f - nm0);
            float p1 = __expf(sacc[ni][1] * 0.125f - nm0);
            float p2 = __expf(sacc[ni][2] * 0.125f - nm1);
            float p3 = __expf(sacc[ni][3] * 0.125f - nm1);
            s0 += p0 + p1; s1 += p2 + p3;
            pw0[ni] = packh2(p0, p1);
            pw1[ni] = packh2(p2, p3);
        }
        s0 += __shfl_xor_sync(0xffffffff, s0, 1);
        s0 += __shfl_xor_sync(0xffffffff, s0, 2);
        s1 += __shfl_xor_sync(0xffffffff, s1, 1);
        s1 += __shfl_xor_sync(0xffffffff, s1, 2);
        l0 = l0 * a0 + s0;
        l1 = l1 * a1 + s1;
        #pragma unroll
        for (int ni = 0; ni < 8; ni++) {
            oacc[ni][0] *= a0; oacc[ni][1] *= a0;
            oacc[ni][2] *= a1; oacc[ni][3] *= a1;
        }

        // O += P @ V  (B = V^T tile)
        #pragma unroll
        for (int kp = 0; kp < 4; kp++) {
            uint32_t pa[4] = { pw0[2 * kp], pw1[2 * kp], pw0[2 * kp + 1], pw1[2 * kp + 1] };
            #pragma unroll
            for (int ni = 0; ni < 8; ni++) {
                int rn = ni * 8 + (lane >> 2);
                uint2 bb = *(const uint2*)&Vs[rn * FROW + kp * 8 + co];
                uint32_t bfr[2] = { bb.x, bb.y };
                mma_f16(oacc[ni], pa, bfr);
            }
        }
    }

    float i0 = 1.0f / l0, i1 = 1.0f / l1;
    int r = warp * 16 + (lane >> 2);
    #pragma unroll
    for (int ni = 0; ni < 8; ni++) {
        int col = ni * 8 + 2 * (lane & 3);
        store2(Og + (size_t)r * D_MODEL + col,       oacc[ni][0] * i0, oacc[ni][1] * i0);
        store2(Og + (size_t)(r + 8) * D_MODEL + col, oacc[ni][2] * i1, oacc[ni][3] * i1);
    }
}

// ============ fp16 mma.sync GEMM (unchanged from R6) ============
#define LDSROW 24

template <int TN, typename CT>
__global__ void __launch_bounds__(256)
mm_h(const __half* __restrict__ Abase, const __half* __restrict__ Bbase,
     const float* __restrict__ bias, const float* __restrict__ resbase,
     CT* __restrict__ Cbase, int K, int lda, int ldb, int ldc,
     long sAb, long sAh, long sBb, long sBh, long sCb, long sCh,
     int nh, float scale, int act) {
    constexpr int TM = 128;
    constexpr int WX = (TN == 128) ? 4 : 2;
    constexpr int WY = 8 / WX;
    constexpr int WNT = TN / WX;
    constexpr int WMT = TM / WY;
    constexpr int MI = WMT / 16;
    constexpr int NI = WNT / 8;
    constexpr int NA = TM * 4 / 256;
    constexpr int NB = TN * 4 / 256;

    extern __shared__ uint32_t sm[];
    uint32_t* Ast[2] = { sm, sm + TM * LDSROW };
    uint32_t* Bst[2] = { sm + 2 * TM * LDSROW, sm + 2 * TM * LDSROW + TN * LDSROW };

    int tid = threadIdx.x, lane = tid & 31, warp = tid >> 5;
    int wy = warp % WY, wx = warp / WY;
    int z = blockIdx.z, b = z / nh, h = z - b * nh;
    const __half* A = Abase + (size_t)b * sAb + (size_t)h * sAh + (size_t)blockIdx.y * TM * lda;
    const __half* B = Bbase + (size_t)b * sBb + (size_t)h * sBh + (size_t)blockIdx.x * TN * ldb;
    CT* C = Cbase + (size_t)b * sCb + (size_t)h * sCh;
    const float* res = resbase ? resbase + (size_t)b * sCb + (size_t)h * sCh : nullptr;
    int m0 = blockIdx.y * TM, n0 = blockIdx.x * TN;

    float acc[MI][NI][4];
    #pragma unroll
    for (int mi = 0; mi < MI; mi++)
        #pragma unroll
        for (int ni = 0; ni < NI; ni++)
            #pragma unroll
            for (int c = 0; c < 4; c++) acc[mi][ni][c] = 0.f;

    auto sts_q = [&](uint32_t* stg, int row, int q, uint4 v) {
        int g = q >> 1, hh = q & 1;
        uint32_t* p = stg + row * LDSROW + g * 8 + hh;
        p[0] = v.x; p[2] = v.y; p[4] = v.z; p[6] = v.w;
    };

    int nkb = K >> 5;
    {
        #pragma unroll
        for (int i = 0; i < NA; i++) {
            int f = i * 256 + tid, row = f >> 2, q = f & 3;
            sts_q(Ast[0], row, q, *(const uint4*)(A + (size_t)row * lda + q * 8));
        }
        #pragma unroll
        for (int i = 0; i < NB; i++) {
            int f = i * 256 + tid, row = f >> 2, q = f & 3;
            sts_q(Bst[0], row, q, *(const uint4*)(B + (size_t)row * ldb + q * 8));
        }
    }
    __syncthreads();

    for (int kb = 0; kb < nkb; kb++) {
        int cur = kb & 1;
        uint4 pa[NA], pb[NB];
        if (kb + 1 < nkb) {
            int koff = (kb + 1) * 32;
            #pragma unroll
            for (int i = 0; i < NA; i++) {
                int f = i * 256 + tid, row = f >> 2, q = f & 3;
                pa[i] = *(const uint4*)(A + (size_t)row * lda + koff + q * 8);
            }
            #pragma unroll
            for (int i = 0; i < NB; i++) {
                int f = i * 256 + tid, row = f >> 2, q = f & 3;
                pb[i] = *(const uint4*)(B + (size_t)row * ldb + koff + q * 8);
            }
        }
        const uint32_t* Ac = Ast[cur];
        const uint32_t* Bc = Bst[cur];
        #pragma unroll
        for (int kk = 0; kk < 2; kk++) {
            int g8 = kk * 8;
            int co = 2 * (lane & 3);
            uint32_t afr[MI][4], bfr[NI][2];
            #pragma unroll
            for (int mi = 0; mi < MI; mi++) {
                int r = wy * WMT + mi * 16 + (lane >> 2);
                uint2 lo = *(const uint2*)&Ac[r * LDSROW + g8 + co];
                uint2 hi = *(const uint2*)&Ac[(r + 8) * LDSROW + g8 + co];
                afr[mi][0] = lo.x; afr[mi][1] = hi.x;
                afr[mi][2] = lo.y; afr[mi][3] = hi.y;
            }
            #pragma unroll
            for (int ni = 0; ni < NI; ni++) {
                int rn = wx * WNT + ni * 8 + (lane >> 2);
                uint2 bb = *(const uint2*)&Bc[rn * LDSROW + g8 + co];
                bfr[ni][0] = bb.x; bfr[ni][1] = bb.y;
            }
            #pragma unroll
            for (int mi = 0; mi < MI; mi++)
                #pragma unroll
                for (int ni = 0; ni < NI; ni++)
                    mma_f16(acc[mi][ni], afr[mi], bfr[ni]);
        }
        if (kb + 1 < nkb) {
            int nxt = cur ^ 1;
            __syncthreads();
            #pragma unroll
            for (int i = 0; i < NA; i++) {
                int f = i * 256 + tid, row = f >> 2, q = f & 3;
                sts_q(Ast[nxt], row, q, pa[i]);
            }
            #pragma unroll
            for (int i = 0; i < NB; i++) {
                int f = i * 256 + tid, row = f >> 2, q = f & 3;
                sts_q(Bst[nxt], row, q, pb[i]);
            }
            __syncthreads();
        }
    }

    #pragma unroll
    for (int mi = 0; mi < MI; mi++) {
        #pragma unroll
        for (int ni = 0; ni < NI; ni++) {
            int col = n0 + wx * WNT + ni * 8 + 2 * (lane & 3);
            #pragma unroll
            for (int half = 0; half < 2; half++) {
                int row = m0 + wy * WMT + mi * 16 + (lane >> 2) + half * 8;
                float c0 = acc[mi][ni][2 * half]     * scale;
                float c1 = acc[mi][ni][2 * half + 1] * scale;
                if (bias) { c0 += bias[col]; c1 += bias[col + 1]; }
                if (act == 1) { c0 = gelu_tanh(c0); c1 = gelu_tanh(c1); }
                if (res) {
                    float2 rv = *(const float2*)(res + (size_t)row * ldc + col);
                    c0 += rv.x; c1 += rv.y;
                }
                store2(C + (size_t)row * ldc + col, c0, c1);
            }
        }
    }
}

#define SMEMB(TN) ((2 * 128 * LDSROW + 2 * (TN) * LDSROW) * 4)

// ---------------- host launch ----------------
extern "C" void kernel_launch(void* const* d_in, const int* in_sizes, int n_in,
                              void* d_out, int out_size) {
    const float* x     = (const float*)d_in[0];
    const float* zin   = (const float*)d_in[1];
    const float* g1    = (const float*)d_in[2];
    const float* b1    = (const float*)d_in[3];
    const float* w_qkv = (const float*)d_in[4];
    const float* b_qkv = (const float*)d_in[5];
    const float* w_o   = (const float*)d_in[6];
    const float* b_o   = (const float*)d_in[7];
    const float* w_kv  = (const float*)d_in[8];
    const float* b_kv  = (const float*)d_in[9];
    const float* g2    = (const float*)d_in[10];
    const float* b2    = (const float*)d_in[11];
    const float* w_m1  = (const float*)d_in[12];
    const float* b_m1  = (const float*)d_in[13];
    const float* w_m2  = (const float*)d_in[14];
    const float* b_m2  = (const float*)d_in[15];
    float* out = (float*)d_out;

    __half *ln, *qkv, *kv, *attn, *q, *mlp, *p, *z16;
    __half *wtqkv, *wto, *wtkv, *wtm1, *wtm2, *vts, *vtc;
    float *cross, *xs;
    cudaGetSymbolAddress((void**)&ln,     h_ln);
    cudaGetSymbolAddress((void**)&qkv,    h_qkv);
    cudaGetSymbolAddress((void**)&kv,     h_kv);
    cudaGetSymbolAddress((void**)&attn,   h_attn);
    cudaGetSymbolAddress((void**)&q,      h_q);
    cudaGetSymbolAddress((void**)&cross,  g_cross);
    cudaGetSymbolAddress((void**)&mlp,    h_mlp);
    cudaGetSymbolAddress((void**)&xs,     g_xs);
    cudaGetSymbolAddress((void**)&p,      h_p);
    cudaGetSymbolAddress((void**)&z16,    h_z);
    cudaGetSymbolAddress((void**)&wtqkv,  h_wt_qkv);
    cudaGetSymbolAddress((void**)&wto,    h_wt_o);
    cudaGetSymbolAddress((void**)&wtkv,   h_wt_kv);
    cudaGetSymbolAddress((void**)&wtm1,   h_wt_m1);
    cudaGetSymbolAddress((void**)&wtm2,   h_wt_m2);
    cudaGetSymbolAddress((void**)&vts,    h_vt_self);
    cudaGetSymbolAddress((void**)&vtc,    h_vt_cross);

    cudaFuncSetAttribute(mm_h<128, __half>, cudaFuncAttributeMaxDynamicSharedMemorySize, SMEMB(128));
    cudaFuncSetAttribute(mm_h<128, float>,  cudaFuncAttributeMaxDynamicSharedMemorySize, SMEMB(128));

    dim3 tb(32, 8);

    // weight transposes + fp16 convert ([K][N] -> [N][K])
    transpose_h<float><<<dim3(3 * D_MODEL / 32, D_MODEL / 32, 1), tb>>>(w_qkv, wtqkv, 3 * D_MODEL, D_MODEL, 0, 0, 0, 0, 1);
    transpose_h<float><<<dim3(D_MODEL / 32, D_MODEL / 32, 1), tb>>>(w_o, wto, D_MODEL, D_MODEL, 0, 0, 0, 0, 1);
    transpose_h<float><<<dim3(2 * D_MODEL / 32, D_MODEL / 32, 1), tb>>>(w_kv, wtkv, 2 * D_MODEL, D_MODEL, 0, 0, 0, 0, 1);
    transpose_h<float><<<dim3(HMLP / 32, D_MODEL / 32, 1), tb>>>(w_m1, wtm1, HMLP, D_MODEL, 0, 0, 0, 0, 1);
    transpose_h<float><<<dim3(D_MODEL / 32, HMLP / 32, 1), tb>>>(w_m2, wtm2, D_MODEL, HMLP, 0, 0, 0, 0, 1);

    // z -> fp16
    cvt_f2h<<<ROWS * D_MODEL / 8 / 256, 256>>>(zin, z16, ROWS * D_MODEL / 8);

    // 1) ln1(x) -> fp16
    ln_kernel<<<ROWS, 256>>>(x, g1, b1, ln);

    // 2) qkv = ln1 @ w_qkv + b_qkv  (fp16 out)
    mm_h<128, __half><<<dim3(24, 32, 1), 256, SMEMB(128)>>>(
        ln, wtqkv, b_qkv, nullptr, qkv, D_MODEL, D_MODEL, D_MODEL, 3 * D_MODEL,
        0, 0, 0, 0, 0, 0, 1, 1.0f, 0);

    // transpose self V: per (b,h): [S,64] -> [64,S]
    transpose_h<__half><<<dim3(2, 32, BATCH * NHEADS), tb>>>(
        qkv + 2 * D_MODEL, vts, 3 * D_MODEL, SEQ,
        (long)SEQ * 3 * D_MODEL, HDIM, (long)NHEADS * HDIM * SEQ, (long)HDIM * SEQ, NHEADS);

    // 3-5) fused flash self-attention -> attn (fp16)
    flash_self<<<dim3(8, BATCH * NHEADS), 256>>>(qkv, vts, attn);

    // 6) q = x + attn @ w_o + b_o  (fp16 out)
    mm_h<128, __half><<<dim3(8, 32, 1), 256, SMEMB(128)>>>(
        attn, wto, b_o, x, q, D_MODEL, D_MODEL, D_MODEL, D_MODEL,
        0, 0, 0, 0, 0, 0, 1, 1.0f, 0);

    // 7) kv = z @ w_kv + b_kv  (fp16 out)
    mm_h<128, __half><<<dim3(16, 32, 1), 256, SMEMB(128)>>>(
        z16, wtkv, b_kv, nullptr, kv, D_MODEL, D_MODEL, D_MODEL, 2 * D_MODEL,
        0, 0, 0, 0, 0, 0, 1, 1.0f, 0);

    // transpose cross V: per b: [S,D] -> [D,S]
    transpose_h<__half><<<dim3(32, 32, BATCH), tb>>>(
        kv + D_MODEL, vtc, 2 * D_MODEL, SEQ,
        (long)SEQ * 2 * D_MODEL, 0, (long)D_MODEL * SEQ, 0, 1);

    // 8) cross scores = q @ k^T / 32  (fp32 out for precision)
    mm_h<128, float><<<dim3(8, 8, BATCH), 256, SMEMB(128)>>>(
        q, kv, nullptr, nullptr, xs, D_MODEL, D_MODEL, 2 * D_MODEL, SEQ,
        (long)SEQ * D_MODEL, 0, (long)SEQ * 2 * D_MODEL, 0,
        (long)SEQ * SEQ, 0, 1, 0.03125f, 0);

    // 9) softmax fp32 -> fp16 P
    softmax_f2h<<<BATCH * SEQ, 256>>>(xs, p);

    // 10) cross P @ V -> cross (fp32)
    mm_h<128, float><<<dim3(8, 8, BATCH), 256, SMEMB(128)>>>(
        p, vtc, nullptr, nullptr, cross, SEQ, SEQ, SEQ, D_MODEL,
        (long)SEQ * SEQ, 0, (long)D_MODEL * SEQ, 0, (long)SEQ * D_MODEL, 0,
        1, 1.0f, 0);

    // 11) ln2(cross) -> fp16
    ln_kernel<<<ROWS, 256>>>(cross, g2, b2, ln);

    // 12) mlp hidden = gelu(ln2 @ w_m1 + b_m1)  (fp16 out)
    mm_h<128, __half><<<dim3(32, 32, 1), 256, SMEMB(128)>>>(
        ln, wtm1, b_m1, nullptr, mlp, D_MODEL, D_MODEL, D_MODEL, HMLP,
        0, 0, 0, 0, 0, 0, 1, 1.0f, 1);

    // 13) out = cross + mlp @ w_m2 + b_m2  (fp32 out)
    mm_h<128, float><<<dim3(8, 32, 1), 256, SMEMB(128)>>>(
        mlp, wtm2, b_m2, cross, out, HMLP, HMLP, HMLP, D_MODEL,
        0, 0, 0, 0, 0, 0, 1, 1.0f, 0);
}

// round 8
// speedup vs baseline: 7.0816x; 1.7960x over previous
#include <cuda_runtime.h>
#include <cuda_fp16.h>
#include <math.h>
#include <stdint.h>

#define D_MODEL 1024
#define BATCH   4
#define SEQ     1024
#define NHEADS  16
#define HDIM    64
#define HMLP    4096
#define ROWS    (BATCH*SEQ)     // 4096

// ---------------- scratch (device globals; no allocs allowed) ----------------
__device__ __half h_ln   [ROWS * D_MODEL];
__device__ __half h_qkv  [ROWS * 3 * D_MODEL];
__device__ __half h_kv   [ROWS * 2 * D_MODEL];
__device__ __half h_attn [ROWS * D_MODEL];
__device__ __half h_q    [ROWS * D_MODEL];
__device__ float  g_cross[ROWS * D_MODEL];
__device__ __half h_mlp  [ROWS * HMLP];
__device__ float  g_xs   [(size_t)BATCH * SEQ * SEQ];
__device__ __half h_p    [(size_t)BATCH * SEQ * SEQ];
__device__ __half h_z    [ROWS * D_MODEL];
__device__ __half h_wt_qkv[3 * D_MODEL * D_MODEL];
__device__ __half h_wt_o  [D_MODEL * D_MODEL];
__device__ __half h_wt_kv [2 * D_MODEL * D_MODEL];
__device__ __half h_wt_m1 [HMLP * D_MODEL];
__device__ __half h_wt_m2 [D_MODEL * HMLP];
__device__ __half h_vt_self [BATCH * NHEADS * HDIM * SEQ];
__device__ __half h_vt_cross[(size_t)BATCH * D_MODEL * SEQ];

__device__ __forceinline__ float gelu_tanh(float c) {
    float t = 0.7978845608028654f * (c + 0.044715f * c * c * c);
    return 0.5f * c * (1.0f + tanhf(t));
}
__device__ __forceinline__ void mma_f16(float* d, const uint32_t* a, const uint32_t* b) {
    asm volatile("mma.sync.aligned.m16n8k16.row.col.f32.f16.f16.f32 "
        "{%0,%1,%2,%3}, {%4,%5,%6,%7}, {%8,%9}, {%0,%1,%2,%3};"
        : "+f"(d[0]), "+f"(d[1]), "+f"(d[2]), "+f"(d[3])
        : "r"(a[0]), "r"(a[1]), "r"(a[2]), "r"(a[3]), "r"(b[0]), "r"(b[1]));
}
__device__ __forceinline__ void ldsm_x4(uint32_t& r0, uint32_t& r1, uint32_t& r2, uint32_t& r3,
                                        uint32_t addr) {
    asm volatile("ldmatrix.sync.aligned.m8n8.x4.shared.b16 {%0,%1,%2,%3}, [%4];"
        : "=r"(r0), "=r"(r1), "=r"(r2), "=r"(r3) : "r"(addr));
}
__device__ __forceinline__ void cp16(uint32_t smem, const void* g) {
    asm volatile("cp.async.cg.shared.global [%0], [%1], 16;" :: "r"(smem), "l"(g));
}
__device__ __forceinline__ uint32_t smem_u32(const void* p) {
    return (uint32_t)__cvta_generic_to_shared(p);
}
__device__ __forceinline__ void store2(__half* p, float a, float b) {
    *(__half2*)p = __floats2half2_rn(a, b);
}
__device__ __forceinline__ void store2(float* p, float a, float b) {
    float2 v; v.x = a; v.y = b; *(float2*)p = v;
}
__device__ __forceinline__ uint32_t packh2(float a, float b) {
    __half2 h = __floats2half2_rn(a, b);
    return *(uint32_t*)&h;
}

// ---------------- layernorm (fp32 in -> fp16 out) ----------------
__global__ void ln_kernel(const float* __restrict__ x, const float* __restrict__ g,
                          const float* __restrict__ b, __half* __restrict__ out) {
    int row = blockIdx.x;
    const float* xr = x + (size_t)row * D_MODEL;
    __half* orow = out + (size_t)row * D_MODEL;
    int tid = threadIdx.x;
    float s = 0.f, s2 = 0.f;
    for (int i = tid; i < D_MODEL; i += 256) {
        float v = xr[i]; s += v; s2 += v * v;
    }
    __shared__ float red[256], red2[256];
    red[tid] = s; red2[tid] = s2; __syncthreads();
    for (int o = 128; o > 0; o >>= 1) {
        if (tid < o) { red[tid] += red[tid + o]; red2[tid] += red2[tid + o]; }
        __syncthreads();
    }
    float mu  = red[0]  * (1.0f / D_MODEL);
    float var = red2[0] * (1.0f / D_MODEL) - mu * mu;
    float inv = rsqrtf(var + 1e-5f);
    for (int i = tid; i < D_MODEL; i += 512) {
        float v0 = (xr[i] - mu) * inv * g[i] + b[i];
        float v1 = (xr[i + 256] - mu) * inv * g[i + 256] + b[i + 256];
        orow[i] = __float2half(v0);
        orow[i + 256] = __float2half(v1);
    }
}

// ---------------- softmax fp32 in -> fp16 out (cross) ----------------
__global__ void softmax_f2h(const float* __restrict__ S, __half* __restrict__ P) {
    const float* row = S + (size_t)blockIdx.x * 1024;
    __half* prow = P + (size_t)blockIdx.x * 1024;
    int tid = threadIdx.x;
    float4 v = *(const float4*)(row + tid * 4);
    float mx = fmaxf(fmaxf(v.x, v.y), fmaxf(v.z, v.w));
    __shared__ float red[32];
    for (int o = 16; o > 0; o >>= 1) mx = fmaxf(mx, __shfl_xor_sync(0xffffffff, mx, o));
    if ((tid & 31) == 0) red[tid >> 5] = mx;
    __syncthreads();
    if (tid < 32) {
        float m = (tid < 8) ? red[tid] : -1e30f;
        for (int o = 4; o > 0; o >>= 1) m = fmaxf(m, __shfl_xor_sync(0xffffffff, m, o));
        red[0] = m;
    }
    __syncthreads();
    mx = red[0];
    v.x = expf(v.x - mx); v.y = expf(v.y - mx); v.z = expf(v.z - mx); v.w = expf(v.w - mx);
    float s = v.x + v.y + v.z + v.w;
    for (int o = 16; o > 0; o >>= 1) s += __shfl_xor_sync(0xffffffff, s, o);
    __syncthreads();
    if ((tid & 31) == 0) red[tid >> 5] = s;
    __syncthreads();
    if (tid < 32) {
        float t = (tid < 8) ? red[tid] : 0.f;
        for (int o = 4; o > 0; o >>= 1) t += __shfl_xor_sync(0xffffffff, t, o);
        red[0] = t;
    }
    __syncthreads();
    float inv = 1.0f / red[0];
    __half2 h2[2];
    h2[0] = __floats2half2_rn(v.x * inv, v.y * inv);
    h2[1] = __floats2half2_rn(v.z * inv, v.w * inv);
    *(uint2*)(prow + tid * 4) = *(uint2*)h2;
}

// ---------------- batched transpose (TS in -> half out) ----------------
template <typename TS>
__global__ void transpose_h(const TS* __restrict__ srcb, __half* __restrict__ dstb,
                            int lds, int ldd, long sSb, long sSh, long sDb, long sDh, int nh) {
    int z = blockIdx.z, b = z / nh, h = z - b * nh;
    const TS* src = srcb + (size_t)b * sSb + (size_t)h * sSh;
    __half* dst = dstb + (size_t)b * sDb + (size_t)h * sDh;
    __shared__ __half tile[32][34];
    int x = blockIdx.x * 32, y = blockIdx.y * 32;
    int tx = threadIdx.x, ty = threadIdx.y;
    #pragma unroll
    for (int i = ty; i < 32; i += 8)
        tile[i][tx] = __float2half((float)src[(size_t)(y + i) * lds + x + tx]);
    __syncthreads();
    #pragma unroll
    for (int i = ty; i < 32; i += 8)
        dst[(size_t)(x + i) * ldd + y + tx] = tile[tx][i];
}

// ---------------- fp32 -> fp16 elementwise ----------------
__global__ void cvt_f2h(const float* __restrict__ src, __half* __restrict__ dst, int n8) {
    int i = blockIdx.x * 256 + threadIdx.x;
    if (i < n8) {
        float4 a = *(const float4*)(src + (size_t)i * 8);
        float4 b = *(const float4*)(src + (size_t)i * 8 + 4);
        __half2 h[4];
        h[0] = __floats2half2_rn(a.x, a.y); h[1] = __floats2half2_rn(a.z, a.w);
        h[2] = __floats2half2_rn(b.x, b.y); h[3] = __floats2half2_rn(b.z, b.w);
        *(uint4*)(dst + (size_t)i * 8) = *(uint4*)h;
    }
}

// ================= flash self-attention (unchanged from R7) =================
#define FROW 40
__device__ __forceinline__ void sts_q40(uint32_t* stg, int row, int q, uint4 v) {
    int g = q >> 1, hh = q & 1;
    uint32_t* p = stg + row * FROW + g * 8 + hh;
    p[0] = v.x; p[2] = v.y; p[4] = v.z; p[6] = v.w;
}

__global__ void __launch_bounds__(256)
flash_self(const __half* __restrict__ qkvg, const __half* __restrict__ vtsg,
           __half* __restrict__ attng) {
    __shared__ uint32_t Qs[128 * FROW];
    __shared__ uint32_t Ks[64 * FROW];
    __shared__ uint32_t Vs[64 * FROW];

    int tid = threadIdx.x, lane = tid & 31, warp = tid >> 5;
    int bh = blockIdx.y, b = bh >> 4, h = bh & 15;
    const __half* Qg = qkvg + (size_t)b * SEQ * 3 * D_MODEL
                     + (size_t)blockIdx.x * 128 * 3 * D_MODEL + h * HDIM;
    const __half* Kg = qkvg + (size_t)b * SEQ * 3 * D_MODEL + D_MODEL + h * HDIM;
    const __half* Vt = vtsg + (size_t)bh * HDIM * SEQ;
    __half* Og = attng + (size_t)b * SEQ * D_MODEL
               + (size_t)blockIdx.x * 128 * D_MODEL + h * HDIM;

    #pragma unroll
    for (int i = 0; i < 4; i++) {
        int f = i * 256 + tid, row = f >> 3, q = f & 7;
        sts_q40(Qs, row, q, *(const uint4*)(Qg + (size_t)row * 3 * D_MODEL + q * 8));
    }
    __syncthreads();

    uint32_t qa[4][4];
    {
        int r = warp * 16 + (lane >> 2);
        int co = 2 * (lane & 3);
        #pragma unroll
        for (int kk = 0; kk < 4; kk++) {
            uint2 lo = *(const uint2*)&Qs[r * FROW + kk * 8 + co];
            uint2 hi = *(const uint2*)&Qs[(r + 8) * FROW + kk * 8 + co];
            qa[kk][0] = lo.x; qa[kk][1] = hi.x; qa[kk][2] = lo.y; qa[kk][3] = hi.y;
        }
    }

    float oacc[8][4];
    #pragma unroll
    for (int ni = 0; ni < 8; ni++)
        #pragma unroll
        for (int c = 0; c < 4; c++) oacc[ni][c] = 0.f;
    float m0 = -1e30f, m1 = -1e30f, l0 = 0.f, l1 = 0.f;

    for (int kb = 0; kb < 16; kb++) {
        __syncthreads();
        #pragma unroll
        for (int i = 0; i < 2; i++) {
            int f = i * 256 + tid, row = f >> 3, q = f & 7;
            sts_q40(Ks, row, q, *(const uint4*)(Kg + (size_t)(kb * 64 + row) * 3 * D_MODEL + q * 8));
            sts_q40(Vs, row, q, *(const uint4*)(Vt + (size_t)row * SEQ + kb * 64 + q * 8));
        }
        __syncthreads();

        float sacc[8][4];
        #pragma unroll
        for (int ni = 0; ni < 8; ni++)
            #pragma unroll
            for (int c = 0; c < 4; c++) sacc[ni][c] = 0.f;
        int co = 2 * (lane & 3);
        #pragma unroll
        for (int kk = 0; kk < 4; kk++) {
            #pragma unroll
            for (int ni = 0; ni < 8; ni++) {
                int rn = ni * 8 + (lane >> 2);
                uint2 bb = *(const uint2*)&Ks[rn * FROW + kk * 8 + co];
                uint32_t bfr[2] = { bb.x, bb.y };
                mma_f16(sacc[ni], qa[kk], bfr);
            }
        }

        float mx0 = -1e30f, mx1 = -1e30f;
        #pragma unroll
        for (int ni = 0; ni < 8; ni++) {
            mx0 = fmaxf(mx0, fmaxf(sacc[ni][0], sacc[ni][1]));
            mx1 = fmaxf(mx1, fmaxf(sacc[ni][2], sacc[ni][3]));
        }
        mx0 = fmaxf(mx0, __shfl_xor_sync(0xffffffff, mx0, 1));
        mx0 = fmaxf(mx0, __shfl_xor_sync(0xffffffff, mx0, 2));
        mx1 = fmaxf(mx1, __shfl_xor_sync(0xffffffff, mx1, 1));
        mx1 = fmaxf(mx1, __shfl_xor_sync(0xffffffff, mx1, 2));
        float nm0 = fmaxf(m0, mx0 * 0.125f);
        float nm1 = fmaxf(m1, mx1 * 0.125f);
        float a0 = __expf(m0 - nm0);
        float a1 = __expf(m1 - nm1);
        m0 = nm0; m1 = nm1;

        uint32_t pw0[8], pw1[8];
        float s0 = 0.f, s1 = 0.f;
        #pragma unroll
        for (int ni = 0; ni < 8; ni++) {
            float p0 = __expf(sacc[ni][0] * 0.125f - nm0);
            float p1 = __expf(sacc[ni][1] * 0.125f - nm0);
            float p2 = __expf(sacc[ni][2] * 0.125f - nm1);
            float p3 = __expf(sacc[ni][3] * 0.125f - nm1);
            s0 += p0 + p1; s1 += p2 + p3;
            pw0[ni] = packh2(p0, p1);
            pw1[ni] = packh2(p2, p3);
        }
        s0 += __shfl_xor_sync(0xffffffff, s0, 1);
        s0 += __shfl_xor_sync(0xffffffff, s0, 2);
        s1 += __shfl_xor_sync(0xffffffff, s1, 1);
        s1 += __shfl_xor_sync(0xffffffff, s1, 2);
        l0 = l0 * a0 + s0;
        l1 = l1 * a1 + s1;
        #pragma unroll
        for (int ni = 0; ni < 8; ni++) {
            oacc[ni][0] *= a0; oacc[ni][1] *= a0;
            oacc[ni][2] *= a1; oacc[ni][3] *= a1;
        }

        #pragma unroll
        for (int kp = 0; kp < 4; kp++) {
            uint32_t pa[4] = { pw0[2 * kp], pw1[2 * kp], pw0[2 * kp + 1], pw1[2 * kp + 1] };
            #pragma unroll
            for (int ni = 0; ni < 8; ni++) {
                int rn = ni * 8 + (lane >> 2);
                uint2 bb = *(const uint2*)&Vs[rn * FROW + kp * 8 + co];
                uint32_t bfr[2] = { bb.x, bb.y };
                mma_f16(oacc[ni], pa, bfr);
            }
        }
    }

    float i0 = 1.0f / l0, i1 = 1.0f / l1;
    int r = warp * 16 + (lane >> 2);
    #pragma unroll
    for (int ni = 0; ni < 8; ni++) {
        int col = ni * 8 + 2 * (lane & 3);
        store2(Og + (size_t)r * D_MODEL + col,       oacc[ni][0] * i0, oacc[ni][1] * i0);
        store2(Og + (size_t)(r + 8) * D_MODEL + col, oacc[ni][2] * i1, oacc[ni][3] * i1);
    }
}

// ============ fp16 GEMM: cp.async + swizzled smem + ldmatrix ============
// C[M,N] = scale * A[M,K] @ B[N,K]^T (+bias)(+gelu)(+res). 128x128 tile, KB=64, 3 stages.
// Stage = A(128 rows x 128B) + B(128 x 128B), 16B chunk swizzle: c' = c ^ (row & 7).
#define NSTAGE 3
#define STAGEB 32768
#define SMEM2  (NSTAGE * STAGEB)

template <typename CT>
__global__ void __launch_bounds__(256)
mm2(const __half* __restrict__ Abase, const __half* __restrict__ Bbase,
    const float* __restrict__ bias, const float* __restrict__ resbase,
    CT* __restrict__ Cbase, int K, int lda, int ldb, int ldc,
    long sAb, long sAh, long sBb, long sBh, long sCb, long sCh,
    int nh, float scale, int act) {
    extern __shared__ __align__(16) char smc[];
    uint32_t sb = smem_u32(smc);

    int tid = threadIdx.x, lane = tid & 31, warp = tid >> 5;
    int wy = warp & 1, wx = warp >> 1;           // 2 x 4 warp grid; warp tile 64x32
    int z = blockIdx.z, b = z / nh, h = z - b * nh;
    const __half* A = Abase + (size_t)b * sAb + (size_t)h * sAh + (size_t)blockIdx.y * 128 * lda;
    const __half* B = Bbase + (size_t)b * sBb + (size_t)h * sBh + (size_t)blockIdx.x * 128 * ldb;
    CT* C = Cbase + (size_t)b * sCb + (size_t)h * sCh;
    const float* res = resbase ? resbase + (size_t)b * sCb + (size_t)h * sCh : nullptr;
    int m0 = blockIdx.y * 128, n0 = blockIdx.x * 128;

    float acc[4][4][4];
    #pragma unroll
    for (int mi = 0; mi < 4; mi++)
        #pragma unroll
        for (int ni = 0; ni < 4; ni++)
            #pragma unroll
            for (int c = 0; c < 4; c++) acc[mi][ni][c] = 0.f;

    int lrow = tid >> 3;          // 0..31 (row block: 4 rows per warp-slice pattern)
    int lc   = tid & 7;           // chunk 0..7
    // each thread: 4 A chunks (rows lrow, lrow+32, lrow+64, lrow+96) + 4 B chunks
    auto issue_stage = [&](int kb, int stage) {
        uint32_t as = sb + stage * STAGEB;
        uint32_t bs = as + 16384;
        int koff = kb * 64 + lc * 8;
        #pragma unroll
        for (int i = 0; i < 4; i++) {
            int row = lrow + i * 32;
            cp16(as + row * 128 + ((lc ^ (row & 7)) * 16),
                 A + (size_t)row * lda + koff);
        }
        #pragma unroll
        for (int i = 0; i < 4; i++) {
            int row = lrow + i * 32;
            cp16(bs + row * 128 + ((lc ^ (row & 7)) * 16),
                 B + (size_t)row * ldb + koff);
        }
        asm volatile("cp.async.commit_group;");
    };

    int nkb = K >> 6;
    issue_stage(0, 0);
    issue_stage(1, 1);

    // fragment address precompute
    int arow = wy * 64 + (lane & 15);            // + mi*16
    int brow = wx * 32 + (lane & 15);            // + p*16
    int csel = lane >> 4;                        // 0/1 chunk within k16

    for (int kb = 0; kb < nkb; kb++) {
        asm volatile("cp.async.wait_group 1;");
        __syncthreads();
        int stage = kb % NSTAGE;
        if (kb + 2 < nkb) issue_stage(kb + 2, (kb + 2) % NSTAGE);
        else asm volatile("cp.async.commit_group;");

        uint32_t as = sb + stage * STAGEB;
        uint32_t bs = as + 16384;
        #pragma unroll
        for (int kk = 0; kk < 4; kk++) {
            int ch = kk * 2 + csel;
            uint32_t afr[4][4], breg[2][4];
            #pragma unroll
            for (int mi = 0; mi < 4; mi++) {
                int r = arow + mi * 16;
                ldsm_x4(afr[mi][0], afr[mi][1], afr[mi][2], afr[mi][3],
                        as + r * 128 + ((ch ^ (r & 7)) * 16));
            }
            #pragma unroll
            for (int p = 0; p < 2; p++) {
                int r = brow + p * 16;
                ldsm_x4(breg[p][0], breg[p][1], breg[p][2], breg[p][3],
                        bs + r * 128 + ((ch ^ (r & 7)) * 16));
            }
            #pragma unroll
            for (int mi = 0; mi < 4; mi++)
                #pragma unroll
                for (int ni = 0; ni < 4; ni++) {
                    uint32_t bfr[2] = { breg[ni >> 1][ni & 1], breg[ni >> 1][(ni & 1) + 2] };
                    mma_f16(acc[mi][ni], afr[mi], bfr);
                }
        }
        __syncthreads();
    }

    // epilogue (same acc layout as before)
    #pragma unroll
    for (int mi = 0; mi < 4; mi++) {
        #pragma unroll
        for (int ni = 0; ni < 4; ni++) {
            int col = n0 + wx * 32 + ni * 8 + 2 * (lane & 3);
            #pragma unroll
            for (int half = 0; half < 2; half++) {
                int row = m0 + wy * 64 + mi * 16 + (lane >> 2) + half * 8;
                float c0 = acc[mi][ni][2 * half]     * scale;
                float c1 = acc[mi][ni][2 * half + 1] * scale;
                if (bias) { c0 += bias[col]; c1 += bias[col + 1]; }
                if (act == 1) { c0 = gelu_tanh(c0); c1 = gelu_tanh(c1); }
                if (res) {
                    float2 rv = *(const float2*)(res + (size_t)row * ldc + col);
                    c0 += rv.x; c1 += rv.y;
                }
                store2(C + (size_t)row * ldc + col, c0, c1);
            }
        }
    }
}

// ---------------- host launch ----------------
extern "C" void kernel_launch(void* const* d_in, const int* in_sizes, int n_in,
                              void* d_out, int out_size) {
    const float* x     = (const float*)d_in[0];
    const float* zin   = (const float*)d_in[1];
    const float* g1    = (const float*)d_in[2];
    const float* b1    = (const float*)d_in[3];
    const float* w_qkv = (const float*)d_in[4];
    const float* b_qkv = (const float*)d_in[5];
    const float* w_o   = (const float*)d_in[6];
    const float* b_o   = (const float*)d_in[7];
    const float* w_kv  = (const float*)d_in[8];
    const float* b_kv  = (const float*)d_in[9];
    const float* g2    = (const float*)d_in[10];
    const float* b2    = (const float*)d_in[11];
    const float* w_m1  = (const float*)d_in[12];
    const float* b_m1  = (const float*)d_in[13];
    const float* w_m2  = (const float*)d_in[14];
    const float* b_m2  = (const float*)d_in[15];
    float* out = (float*)d_out;

    __half *ln, *qkv, *kv, *attn, *q, *mlp, *p, *z16;
    __half *wtqkv, *wto, *wtkv, *wtm1, *wtm2, *vts, *vtc;
    float *cross, *xs;
    cudaGetSymbolAddress((void**)&ln,     h_ln);
    cudaGetSymbolAddress((void**)&qkv,    h_qkv);
    cudaGetSymbolAddress((void**)&kv,     h_kv);
    cudaGetSymbolAddress((void**)&attn,   h_attn);
    cudaGetSymbolAddress((void**)&q,      h_q);
    cudaGetSymbolAddress((void**)&cross,  g_cross);
    cudaGetSymbolAddress((void**)&mlp,    h_mlp);
    cudaGetSymbolAddress((void**)&xs,     g_xs);
    cudaGetSymbolAddress((void**)&p,      h_p);
    cudaGetSymbolAddress((void**)&z16,    h_z);
    cudaGetSymbolAddress((void**)&wtqkv,  h_wt_qkv);
    cudaGetSymbolAddress((void**)&wto,    h_wt_o);
    cudaGetSymbolAddress((void**)&wtkv,   h_wt_kv);
    cudaGetSymbolAddress((void**)&wtm1,   h_wt_m1);
    cudaGetSymbolAddress((void**)&wtm2,   h_wt_m2);
    cudaGetSymbolAddress((void**)&vts,    h_vt_self);
    cudaGetSymbolAddress((void**)&vtc,    h_vt_cross);

    cudaFuncSetAttribute(mm2<__half>, cudaFuncAttributeMaxDynamicSharedMemorySize, SMEM2);
    cudaFuncSetAttribute(mm2<float>,  cudaFuncAttributeMaxDynamicSharedMemorySize, SMEM2);

    dim3 tb(32, 8);

    // weight transposes + fp16 convert ([K][N] -> [N][K])
    transpose_h<float><<<dim3(3 * D_MODEL / 32, D_MODEL / 32, 1), tb>>>(w_qkv, wtqkv, 3 * D_MODEL, D_MODEL, 0, 0, 0, 0, 1);
    transpose_h<float><<<dim3(D_MODEL / 32, D_MODEL / 32, 1), tb>>>(w_o, wto, D_MODEL, D_MODEL, 0, 0, 0, 0, 1);
    transpose_h<float><<<dim3(2 * D_MODEL / 32, D_MODEL / 32, 1), tb>>>(w_kv, wtkv, 2 * D_MODEL, D_MODEL, 0, 0, 0, 0, 1);
    transpose_h<float><<<dim3(HMLP / 32, D_MODEL / 32, 1), tb>>>(w_m1, wtm1, HMLP, D_MODEL, 0, 0, 0, 0, 1);
    transpose_h<float><<<dim3(D_MODEL / 32, HMLP / 32, 1), tb>>>(w_m2, wtm2, D_MODEL, HMLP, 0, 0, 0, 0, 1);

    // z -> fp16
    cvt_f2h<<<ROWS * D_MODEL / 8 / 256, 256>>>(zin, z16, ROWS * D_MODEL / 8);

    // 1) ln1(x) -> fp16
    ln_kernel<<<ROWS, 256>>>(x, g1, b1, ln);

    // 2) qkv = ln1 @ w_qkv + b_qkv  (fp16 out)
    mm2<__half><<<dim3(24, 32, 1), 256, SMEM2>>>(
        ln, wtqkv, b_qkv, nullptr, qkv, D_MODEL, D_MODEL, D_MODEL, 3 * D_MODEL,
        0, 0, 0, 0, 0, 0, 1, 1.0f, 0);

    // transpose self V: per (b,h): [S,64] -> [64,S]
    transpose_h<__half><<<dim3(2, 32, BATCH * NHEADS), tb>>>(
        qkv + 2 * D_MODEL, vts, 3 * D_MODEL, SEQ,
        (long)SEQ * 3 * D_MODEL, HDIM, (long)NHEADS * HDIM * SEQ, (long)HDIM * SEQ, NHEADS);

    // 3-5) fused flash self-attention -> attn (fp16)
    flash_self<<<dim3(8, BATCH * NHEADS), 256>>>(qkv, vts, attn);

    // 6) q = x + attn @ w_o + b_o  (fp16 out)
    mm2<__half><<<dim3(8, 32, 1), 256, SMEM2>>>(
        attn, wto, b_o, x, q, D_MODEL, D_MODEL, D_MODEL, D_MODEL,
        0, 0, 0, 0, 0, 0, 1, 1.0f, 0);

    // 7) kv = z @ w_kv + b_kv  (fp16 out)
    mm2<__half><<<dim3(16, 32, 1), 256, SMEM2>>>(
        z16, wtkv, b_kv, nullptr, kv, D_MODEL, D_MODEL, D_MODEL, 2 * D_MODEL,
        0, 0, 0, 0, 0, 0, 1, 1.0f, 0);

    // transpose cross V: per b: [S,D] -> [D,S]
    transpose_h<__half><<<dim3(32, 32, BATCH), tb>>>(
        kv + D_MODEL, vtc, 2 * D_MODEL, SEQ,
        (long)SEQ * 2 * D_MODEL, 0, (long)D_MODEL * SEQ, 0, 1);

    // 8) cross scores = q @ k^T / 32  (fp32 out)
    mm2<float><<<dim3(8, 8, BATCH), 256, SMEM2>>>(
        q, kv, nullptr, nullptr, xs, D_MODEL, D_MODEL, 2 * D_MODEL, SEQ,
        (long)SEQ * D_MODEL, 0, (long)SEQ * 2 * D_MODEL, 0,
        (long)SEQ * SEQ, 0, 1, 0.03125f, 0);

    // 9) softmax fp32 -> fp16 P
    softmax_f2h<<<BATCH * SEQ, 256>>>(xs, p);

    // 10) cross P @ V -> cross (fp32)
    mm2<float><<<dim3(8, 8, BATCH), 256, SMEM2>>>(
        p, vtc, nullptr, nullptr, cross, SEQ, SEQ, SEQ, D_MODEL,
        (long)SEQ * SEQ, 0, (long)D_MODEL * SEQ, 0, (long)SEQ * D_MODEL, 0,
        1, 1.0f, 0);

    // 11) ln2(cross) -> fp16
    ln_kernel<<<ROWS, 256>>>(cross, g2, b2, ln);

    // 12) mlp hidden = gelu(ln2 @ w_m1 + b_m1)  (fp16 out)
    mm2<__half><<<dim3(32, 32, 1), 256, SMEM2>>>(
        ln, wtm1, b_m1, nullptr, mlp, D_MODEL, D_MODEL, D_MODEL, HMLP,
        0, 0, 0, 0, 0, 0, 1, 1.0f, 1);

    // 13) out = cross + mlp @ w_m2 + b_m2  (fp32 out)
    mm2<float><<<dim3(8, 32, 1), 256, SMEM2>>>(
        mlp, wtm2, b_m2, cross, out, HMLP, HMLP, HMLP, D_MODEL,
        0, 0, 0, 0, 0, 0, 1, 1.0f, 0);
}

// round 9
// speedup vs baseline: 7.3191x; 1.0335x over previous
#include <cuda_runtime.h>
#include <cuda_fp16.h>
#include <math.h>
#include <stdint.h>

#define D_MODEL 1024
#define BATCH   4
#define SEQ     1024
#define NHEADS  16
#define HDIM    64
#define HMLP    4096
#define ROWS    (BATCH*SEQ)     // 4096

// ---------------- scratch (device globals; no allocs allowed) ----------------
__device__ __half h_ln   [ROWS * D_MODEL];
__device__ __half h_qkv  [ROWS * 3 * D_MODEL];
__device__ __half h_kv   [ROWS * 2 * D_MODEL];
__device__ __half h_attn [ROWS * D_MODEL];
__device__ __half h_q    [ROWS * D_MODEL];
__device__ float  g_cross[ROWS * D_MODEL];
__device__ __half h_mlp  [ROWS * HMLP];
__device__ float  g_xs   [(size_t)BATCH * SEQ * SEQ];
__device__ __half h_p    [(size_t)BATCH * SEQ * SEQ];
__device__ __half h_z    [ROWS * D_MODEL];
__device__ __half h_wt_qkv[3 * D_MODEL * D_MODEL];
__device__ __half h_wt_o  [D_MODEL * D_MODEL];
__device__ __half h_wt_kv [2 * D_MODEL * D_MODEL];
__device__ __half h_wt_m1 [HMLP * D_MODEL];
__device__ __half h_wt_m2 [D_MODEL * HMLP];
__device__ __half h_vt_self [BATCH * NHEADS * HDIM * SEQ];
__device__ __half h_vt_cross[(size_t)BATCH * D_MODEL * SEQ];

__device__ __forceinline__ float gelu_tanh(float c) {
    float t = 0.7978845608028654f * (c + 0.044715f * c * c * c);
    return 0.5f * c * (1.0f + tanhf(t));
}
__device__ __forceinline__ void mma_f16(float* d, const uint32_t* a, const uint32_t* b) {
    asm volatile("mma.sync.aligned.m16n8k16.row.col.f32.f16.f16.f32 "
        "{%0,%1,%2,%3}, {%4,%5,%6,%7}, {%8,%9}, {%0,%1,%2,%3};"
        : "+f"(d[0]), "+f"(d[1]), "+f"(d[2]), "+f"(d[3])
        : "r"(a[0]), "r"(a[1]), "r"(a[2]), "r"(a[3]), "r"(b[0]), "r"(b[1]));
}
__device__ __forceinline__ void ldsm_x4(uint32_t& r0, uint32_t& r1, uint32_t& r2, uint32_t& r3,
                                        uint32_t addr) {
    asm volatile("ldmatrix.sync.aligned.m8n8.x4.shared.b16 {%0,%1,%2,%3}, [%4];"
        : "=r"(r0), "=r"(r1), "=r"(r2), "=r"(r3) : "r"(addr));
}
__device__ __forceinline__ void cp16(uint32_t smem, const void* g) {
    asm volatile("cp.async.cg.shared.global [%0], [%1], 16;" :: "r"(smem), "l"(g));
}
__device__ __forceinline__ uint32_t smem_u32(const void* p) {
    return (uint32_t)__cvta_generic_to_shared(p);
}
__device__ __forceinline__ void store2(__half* p, float a, float b) {
    *(__half2*)p = __floats2half2_rn(a, b);
}
__device__ __forceinline__ void store2(float* p, float a, float b) {
    float2 v; v.x = a; v.y = b; *(float2*)p = v;
}
__device__ __forceinline__ uint32_t packh2(float a, float b) {
    __half2 h = __floats2half2_rn(a, b);
    return *(uint32_t*)&h;
}

// ---------------- layernorm (fp32 in -> fp16 out) ----------------
__global__ void ln_kernel(const float* __restrict__ x, const float* __restrict__ g,
                          const float* __restrict__ b, __half* __restrict__ out) {
    int row = blockIdx.x;
    const float* xr = x + (size_t)row * D_MODEL;
    __half* orow = out + (size_t)row * D_MODEL;
    int tid = threadIdx.x;
    float s = 0.f, s2 = 0.f;
    for (int i = tid; i < D_MODEL; i += 256) {
        float v = xr[i]; s += v; s2 += v * v;
    }
    __shared__ float red[256], red2[256];
    red[tid] = s; red2[tid] = s2; __syncthreads();
    for (int o = 128; o > 0; o >>= 1) {
        if (tid < o) { red[tid] += red[tid + o]; red2[tid] += red2[tid + o]; }
        __syncthreads();
    }
    float mu  = red[0]  * (1.0f / D_MODEL);
    float var = red2[0] * (1.0f / D_MODEL) - mu * mu;
    float inv = rsqrtf(var + 1e-5f);
    for (int i = tid; i < D_MODEL; i += 512) {
        float v0 = (xr[i] - mu) * inv * g[i] + b[i];
        float v1 = (xr[i + 256] - mu) * inv * g[i + 256] + b[i + 256];
        orow[i] = __float2half(v0);
        orow[i + 256] = __float2half(v1);
    }
}

// ---------------- softmax fp32 in -> fp16 out (cross) ----------------
__global__ void softmax_f2h(const float* __restrict__ S, __half* __restrict__ P) {
    const float* row = S + (size_t)blockIdx.x * 1024;
    __half* prow = P + (size_t)blockIdx.x * 1024;
    int tid = threadIdx.x;
    float4 v = *(const float4*)(row + tid * 4);
    float mx = fmaxf(fmaxf(v.x, v.y), fmaxf(v.z, v.w));
    __shared__ float red[32];
    for (int o = 16; o > 0; o >>= 1) mx = fmaxf(mx, __shfl_xor_sync(0xffffffff, mx, o));
    if ((tid & 31) == 0) red[tid >> 5] = mx;
    __syncthreads();
    if (tid < 32) {
        float m = (tid < 8) ? red[tid] : -1e30f;
        for (int o = 4; o > 0; o >>= 1) m = fmaxf(m, __shfl_xor_sync(0xffffffff, m, o));
        red[0] = m;
    }
    __syncthreads();
    mx = red[0];
    v.x = expf(v.x - mx); v.y = expf(v.y - mx); v.z = expf(v.z - mx); v.w = expf(v.w - mx);
    float s = v.x + v.y + v.z + v.w;
    for (int o = 16; o > 0; o >>= 1) s += __shfl_xor_sync(0xffffffff, s, o);
    __syncthreads();
    if ((tid & 31) == 0) red[tid >> 5] = s;
    __syncthreads();
    if (tid < 32) {
        float t = (tid < 8) ? red[tid] : 0.f;
        for (int o = 4; o > 0; o >>= 1) t += __shfl_xor_sync(0xffffffff, t, o);
        red[0] = t;
    }
    __syncthreads();
    float inv = 1.0f / red[0];
    __half2 h2[2];
    h2[0] = __floats2half2_rn(v.x * inv, v.y * inv);
    h2[1] = __floats2half2_rn(v.z * inv, v.w * inv);
    *(uint2*)(prow + tid * 4) = *(uint2*)h2;
}

// ---------------- batched transpose (TS in -> half out) ----------------
template <typename TS>
__global__ void transpose_h(const TS* __restrict__ srcb, __half* __restrict__ dstb,
                            int lds, int ldd, long sSb, long sSh, long sDb, long sDh, int nh) {
    int z = blockIdx.z, b = z / nh, h = z - b * nh;
    const TS* src = srcb + (size_t)b * sSb + (size_t)h * sSh;
    __half* dst = dstb + (size_t)b * sDb + (size_t)h * sDh;
    __shared__ __half tile[32][34];
    int x = blockIdx.x * 32, y = blockIdx.y * 32;
    int tx = threadIdx.x, ty = threadIdx.y;
    #pragma unroll
    for (int i = ty; i < 32; i += 8)
        tile[i][tx] = __float2half((float)src[(size_t)(y + i) * lds + x + tx]);
    __syncthreads();
    #pragma unroll
    for (int i = ty; i < 32; i += 8)
        dst[(size_t)(x + i) * ldd + y + tx] = tile[tx][i];
}

// ---------------- fp32 -> fp16 elementwise ----------------
__global__ void cvt_f2h(const float* __restrict__ src, __half* __restrict__ dst, int n8) {
    int i = blockIdx.x * 256 + threadIdx.x;
    if (i < n8) {
        float4 a = *(const float4*)(src + (size_t)i * 8);
        float4 b = *(const float4*)(src + (size_t)i * 8 + 4);
        __half2 h[4];
        h[0] = __floats2half2_rn(a.x, a.y); h[1] = __floats2half2_rn(a.z, a.w);
        h[2] = __floats2half2_rn(b.x, b.y); h[3] = __floats2half2_rn(b.z, b.w);
        *(uint4*)(dst + (size_t)i * 8) = *(uint4*)h;
    }
}

// ================= flash self-attention (unchanged) =================
#define FROW 40
__device__ __forceinline__ void sts_q40(uint32_t* stg, int row, int q, uint4 v) {
    int g = q >> 1, hh = q & 1;
    uint32_t* p = stg + row * FROW + g * 8 + hh;
    p[0] = v.x; p[2] = v.y; p[4] = v.z; p[6] = v.w;
}

__global__ void __launch_bounds__(256)
flash_self(const __half* __restrict__ qkvg, const __half* __restrict__ vtsg,
           __half* __restrict__ attng) {
    __shared__ uint32_t Qs[128 * FROW];
    __shared__ uint32_t Ks[64 * FROW];
    __shared__ uint32_t Vs[64 * FROW];

    int tid = threadIdx.x, lane = tid & 31, warp = tid >> 5;
    int bh = blockIdx.y, b = bh >> 4, h = bh & 15;
    const __half* Qg = qkvg + (size_t)b * SEQ * 3 * D_MODEL
                     + (size_t)blockIdx.x * 128 * 3 * D_MODEL + h * HDIM;
    const __half* Kg = qkvg + (size_t)b * SEQ * 3 * D_MODEL + D_MODEL + h * HDIM;
    const __half* Vt = vtsg + (size_t)bh * HDIM * SEQ;
    __half* Og = attng + (size_t)b * SEQ * D_MODEL
               + (size_t)blockIdx.x * 128 * D_MODEL + h * HDIM;

    #pragma unroll
    for (int i = 0; i < 4; i++) {
        int f = i * 256 + tid, row = f >> 3, q = f & 7;
        sts_q40(Qs, row, q, *(const uint4*)(Qg + (size_t)row * 3 * D_MODEL + q * 8));
    }
    __syncthreads();

    uint32_t qa[4][4];
    {
        int r = warp * 16 + (lane >> 2);
        int co = 2 * (lane & 3);
        #pragma unroll
        for (int kk = 0; kk < 4; kk++) {
            uint2 lo = *(const uint2*)&Qs[r * FROW + kk * 8 + co];
            uint2 hi = *(const uint2*)&Qs[(r + 8) * FROW + kk * 8 + co];
            qa[kk][0] = lo.x; qa[kk][1] = hi.x; qa[kk][2] = lo.y; qa[kk][3] = hi.y;
        }
    }

    float oacc[8][4];
    #pragma unroll
    for (int ni = 0; ni < 8; ni++)
        #pragma unroll
        for (int c = 0; c < 4; c++) oacc[ni][c] = 0.f;
    float m0 = -1e30f, m1 = -1e30f, l0 = 0.f, l1 = 0.f;

    for (int kb = 0; kb < 16; kb++) {
        __syncthreads();
        #pragma unroll
        for (int i = 0; i < 2; i++) {
            int f = i * 256 + tid, row = f >> 3, q = f & 7;
            sts_q40(Ks, row, q, *(const uint4*)(Kg + (size_t)(kb * 64 + row) * 3 * D_MODEL + q * 8));
            sts_q40(Vs, row, q, *(const uint4*)(Vt + (size_t)row * SEQ + kb * 64 + q * 8));
        }
        __syncthreads();

        float sacc[8][4];
        #pragma unroll
        for (int ni = 0; ni < 8; ni++)
            #pragma unroll
            for (int c = 0; c < 4; c++) sacc[ni][c] = 0.f;
        int co = 2 * (lane & 3);
        #pragma unroll
        for (int kk = 0; kk < 4; kk++) {
            #pragma unroll
            for (int ni = 0; ni < 8; ni++) {
                int rn = ni * 8 + (lane >> 2);
                uint2 bb = *(const uint2*)&Ks[rn * FROW + kk * 8 + co];
                uint32_t bfr[2] = { bb.x, bb.y };
                mma_f16(sacc[ni], qa[kk], bfr);
            }
        }

        float mx0 = -1e30f, mx1 = -1e30f;
        #pragma unroll
        for (int ni = 0; ni < 8; ni++) {
            mx0 = fmaxf(mx0, fmaxf(sacc[ni][0], sacc[ni][1]));
            mx1 = fmaxf(mx1, fmaxf(sacc[ni][2], sacc[ni][3]));
        }
        mx0 = fmaxf(mx0, __shfl_xor_sync(0xffffffff, mx0, 1));
        mx0 = fmaxf(mx0, __shfl_xor_sync(0xffffffff, mx0, 2));
        mx1 = fmaxf(mx1, __shfl_xor_sync(0xffffffff, mx1, 1));
        mx1 = fmaxf(mx1, __shfl_xor_sync(0xffffffff, mx1, 2));
        float nm0 = fmaxf(m0, mx0 * 0.125f);
        float nm1 = fmaxf(m1, mx1 * 0.125f);
        float a0 = __expf(m0 - nm0);
        float a1 = __expf(m1 - nm1);
        m0 = nm0; m1 = nm1;

        uint32_t pw0[8], pw1[8];
        float s0 = 0.f, s1 = 0.f;
        #pragma unroll
        for (int ni = 0; ni < 8; ni++) {
            float p0 = __expf(sacc[ni][0] * 0.125f - nm0);
            float p1 = __expf(sacc[ni][1] * 0.125f - nm0);
            float p2 = __expf(sacc[ni][2] * 0.125f - nm1);
            float p3 = __expf(sacc[ni][3] * 0.125f - nm1);
            s0 += p0 + p1; s1 += p2 + p3;
            pw0[ni] = packh2(p0, p1);
            pw1[ni] = packh2(p2, p3);
        }
        s0 += __shfl_xor_sync(0xffffffff, s0, 1);
        s0 += __shfl_xor_sync(0xffffffff, s0, 2);
        s1 += __shfl_xor_sync(0xffffffff, s1, 1);
        s1 += __shfl_xor_sync(0xffffffff, s1, 2);
        l0 = l0 * a0 + s0;
        l1 = l1 * a1 + s1;
        #pragma unroll
        for (int ni = 0; ni < 8; ni++) {
            oacc[ni][0] *= a0; oacc[ni][1] *= a0;
            oacc[ni][2] *= a1; oacc[ni][3] *= a1;
        }

        #pragma unroll
        for (int kp = 0; kp < 4; kp++) {
            uint32_t pa[4] = { pw0[2 * kp], pw1[2 * kp], pw0[2 * kp + 1], pw1[2 * kp + 1] };
            #pragma unroll
            for (int ni = 0; ni < 8; ni++) {
                int rn = ni * 8 + (lane >> 2);
                uint2 bb = *(const uint2*)&Vs[rn * FROW + kp * 8 + co];
                uint32_t bfr[2] = { bb.x, bb.y };
                mma_f16(oacc[ni], pa, bfr);
            }
        }
    }

    float i0 = 1.0f / l0, i1 = 1.0f / l1;
    int r = warp * 16 + (lane >> 2);
    #pragma unroll
    for (int ni = 0; ni < 8; ni++) {
        int col = ni * 8 + 2 * (lane & 3);
        store2(Og + (size_t)r * D_MODEL + col,       oacc[ni][0] * i0, oacc[ni][1] * i0);
        store2(Og + (size_t)(r + 8) * D_MODEL + col, oacc[ni][2] * i1, oacc[ni][3] * i1);
    }
}

// ============ fp16 GEMM: cp.async + swizzle + ldmatrix, 128x256 tile ============
// C[M,N] = scale * A[M,K] @ B[N,K]^T (+bias)(+gelu)(+res). KB=64, 3 stages.
// Warp grid 2x4, warp tile 64x64 (mma:ldsm = 4:1).
#define NSTAGE 3
#define A_BYTES 16384
#define B_BYTES 32768
#define STAGEB (A_BYTES + B_BYTES)
#define SMEM2  (NSTAGE * STAGEB)

template <typename CT>
__global__ void __launch_bounds__(256)
mm2(const __half* __restrict__ Abase, const __half* __restrict__ Bbase,
    const float* __restrict__ bias, const float* __restrict__ resbase,
    CT* __restrict__ Cbase, int K, int lda, int ldb, int ldc,
    long sAb, long sBb, long sCb, float scale, int act) {
    extern __shared__ __align__(16) char smc[];
    uint32_t sb = smem_u32(smc);

    int tid = threadIdx.x, lane = tid & 31, warp = tid >> 5;
    int wy = warp & 1, wx = warp >> 1;           // 2 x 4 warp grid; warp tile 64x64
    int z = blockIdx.z;
    const __half* A = Abase + (size_t)z * sAb + (size_t)blockIdx.y * 128 * lda;
    const __half* B = Bbase + (size_t)z * sBb + (size_t)blockIdx.x * 256 * ldb;
    CT* C = Cbase + (size_t)z * sCb;
    const float* res = resbase ? resbase + (size_t)z * sCb : nullptr;
    int m0 = blockIdx.y * 128, n0 = blockIdx.x * 256;

    float acc[4][8][4];
    #pragma unroll
    for (int mi = 0; mi < 4; mi++)
        #pragma unroll
        for (int ni = 0; ni < 8; ni++)
            #pragma unroll
            for (int c = 0; c < 4; c++) acc[mi][ni][c] = 0.f;

    int lrow = tid >> 3;          // 0..31
    int lc   = tid & 7;           // chunk 0..7
    auto issue_stage = [&](int kb, int stage) {
        uint32_t as = sb + stage * STAGEB;
        uint32_t bs = as + A_BYTES;
        int koff = kb * 64 + lc * 8;
        #pragma unroll
        for (int i = 0; i < 4; i++) {
            int row = lrow + i * 32;
            cp16(as + row * 128 + ((lc ^ (row & 7)) * 16),
                 A + (size_t)row * lda + koff);
        }
        #pragma unroll
        for (int i = 0; i < 8; i++) {
            int row = lrow + i * 32;
            cp16(bs + row * 128 + ((lc ^ (row & 7)) * 16),
                 B + (size_t)row * ldb + koff);
        }
        asm volatile("cp.async.commit_group;");
    };

    int nkb = K >> 6;
    issue_stage(0, 0);
    issue_stage(1, 1);

    int arow = wy * 64 + (lane & 15);            // + mi*16
    int brow = wx * 64 + (lane & 15);            // + p*16
    int csel = lane >> 4;

    for (int kb = 0; kb < nkb; kb++) {
        asm volatile("cp.async.wait_group 1;");
        __syncthreads();
        int stage = kb % NSTAGE;
        if (kb + 2 < nkb) issue_stage(kb + 2, (kb + 2) % NSTAGE);
        else asm volatile("cp.async.commit_group;");

        uint32_t as = sb + stage * STAGEB;
        uint32_t bs = as + A_BYTES;
        #pragma unroll
        for (int kk = 0; kk < 4; kk++) {
            int ch = kk * 2 + csel;
            uint32_t afr[4][4], breg[4][4];
            #pragma unroll
            for (int mi = 0; mi < 4; mi++) {
                int r = arow + mi * 16;
                ldsm_x4(afr[mi][0], afr[mi][1], afr[mi][2], afr[mi][3],
                        as + r * 128 + ((ch ^ (r & 7)) * 16));
            }
            #pragma unroll
            for (int p = 0; p < 4; p++) {
                int r = brow + p * 16;
                ldsm_x4(breg[p][0], breg[p][1], breg[p][2], breg[p][3],
                        bs + r * 128 + ((ch ^ (r & 7)) * 16));
            }
            #pragma unroll
            for (int mi = 0; mi < 4; mi++)
                #pragma unroll
                for (int ni = 0; ni < 8; ni++) {
                    uint32_t bfr[2] = { breg[ni >> 1][ni & 1], breg[ni >> 1][(ni & 1) + 2] };
                    mma_f16(acc[mi][ni], afr[mi], bfr);
                }
        }
        // NOTE: no trailing barrier — top-of-loop __syncthreads orders stage reuse
    }

    // epilogue
    #pragma unroll
    for (int mi = 0; mi < 4; mi++) {
        #pragma unroll
        for (int ni = 0; ni < 8; ni++) {
            int col = n0 + wx * 64 + ni * 8 + 2 * (lane & 3);
            #pragma unroll
            for (int half = 0; half < 2; half++) {
                int row = m0 + wy * 64 + mi * 16 + (lane >> 2) + half * 8;
                float c0 = acc[mi][ni][2 * half]     * scale;
                float c1 = acc[mi][ni][2 * half + 1] * scale;
                if (bias) { c0 += bias[col]; c1 += bias[col + 1]; }
                if (act == 1) { c0 = gelu_tanh(c0); c1 = gelu_tanh(c1); }
                if (res) {
                    float2 rv = *(const float2*)(res + (size_t)row * ldc + col);
                    c0 += rv.x; c1 += rv.y;
                }
                store2(C + (size_t)row * ldc + col, c0, c1);
            }
        }
    }
}

// ---------------- host launch ----------------
extern "C" void kernel_launch(void* const* d_in, const int* in_sizes, int n_in,
                              void* d_out, int out_size) {
    const float* x     = (const float*)d_in[0];
    const float* zin   = (const float*)d_in[1];
    const float* g1    = (const float*)d_in[2];
    const float* b1    = (const float*)d_in[3];
    const float* w_qkv = (const float*)d_in[4];
    const float* b_qkv = (const float*)d_in[5];
    const float* w_o   = (const float*)d_in[6];
    const float* b_o   = (const float*)d_in[7];
    const float* w_kv  = (const float*)d_in[8];
    const float* b_kv  = (const float*)d_in[9];
    const float* g2    = (const float*)d_in[10];
    const float* b2    = (const float*)d_in[11];
    const float* w_m1  = (const float*)d_in[12];
    const float* b_m1  = (const float*)d_in[13];
    const float* w_m2  = (const float*)d_in[14];
    const float* b_m2  = (const float*)d_in[15];
    float* out = (float*)d_out;

    __half *ln, *qkv, *kv, *attn, *q, *mlp, *p, *z16;
    __half *wtqkv, *wto, *wtkv, *wtm1, *wtm2, *vts, *vtc;
    float *cross, *xs;
    cudaGetSymbolAddress((void**)&ln,     h_ln);
    cudaGetSymbolAddress((void**)&qkv,    h_qkv);
    cudaGetSymbolAddress((void**)&kv,     h_kv);
    cudaGetSymbolAddress((void**)&attn,   h_attn);
    cudaGetSymbolAddress((void**)&q,      h_q);
    cudaGetSymbolAddress((void**)&cross,  g_cross);
    cudaGetSymbolAddress((void**)&mlp,    h_mlp);
    cudaGetSymbolAddress((void**)&xs,     g_xs);
    cudaGetSymbolAddress((void**)&p,      h_p);
    cudaGetSymbolAddress((void**)&z16,    h_z);
    cudaGetSymbolAddress((void**)&wtqkv,  h_wt_qkv);
    cudaGetSymbolAddress((void**)&wto,    h_wt_o);
    cudaGetSymbolAddress((void**)&wtkv,   h_wt_kv);
    cudaGetSymbolAddress((void**)&wtm1,   h_wt_m1);
    cudaGetSymbolAddress((void**)&wtm2,   h_wt_m2);
    cudaGetSymbolAddress((void**)&vts,    h_vt_self);
    cudaGetSymbolAddress((void**)&vtc,    h_vt_cross);

    cudaFuncSetAttribute(mm2<__half>, cudaFuncAttributeMaxDynamicSharedMemorySize, SMEM2);
    cudaFuncSetAttribute(mm2<float>,  cudaFuncAttributeMaxDynamicSharedMemorySize, SMEM2);

    dim3 tb(32, 8);

    // weight transposes + fp16 convert ([K][N] -> [N][K])
    transpose_h<float><<<dim3(3 * D_MODEL / 32, D_MODEL / 32, 1), tb>>>(w_qkv, wtqkv, 3 * D_MODEL, D_MODEL, 0, 0, 0, 0, 1);
    transpose_h<float><<<dim3(D_MODEL / 32, D_MODEL / 32, 1), tb>>>(w_o, wto, D_MODEL, D_MODEL, 0, 0, 0, 0, 1);
    transpose_h<float><<<dim3(2 * D_MODEL / 32, D_MODEL / 32, 1), tb>>>(w_kv, wtkv, 2 * D_MODEL, D_MODEL, 0, 0, 0, 0, 1);
    transpose_h<float><<<dim3(HMLP / 32, D_MODEL / 32, 1), tb>>>(w_m1, wtm1, HMLP, D_MODEL, 0, 0, 0, 0, 1);
    transpose_h<float><<<dim3(D_MODEL / 32, HMLP / 32, 1), tb>>>(w_m2, wtm2, D_MODEL, HMLP, 0, 0, 0, 0, 1);

    // z -> fp16
    cvt_f2h<<<ROWS * D_MODEL / 8 / 256, 256>>>(zin, z16, ROWS * D_MODEL / 8);

    // 1) ln1(x) -> fp16
    ln_kernel<<<ROWS, 256>>>(x, g1, b1, ln);

    // 2) qkv = ln1 @ w_qkv + b_qkv  (fp16 out)
    mm2<__half><<<dim3(12, 32, 1), 256, SMEM2>>>(
        ln, wtqkv, b_qkv, nullptr, qkv, D_MODEL, D_MODEL, D_MODEL, 3 * D_MODEL,
        0, 0, 0, 1.0f, 0);

    // transpose self V: per (b,h): [S,64] -> [64,S]
    transpose_h<__half><<<dim3(2, 32, BATCH * NHEADS), tb>>>(
        qkv + 2 * D_MODEL, vts, 3 * D_MODEL, SEQ,
        (long)SEQ * 3 * D_MODEL, HDIM, (long)NHEADS * HDIM * SEQ, (long)HDIM * SEQ, NHEADS);

    // 3-5) fused flash self-attention -> attn (fp16)
    flash_self<<<dim3(8, BATCH * NHEADS), 256>>>(qkv, vts, attn);

    // 6) q = x + attn @ w_o + b_o  (fp16 out)
    mm2<__half><<<dim3(4, 32, 1), 256, SMEM2>>>(
        attn, wto, b_o, x, q, D_MODEL, D_MODEL, D_MODEL, D_MODEL,
        0, 0, 0, 1.0f, 0);

    // 7) kv = z @ w_kv + b_kv  (fp16 out)
    mm2<__half><<<dim3(8, 32, 1), 256, SMEM2>>>(
        z16, wtkv, b_kv, nullptr, kv, D_MODEL, D_MODEL, D_MODEL, 2 * D_MODEL,
        0, 0, 0, 1.0f, 0);

    // transpose cross V: per b: [S,D] -> [D,S]
    transpose_h<__half><<<dim3(32, 32, BATCH), tb>>>(
        kv + D_MODEL, vtc, 2 * D_MODEL, SEQ,
        (long)SEQ * 2 * D_MODEL, 0, (long)D_MODEL * SEQ, 0, 1);

    // 8) cross scores = q @ k^T / 32  (fp32 out)
    mm2<float><<<dim3(4, 8, BATCH), 256, SMEM2>>>(
        q, kv, nullptr, nullptr, xs, D_MODEL, D_MODEL, 2 * D_MODEL, SEQ,
        (long)SEQ * D_MODEL, (long)SEQ * 2 * D_MODEL, (long)SEQ * SEQ, 0.03125f, 0);

    // 9) softmax fp32 -> fp16 P
    softmax_f2h<<<BATCH * SEQ, 256>>>(xs, p);

    // 10) cross P @ V -> cross (fp32)
    mm2<float><<<dim3(4, 8, BATCH), 256, SMEM2>>>(
        p, vtc, nullptr, nullptr, cross, SEQ, SEQ, SEQ, D_MODEL,
        (long)SEQ * SEQ, (long)D_MODEL * SEQ, (long)SEQ * D_MODEL, 1.0f, 0);

    // 11) ln2(cross) -> fp16
    ln_kernel<<<ROWS, 256>>>(cross, g2, b2, ln);

    // 12) mlp hidden = gelu(ln2 @ w_m1 + b_m1)  (fp16 out)
    mm2<__half><<<dim3(16, 32, 1), 256, SMEM2>>>(
        ln, wtm1, b_m1, nullptr, mlp, D_MODEL, D_MODEL, D_MODEL, HMLP,
        0, 0, 0, 1.0f, 1);

    // 13) out = cross + mlp @ w_m2 + b_m2  (fp32 out)
    mm2<float><<<dim3(4, 32, 1), 256, SMEM2>>>(
        mlp, wtm2, b_m2, cross, out, HMLP, HMLP, HMLP, D_MODEL,
        0, 0, 0, 1.0f, 0);
}

// round 10
// speedup vs baseline: 7.5413x; 1.0304x over previous
#include <cuda_runtime.h>
#include <cuda_fp16.h>
#include <math.h>
#include <stdint.h>

#define D_MODEL 1024
#define BATCH   4
#define SEQ     1024
#define NHEADS  16
#define HDIM    64
#define HMLP    4096
#define ROWS    (BATCH*SEQ)     // 4096

// ---------------- scratch (device globals; no allocs allowed) ----------------
__device__ __half h_ln   [ROWS * D_MODEL];
__device__ __half h_qkv  [ROWS * 3 * D_MODEL];
__device__ __half h_kv   [ROWS * 2 * D_MODEL];
__device__ __half h_attn [ROWS * D_MODEL];
__device__ __half h_q    [ROWS * D_MODEL];
__device__ float  g_cross[ROWS * D_MODEL];
__device__ __half h_mlp  [ROWS * HMLP];
__device__ float  g_xs   [(size_t)BATCH * SEQ * SEQ];
__device__ __half h_p    [(size_t)BATCH * SEQ * SEQ];
__device__ __half h_z    [ROWS * D_MODEL];
__device__ __half h_wt_qkv[3 * D_MODEL * D_MODEL];
__device__ __half h_wt_o  [D_MODEL * D_MODEL];
__device__ __half h_wt_kv [2 * D_MODEL * D_MODEL];
__device__ __half h_wt_m1 [HMLP * D_MODEL];
__device__ __half h_wt_m2 [D_MODEL * HMLP];
__device__ __half h_vt_self [BATCH * NHEADS * HDIM * SEQ];
__device__ __half h_vt_cross[(size_t)BATCH * D_MODEL * SEQ];

__device__ __forceinline__ float gelu_tanh(float c) {
    float t = 0.7978845608028654f * (c + 0.044715f * c * c * c);
    return 0.5f * c * (1.0f + tanhf(t));
}
__device__ __forceinline__ void mma_f16(float* d, const uint32_t* a, const uint32_t* b) {
    asm volatile("mma.sync.aligned.m16n8k16.row.col.f32.f16.f16.f32 "
        "{%0,%1,%2,%3}, {%4,%5,%6,%7}, {%8,%9}, {%0,%1,%2,%3};"
        : "+f"(d[0]), "+f"(d[1]), "+f"(d[2]), "+f"(d[3])
        : "r"(a[0]), "r"(a[1]), "r"(a[2]), "r"(a[3]), "r"(b[0]), "r"(b[1]));
}
__device__ __forceinline__ void ldsm_x4(uint32_t& r0, uint32_t& r1, uint32_t& r2, uint32_t& r3,
                                        uint32_t addr) {
    asm volatile("ldmatrix.sync.aligned.m8n8.x4.shared.b16 {%0,%1,%2,%3}, [%4];"
        : "=r"(r0), "=r"(r1), "=r"(r2), "=r"(r3) : "r"(addr));
}
__device__ __forceinline__ void cp16(uint32_t smem, const void* g) {
    asm volatile("cp.async.cg.shared.global [%0], [%1], 16;" :: "r"(smem), "l"(g));
}
__device__ __forceinline__ uint32_t smem_u32(const void* p) {
    return (uint32_t)__cvta_generic_to_shared(p);
}
__device__ __forceinline__ void store2(__half* p, float a, float b) {
    *(__half2*)p = __floats2half2_rn(a, b);
}
__device__ __forceinline__ void store2(float* p, float a, float b) {
    float2 v; v.x = a; v.y = b; *(float2*)p = v;
}
__device__ __forceinline__ uint32_t packh2(float a, float b) {
    __half2 h = __floats2half2_rn(a, b);
    return *(uint32_t*)&h;
}

// ---------------- layernorm (fp32 in -> fp16 out) + optional z convert --------
__global__ void ln_kernel(const float* __restrict__ x, const float* __restrict__ g,
                          const float* __restrict__ b, __half* __restrict__ out,
                          const float* __restrict__ zsrc, __half* __restrict__ zdst) {
    int row = blockIdx.x;
    const float* xr = x + (size_t)row * D_MODEL;
    __half* orow = out + (size_t)row * D_MODEL;
    int tid = threadIdx.x;
    float s = 0.f, s2 = 0.f;
    for (int i = tid; i < D_MODEL; i += 256) {
        float v = xr[i]; s += v; s2 += v * v;
    }
    if (zsrc) {
        const float* zr = zsrc + (size_t)row * D_MODEL;
        __half* zo = zdst + (size_t)row * D_MODEL;
        float4 a = *(const float4*)(zr + tid * 4);
        __half2 h[2];
        h[0] = __floats2half2_rn(a.x, a.y); h[1] = __floats2half2_rn(a.z, a.w);
        *(uint2*)(zo + tid * 4) = *(uint2*)h;
    }
    __shared__ float red[256], red2[256];
    red[tid] = s; red2[tid] = s2; __syncthreads();
    for (int o = 128; o > 0; o >>= 1) {
        if (tid < o) { red[tid] += red[tid + o]; red2[tid] += red2[tid + o]; }
        __syncthreads();
    }
    float mu  = red[0]  * (1.0f / D_MODEL);
    float var = red2[0] * (1.0f / D_MODEL) - mu * mu;
    float inv = rsqrtf(var + 1e-5f);
    for (int i = tid; i < D_MODEL; i += 512) {
        float v0 = (xr[i] - mu) * inv * g[i] + b[i];
        float v1 = (xr[i + 256] - mu) * inv * g[i + 256] + b[i + 256];
        orow[i] = __float2half(v0);
        orow[i + 256] = __float2half(v1);
    }
}

// ---------------- softmax fp32 in -> fp16 out (cross) ----------------
__global__ void softmax_f2h(const float* __restrict__ S, __half* __restrict__ P) {
    const float* row = S + (size_t)blockIdx.x * 1024;
    __half* prow = P + (size_t)blockIdx.x * 1024;
    int tid = threadIdx.x;
    float4 v = *(const float4*)(row + tid * 4);
    float mx = fmaxf(fmaxf(v.x, v.y), fmaxf(v.z, v.w));
    __shared__ float red[32];
    for (int o = 16; o > 0; o >>= 1) mx = fmaxf(mx, __shfl_xor_sync(0xffffffff, mx, o));
    if ((tid & 31) == 0) red[tid >> 5] = mx;
    __syncthreads();
    if (tid < 32) {
        float m = (tid < 8) ? red[tid] : -1e30f;
        for (int o = 4; o > 0; o >>= 1) m = fmaxf(m, __shfl_xor_sync(0xffffffff, m, o));
        red[0] = m;
    }
    __syncthreads();
    mx = red[0];
    v.x = expf(v.x - mx); v.y = expf(v.y - mx); v.z = expf(v.z - mx); v.w = expf(v.w - mx);
    float s = v.x + v.y + v.z + v.w;
    for (int o = 16; o > 0; o >>= 1) s += __shfl_xor_sync(0xffffffff, s, o);
    __syncthreads();
    if ((tid & 31) == 0) red[tid >> 5] = s;
    __syncthreads();
    if (tid < 32) {
        float t = (tid < 8) ? red[tid] : 0.f;
        for (int o = 4; o > 0; o >>= 1) t += __shfl_xor_sync(0xffffffff, t, o);
        red[0] = t;
    }
    __syncthreads();
    float inv = 1.0f / red[0];
    __half2 h2[2];
    h2[0] = __floats2half2_rn(v.x * inv, v.y * inv);
    h2[1] = __floats2half2_rn(v.z * inv, v.w * inv);
    *(uint2*)(prow + tid * 4) = *(uint2*)h2;
}

// ---------------- fast 64x64 batched transpose (TS in -> half out) ------------
// src [R, C] (row stride lds) -> dst [C, R] (row stride ldd). Vectorized both sides.
template <typename TS>
__device__ __forceinline__ void ld4h(const TS* p, __half* v);
template <>
__device__ __forceinline__ void ld4h<float>(const float* p, __half* v) {
    float4 f = *(const float4*)p;
    v[0] = __float2half(f.x); v[1] = __float2half(f.y);
    v[2] = __float2half(f.z); v[3] = __float2half(f.w);
}
template <>
__device__ __forceinline__ void ld4h<__half>(const __half* p, __half* v) {
    uint2 u = *(const uint2*)p;
    *(uint32_t*)&v[0] = u.x; *(uint32_t*)&v[2] = u.y;
}

template <typename TS>
__global__ void __launch_bounds__(256)
transpose64(const TS* __restrict__ srcb, __half* __restrict__ dstb,
            int lds, int ldd, long sSb, long sSh, long sDb, long sDh, int nh) {
    __shared__ __half tile[64][66];
    int z = blockIdx.z, b = z / nh, h = z - b * nh;
    const TS* src = srcb + (size_t)b * sSb + (size_t)h * sSh;
    __half* dst = dstb + (size_t)b * sDb + (size_t)h * sDh;
    int x0 = blockIdx.x * 64;   // src col block == dst row block
    int y0 = blockIdx.y * 64;   // src row block == dst col block
    int tx = threadIdx.x & 15, ty = threadIdx.x >> 4;
    #pragma unroll
    for (int i = 0; i < 4; i++) {
        int row = y0 + ty + i * 16;
        __half v[4];
        ld4h<TS>(src + (size_t)row * lds + x0 + tx * 4, v);
        tile[tx * 4 + 0][ty + i * 16] = v[0];
        tile[tx * 4 + 1][ty + i * 16] = v[1];
        tile[tx * 4 + 2][ty + i * 16] = v[2];
        tile[tx * 4 + 3][ty + i * 16] = v[3];
    }
    __syncthreads();
    #pragma unroll
    for (int i = 0; i < 4; i++) {
        int drow = x0 + ty + i * 16;
        __half2 p0, p1;
        p0.x = tile[ty + i * 16][tx * 4 + 0]; p0.y = tile[ty + i * 16][tx * 4 + 1];
        p1.x = tile[ty + i * 16][tx * 4 + 2]; p1.y = tile[ty + i * 16][tx * 4 + 3];
        uint2 o; o.x = *(uint32_t*)&p0; o.y = *(uint32_t*)&p1;
        *(uint2*)(dst + (size_t)drow * ldd + y0 + tx * 4) = o;
    }
}

// ================= flash self-attention (unchanged) =================
#define FROW 40
__device__ __forceinline__ void sts_q40(uint32_t* stg, int row, int q, uint4 v) {
    int g = q >> 1, hh = q & 1;
    uint32_t* p = stg + row * FROW + g * 8 + hh;
    p[0] = v.x; p[2] = v.y; p[4] = v.z; p[6] = v.w;
}

__global__ void __launch_bounds__(256)
flash_self(const __half* __restrict__ qkvg, const __half* __restrict__ vtsg,
           __half* __restrict__ attng) {
    __shared__ uint32_t Qs[128 * FROW];
    __shared__ uint32_t Ks[64 * FROW];
    __shared__ uint32_t Vs[64 * FROW];

    int tid = threadIdx.x, lane = tid & 31, warp = tid >> 5;
    int bh = blockIdx.y, b = bh >> 4, h = bh & 15;
    const __half* Qg = qkvg + (size_t)b * SEQ * 3 * D_MODEL
                     + (size_t)blockIdx.x * 128 * 3 * D_MODEL + h * HDIM;
    const __half* Kg = qkvg + (size_t)b * SEQ * 3 * D_MODEL + D_MODEL + h * HDIM;
    const __half* Vt = vtsg + (size_t)bh * HDIM * SEQ;
    __half* Og = attng + (size_t)b * SEQ * D_MODEL
               + (size_t)blockIdx.x * 128 * D_MODEL + h * HDIM;

    #pragma unroll
    for (int i = 0; i < 4; i++) {
        int f = i * 256 + tid, row = f >> 3, q = f & 7;
        sts_q40(Qs, row, q, *(const uint4*)(Qg + (size_t)row * 3 * D_MODEL + q * 8));
    }
    __syncthreads();

    uint32_t qa[4][4];
    {
        int r = warp * 16 + (lane >> 2);
        int co = 2 * (lane & 3);
        #pragma unroll
        for (int kk = 0; kk < 4; kk++) {
            uint2 lo = *(const uint2*)&Qs[r * FROW + kk * 8 + co];
            uint2 hi = *(const uint2*)&Qs[(r + 8) * FROW + kk * 8 + co];
            qa[kk][0] = lo.x; qa[kk][1] = hi.x; qa[kk][2] = lo.y; qa[kk][3] = hi.y;
        }
    }

    float oacc[8][4];
    #pragma unroll
    for (int ni = 0; ni < 8; ni++)
        #pragma unroll
        for (int c = 0; c < 4; c++) oacc[ni][c] = 0.f;
    float m0 = -1e30f, m1 = -1e30f, l0 = 0.f, l1 = 0.f;

    for (int kb = 0; kb < 16; kb++) {
        __syncthreads();
        #pragma unroll
        for (int i = 0; i < 2; i++) {
            int f = i * 256 + tid, row = f >> 3, q = f & 7;
            sts_q40(Ks, row, q, *(const uint4*)(Kg + (size_t)(kb * 64 + row) * 3 * D_MODEL + q * 8));
            sts_q40(Vs, row, q, *(const uint4*)(Vt + (size_t)row * SEQ + kb * 64 + q * 8));
        }
        __syncthreads();

        float sacc[8][4];
        #pragma unroll
        for (int ni = 0; ni < 8; ni++)
            #pragma unroll
            for (int c = 0; c < 4; c++) sacc[ni][c] = 0.f;
        int co = 2 * (lane & 3);
        #pragma unroll
        for (int kk = 0; kk < 4; kk++) {
            #pragma unroll
            for (int ni = 0; ni < 8; ni++) {
                int rn = ni * 8 + (lane >> 2);
                uint2 bb = *(const uint2*)&Ks[rn * FROW + kk * 8 + co];
                uint32_t bfr[2] = { bb.x, bb.y };
                mma_f16(sacc[ni], qa[kk], bfr);
            }
        }

        float mx0 = -1e30f, mx1 = -1e30f;
        #pragma unroll
        for (int ni = 0; ni < 8; ni++) {
            mx0 = fmaxf(mx0, fmaxf(sacc[ni][0], sacc[ni][1]));
            mx1 = fmaxf(mx1, fmaxf(sacc[ni][2], sacc[ni][3]));
        }
        mx0 = fmaxf(mx0, __shfl_xor_sync(0xffffffff, mx0, 1));
        mx0 = fmaxf(mx0, __shfl_xor_sync(0xffffffff, mx0, 2));
        mx1 = fmaxf(mx1, __shfl_xor_sync(0xffffffff, mx1, 1));
        mx1 = fmaxf(mx1, __shfl_xor_sync(0xffffffff, mx1, 2));
        float nm0 = fmaxf(m0, mx0 * 0.125f);
        float nm1 = fmaxf(m1, mx1 * 0.125f);
        float a0 = __expf(m0 - nm0);
        float a1 = __expf(m1 - nm1);
        m0 = nm0; m1 = nm1;

        uint32_t pw0[8], pw1[8];
        float s0 = 0.f, s1 = 0.f;
        #pragma unroll
        for (int ni = 0; ni < 8; ni++) {
            float p0 = __expf(sacc[ni][0] * 0.125f - nm0);
            float p1 = __expf(sacc[ni][1] * 0.125f - nm0);
            float p2 = __expf(sacc[ni][2] * 0.125f - nm1);
            float p3 = __expf(sacc[ni][3] * 0.125f - nm1);
            s0 += p0 + p1; s1 += p2 + p3;
            pw0[ni] = packh2(p0, p1);
            pw1[ni] = packh2(p2, p3);
        }
        s0 += __shfl_xor_sync(0xffffffff, s0, 1);
        s0 += __shfl_xor_sync(0xffffffff, s0, 2);
        s1 += __shfl_xor_sync(0xffffffff, s1, 1);
        s1 += __shfl_xor_sync(0xffffffff, s1, 2);
        l0 = l0 * a0 + s0;
        l1 = l1 * a1 + s1;
        #pragma unroll
        for (int ni = 0; ni < 8; ni++) {
            oacc[ni][0] *= a0; oacc[ni][1] *= a0;
            oacc[ni][2] *= a1; oacc[ni][3] *= a1;
        }

        #pragma unroll
        for (int kp = 0; kp < 4; kp++) {
            uint32_t pa[4] = { pw0[2 * kp], pw1[2 * kp], pw0[2 * kp + 1], pw1[2 * kp + 1] };
            #pragma unroll
            for (int ni = 0; ni < 8; ni++) {
                int rn = ni * 8 + (lane >> 2);
                uint2 bb = *(const uint2*)&Vs[rn * FROW + kp * 8 + co];
                uint32_t bfr[2] = { bb.x, bb.y };
                mma_f16(oacc[ni], pa, bfr);
            }
        }
    }

    float i0 = 1.0f / l0, i1 = 1.0f / l1;
    int r = warp * 16 + (lane >> 2);
    #pragma unroll
    for (int ni = 0; ni < 8; ni++) {
        int col = ni * 8 + 2 * (lane & 3);
        store2(Og + (size_t)r * D_MODEL + col,       oacc[ni][0] * i0, oacc[ni][1] * i0);
        store2(Og + (size_t)(r + 8) * D_MODEL + col, oacc[ni][2] * i1, oacc[ni][3] * i1);
    }
}

// ============ fp16 GEMM: cp.async + swizzle + ldmatrix, 128x256 tile ============
// C[M,N] = scale * A[M,K] @ B[N,K]^T (+bias)(+gelu)(+res). KB=64, 4 stages.
#define NSTAGE 4
#define A_BYTES 16384
#define B_BYTES 32768
#define STAGEB (A_BYTES + B_BYTES)
#define SMEM2  (NSTAGE * STAGEB)

template <typename CT>
__global__ void __launch_bounds__(256)
mm2(const __half* __restrict__ Abase, const __half* __restrict__ Bbase,
    const float* __restrict__ bias, const float* __restrict__ resbase,
    CT* __restrict__ Cbase, int K, int lda, int ldb, int ldc,
    long sAb, long sBb, long sCb, float scale, int act) {
    extern __shared__ __align__(16) char smc[];
    uint32_t sb = smem_u32(smc);

    int tid = threadIdx.x, lane = tid & 31, warp = tid >> 5;
    int wy = warp & 1, wx = warp >> 1;           // 2 x 4 warp grid; warp tile 64x64
    int z = blockIdx.z;
    const __half* A = Abase + (size_t)z * sAb + (size_t)blockIdx.y * 128 * lda;
    const __half* B = Bbase + (size_t)z * sBb + (size_t)blockIdx.x * 256 * ldb;
    CT* C = Cbase + (size_t)z * sCb;
    const float* res = resbase ? resbase + (size_t)z * sCb : nullptr;
    int m0 = blockIdx.y * 128, n0 = blockIdx.x * 256;

    float acc[4][8][4];
    #pragma unroll
    for (int mi = 0; mi < 4; mi++)
        #pragma unroll
        for (int ni = 0; ni < 8; ni++)
            #pragma unroll
            for (int c = 0; c < 4; c++) acc[mi][ni][c] = 0.f;

    int lrow = tid >> 3;          // 0..31
    int lc   = tid & 7;           // chunk 0..7
    auto issue_stage = [&](int kb, int stage) {
        uint32_t as = sb + stage * STAGEB;
        uint32_t bs = as + A_BYTES;
        int koff = kb * 64 + lc * 8;
        #pragma unroll
        for (int i = 0; i < 4; i++) {
            int row = lrow + i * 32;
            cp16(as + row * 128 + ((lc ^ (row & 7)) * 16),
                 A + (size_t)row * lda + koff);
        }
        #pragma unroll
        for (int i = 0; i < 8; i++) {
            int row = lrow + i * 32;
            cp16(bs + row * 128 + ((lc ^ (row & 7)) * 16),
                 B + (size_t)row * ldb + koff);
        }
        asm volatile("cp.async.commit_group;");
    };

    int nkb = K >> 6;
    issue_stage(0, 0);
    issue_stage(1, 1);
    if (nkb > 2) issue_stage(2, 2);
    else asm volatile("cp.async.commit_group;");

    int arow = wy * 64 + (lane & 15);            // + mi*16
    int brow = wx * 64 + (lane & 15);            // + p*16
    int csel = lane >> 4;

    for (int kb = 0; kb < nkb; kb++) {
        asm volatile("cp.async.wait_group 2;");
        __syncthreads();
        int stage = kb % NSTAGE;
        if (kb + 3 < nkb) issue_stage(kb + 3, (kb + 3) % NSTAGE);
        else asm volatile("cp.async.commit_group;");

        uint32_t as = sb + stage * STAGEB;
        uint32_t bs = as + A_BYTES;
        #pragma unroll
        for (int kk = 0; kk < 4; kk++) {
            int ch = kk * 2 + csel;
            uint32_t afr[4][4], breg[4][4];
            #pragma unroll
            for (int mi = 0; mi < 4; mi++) {
                int r = arow + mi * 16;
                ldsm_x4(afr[mi][0], afr[mi][1], afr[mi][2], afr[mi][3],
                        as + r * 128 + ((ch ^ (r & 7)) * 16));
            }
            #pragma unroll
            for (int p = 0; p < 4; p++) {
                int r = brow + p * 16;
                ldsm_x4(breg[p][0], breg[p][1], breg[p][2], breg[p][3],
                        bs + r * 128 + ((ch ^ (r & 7)) * 16));
            }
            #pragma unroll
            for (int mi = 0; mi < 4; mi++)
                #pragma unroll
                for (int ni = 0; ni < 8; ni++) {
                    uint32_t bfr[2] = { breg[ni >> 1][ni & 1], breg[ni >> 1][(ni & 1) + 2] };
                    mma_f16(acc[mi][ni], afr[mi], bfr);
                }
        }
    }

    // epilogue
    #pragma unroll
    for (int mi = 0; mi < 4; mi++) {
        #pragma unroll
        for (int ni = 0; ni < 8; ni++) {
            int col = n0 + wx * 64 + ni * 8 + 2 * (lane & 3);
            #pragma unroll
            for (int half = 0; half < 2; half++) {
                int row = m0 + wy * 64 + mi * 16 + (lane >> 2) + half * 8;
                float c0 = acc[mi][ni][2 * half]     * scale;
                float c1 = acc[mi][ni][2 * half + 1] * scale;
                if (bias) { c0 += bias[col]; c1 += bias[col + 1]; }
                if (act == 1) { c0 = gelu_tanh(c0); c1 = gelu_tanh(c1); }
                if (res) {
                    float2 rv = *(const float2*)(res + (size_t)row * ldc + col);
                    c0 += rv.x; c1 += rv.y;
                }
                store2(C + (size_t)row * ldc + col, c0, c1);
            }
        }
    }
}

// ---------------- host launch ----------------
extern "C" void kernel_launch(void* const* d_in, const int* in_sizes, int n_in,
                              void* d_out, int out_size) {
    const float* x     = (const float*)d_in[0];
    const float* zin   = (const float*)d_in[1];
    const float* g1    = (const float*)d_in[2];
    const float* b1    = (const float*)d_in[3];
    const float* w_qkv = (const float*)d_in[4];
    const float* b_qkv = (const float*)d_in[5];
    const float* w_o   = (const float*)d_in[6];
    const float* b_o   = (const float*)d_in[7];
    const float* w_kv  = (const float*)d_in[8];
    const float* b_kv  = (const float*)d_in[9];
    const float* g2    = (const float*)d_in[10];
    const float* b2    = (const float*)d_in[11];
    const float* w_m1  = (const float*)d_in[12];
    const float* b_m1  = (const float*)d_in[13];
    const float* w_m2  = (const float*)d_in[14];
    const float* b_m2  = (const float*)d_in[15];
    float* out = (float*)d_out;

    __half *ln, *qkv, *kv, *attn, *q, *mlp, *p, *z16;
    __half *wtqkv, *wto, *wtkv, *wtm1, *wtm2, *vts, *vtc;
    float *cross, *xs;
    cudaGetSymbolAddress((void**)&ln,     h_ln);
    cudaGetSymbolAddress((void**)&qkv,    h_qkv);
    cudaGetSymbolAddress((void**)&kv,     h_kv);
    cudaGetSymbolAddress((void**)&attn,   h_attn);
    cudaGetSymbolAddress((void**)&q,      h_q);
    cudaGetSymbolAddress((void**)&cross,  g_cross);
    cudaGetSymbolAddress((void**)&mlp,    h_mlp);
    cudaGetSymbolAddress((void**)&xs,     g_xs);
    cudaGetSymbolAddress((void**)&p,      h_p);
    cudaGetSymbolAddress((void**)&z16,    h_z);
    cudaGetSymbolAddress((void**)&wtqkv,  h_wt_qkv);
    cudaGetSymbolAddress((void**)&wto,    h_wt_o);
    cudaGetSymbolAddress((void**)&wtkv,   h_wt_kv);
    cudaGetSymbolAddress((void**)&wtm1,   h_wt_m1);
    cudaGetSymbolAddress((void**)&wtm2,   h_wt_m2);
    cudaGetSymbolAddress((void**)&vts,    h_vt_self);
    cudaGetSymbolAddress((void**)&vtc,    h_vt_cross);

    cudaFuncSetAttribute(mm2<__half>, cudaFuncAttributeMaxDynamicSharedMemorySize, SMEM2);
    cudaFuncSetAttribute(mm2<float>,  cudaFuncAttributeMaxDynamicSharedMemorySize, SMEM2);

    // weight transposes + fp16 convert ([K][N] -> [N][K])
    transpose64<float><<<dim3(48, 16, 1), 256>>>(w_qkv, wtqkv, 3 * D_MODEL, D_MODEL, 0, 0, 0, 0, 1);
    transpose64<float><<<dim3(16, 16, 1), 256>>>(w_o, wto, D_MODEL, D_MODEL, 0, 0, 0, 0, 1);
    transpose64<float><<<dim3(32, 16, 1), 256>>>(w_kv, wtkv, 2 * D_MODEL, D_MODEL, 0, 0, 0, 0, 1);
    transpose64<float><<<dim3(64, 16, 1), 256>>>(w_m1, wtm1, HMLP, D_MODEL, 0, 0, 0, 0, 1);
    transpose64<float><<<dim3(16, 64, 1), 256>>>(w_m2, wtm2, D_MODEL, HMLP, 0, 0, 0, 0, 1);

    // 1) ln1(x) -> fp16, fused z -> fp16
    ln_kernel<<<ROWS, 256>>>(x, g1, b1, ln, zin, z16);

    // 2) qkv = ln1 @ w_qkv + b_qkv  (fp16 out)
    mm2<__half><<<dim3(12, 32, 1), 256, SMEM2>>>(
        ln, wtqkv, b_qkv, nullptr, qkv, D_MODEL, D_MODEL, D_MODEL, 3 * D_MODEL,
        0, 0, 0, 1.0f, 0);

    // transpose self V: per (b,h): [S,64] -> [64,S]
    transpose64<__half><<<dim3(1, 16, BATCH * NHEADS), 256>>>(
        qkv + 2 * D_MODEL, vts, 3 * D_MODEL, SEQ,
        (long)SEQ * 3 * D_MODEL, HDIM, (long)NHEADS * HDIM * SEQ, (long)HDIM * SEQ, NHEADS);

    // 3-5) fused flash self-attention -> attn (fp16)
    flash_self<<<dim3(8, BATCH * NHEADS), 256>>>(qkv, vts, attn);

    // 6) q = x + attn @ w_o + b_o  (fp16 out)
    mm2<__half><<<dim3(4, 32, 1), 256, SMEM2>>>(
        attn, wto, b_o, x, q, D_MODEL, D_MODEL, D_MODEL, D_MODEL,
        0, 0, 0, 1.0f, 0);

    // 7) kv = z @ w_kv + b_kv  (fp16 out)
    mm2<__half><<<dim3(8, 32, 1), 256, SMEM2>>>(
        z16, wtkv, b_kv, nullptr, kv, D_MODEL, D_MODEL, D_MODEL, 2 * D_MODEL,
        0, 0, 0, 1.0f, 0);

    // transpose cross V: per b: [S,D] -> [D,S]
    transpose64<__half><<<dim3(16, 16, BATCH), 256>>>(
        kv + D_MODEL, vtc, 2 * D_MODEL, SEQ,
        (long)SEQ * 2 * D_MODEL, 0, (long)D_MODEL * SEQ, 0, 1);

    // 8) cross scores = q @ k^T / 32  (fp32 out)
    mm2<float><<<dim3(4, 8, BATCH), 256, SMEM2>>>(
        q, kv, nullptr, nullptr, xs, D_MODEL, D_MODEL, 2 * D_MODEL, SEQ,
        (long)SEQ * D_MODEL, (long)SEQ * 2 * D_MODEL, (long)SEQ * SEQ, 0.03125f, 0);

    // 9) softmax fp32 -> fp16 P
    softmax_f2h<<<BATCH * SEQ, 256>>>(xs, p);

    // 10) cross P @ V -> cross (fp32)
    mm2<float><<<dim3(4, 8, BATCH), 256, SMEM2>>>(
        p, vtc, nullptr, nullptr, cross, SEQ, SEQ, SEQ, D_MODEL,
        (long)SEQ * SEQ, (long)D_MODEL * SEQ, (long)SEQ * D_MODEL, 1.0f, 0);

    // 11) ln2(cross) -> fp16
    ln_kernel<<<ROWS, 256>>>(cross, g2, b2, ln, nullptr, nullptr);

    // 12) mlp hidden = gelu(ln2 @ w_m1 + b_m1)  (fp16 out)
    mm2<__half><<<dim3(16, 32, 1), 256, SMEM2>>>(
        ln, wtm1, b_m1, nullptr, mlp, D_MODEL, D_MODEL, D_MODEL, HMLP,
        0, 0, 0, 1.0f, 1);

    // 13) out = cross + mlp @ w_m2 + b_m2  (fp32 out)
    mm2<float><<<dim3(4, 32, 1), 256, SMEM2>>>(
        mlp, wtm2, b_m2, cross, out, HMLP, HMLP, HMLP, D_MODEL,
        0, 0, 0, 1.0f, 0);
}

// round 11
// speedup vs baseline: 8.0433x; 1.0666x over previous
#include <cuda_runtime.h>
#include <cuda_fp16.h>
#include <math.h>
#include <stdint.h>

#define D_MODEL 1024
#define BATCH   4
#define SEQ     1024
#define NHEADS  16
#define HDIM    64
#define HMLP    4096
#define ROWS    (BATCH*SEQ)     // 4096

// ---------------- scratch (device globals; no allocs allowed) ----------------
__device__ __half h_ln   [ROWS * D_MODEL];
__device__ __half h_qkv  [ROWS * 3 * D_MODEL];
__device__ __half h_kv   [ROWS * 2 * D_MODEL];
__device__ __half h_attn [ROWS * D_MODEL];
__device__ __half h_q    [ROWS * D_MODEL];
__device__ float  g_cross[ROWS * D_MODEL];
__device__ __half h_mlp  [ROWS * HMLP];
__device__ float  g_xs   [(size_t)BATCH * SEQ * SEQ];
__device__ __half h_p    [(size_t)BATCH * SEQ * SEQ];
__device__ __half h_z    [ROWS * D_MODEL];
__device__ __half h_wt_qkv[3 * D_MODEL * D_MODEL];
__device__ __half h_wt_o  [D_MODEL * D_MODEL];
__device__ __half h_wt_kv [2 * D_MODEL * D_MODEL];
__device__ __half h_wt_m1 [HMLP * D_MODEL];
__device__ __half h_wt_m2 [D_MODEL * HMLP];
__device__ __half h_vt_self [BATCH * NHEADS * HDIM * SEQ];
__device__ __half h_vt_cross[(size_t)BATCH * D_MODEL * SEQ];

__device__ __forceinline__ float gelu_tanh(float c) {
    float t = 0.7978845608028654f * (c + 0.044715f * c * c * c);
    return 0.5f * c * (1.0f + tanhf(t));
}
__device__ __forceinline__ void mma_f16(float* d, const uint32_t* a, const uint32_t* b) {
    asm volatile("mma.sync.aligned.m16n8k16.row.col.f32.f16.f16.f32 "
        "{%0,%1,%2,%3}, {%4,%5,%6,%7}, {%8,%9}, {%0,%1,%2,%3};"
        : "+f"(d[0]), "+f"(d[1]), "+f"(d[2]), "+f"(d[3])
        : "r"(a[0]), "r"(a[1]), "r"(a[2]), "r"(a[3]), "r"(b[0]), "r"(b[1]));
}
__device__ __forceinline__ void ldsm_x4(uint32_t& r0, uint32_t& r1, uint32_t& r2, uint32_t& r3,
                                        uint32_t addr) {
    asm volatile("ldmatrix.sync.aligned.m8n8.x4.shared.b16 {%0,%1,%2,%3}, [%4];"
        : "=r"(r0), "=r"(r1), "=r"(r2), "=r"(r3) : "r"(addr));
}
__device__ __forceinline__ void cp16(uint32_t smem, const void* g) {
    asm volatile("cp.async.cg.shared.global [%0], [%1], 16;" :: "r"(smem), "l"(g));
}
__device__ __forceinline__ uint32_t smem_u32(const void* p) {
    return (uint32_t)__cvta_generic_to_shared(p);
}
__device__ __forceinline__ void store2(__half* p, float a, float b) {
    *(__half2*)p = __floats2half2_rn(a, b);
}
__device__ __forceinline__ void store2(float* p, float a, float b) {
    float2 v; v.x = a; v.y = b; *(float2*)p = v;
}
__device__ __forceinline__ uint32_t packh2(float a, float b) {
    __half2 h = __floats2half2_rn(a, b);
    return *(uint32_t*)&h;
}

// ---------------- layernorm (fp32 in -> fp16 out) + optional z convert --------
__global__ void ln_kernel(const float* __restrict__ x, const float* __restrict__ g,
                          const float* __restrict__ b, __half* __restrict__ out,
                          const float* __restrict__ zsrc, __half* __restrict__ zdst) {
    int row = blockIdx.x;
    const float* xr = x + (size_t)row * D_MODEL;
    __half* orow = out + (size_t)row * D_MODEL;
    int tid = threadIdx.x;
    float s = 0.f, s2 = 0.f;
    for (int i = tid; i < D_MODEL; i += 256) {
        float v = xr[i]; s += v; s2 += v * v;
    }
    if (zsrc) {
        const float* zr = zsrc + (size_t)row * D_MODEL;
        __half* zo = zdst + (size_t)row * D_MODEL;
        float4 a = *(const float4*)(zr + tid * 4);
        __half2 h[2];
        h[0] = __floats2half2_rn(a.x, a.y); h[1] = __floats2half2_rn(a.z, a.w);
        *(uint2*)(zo + tid * 4) = *(uint2*)h;
    }
    __shared__ float red[256], red2[256];
    red[tid] = s; red2[tid] = s2; __syncthreads();
    for (int o = 128; o > 0; o >>= 1) {
        if (tid < o) { red[tid] += red[tid + o]; red2[tid] += red2[tid + o]; }
        __syncthreads();
    }
    float mu  = red[0]  * (1.0f / D_MODEL);
    float var = red2[0] * (1.0f / D_MODEL) - mu * mu;
    float inv = rsqrtf(var + 1e-5f);
    for (int i = tid; i < D_MODEL; i += 512) {
        float v0 = (xr[i] - mu) * inv * g[i] + b[i];
        float v1 = (xr[i + 256] - mu) * inv * g[i + 256] + b[i + 256];
        orow[i] = __float2half(v0);
        orow[i + 256] = __float2half(v1);
    }
}

// ---------------- softmax fp32 in -> fp16 out (cross) ----------------
__global__ void softmax_f2h(const float* __restrict__ S, __half* __restrict__ P) {
    const float* row = S + (size_t)blockIdx.x * 1024;
    __half* prow = P + (size_t)blockIdx.x * 1024;
    int tid = threadIdx.x;
    float4 v = *(const float4*)(row + tid * 4);
    float mx = fmaxf(fmaxf(v.x, v.y), fmaxf(v.z, v.w));
    __shared__ float red[32];
    for (int o = 16; o > 0; o >>= 1) mx = fmaxf(mx, __shfl_xor_sync(0xffffffff, mx, o));
    if ((tid & 31) == 0) red[tid >> 5] = mx;
    __syncthreads();
    if (tid < 32) {
        float m = (tid < 8) ? red[tid] : -1e30f;
        for (int o = 4; o > 0; o >>= 1) m = fmaxf(m, __shfl_xor_sync(0xffffffff, m, o));
        red[0] = m;
    }
    __syncthreads();
    mx = red[0];
    v.x = expf(v.x - mx); v.y = expf(v.y - mx); v.z = expf(v.z - mx); v.w = expf(v.w - mx);
    float s = v.x + v.y + v.z + v.w;
    for (int o = 16; o > 0; o >>= 1) s += __shfl_xor_sync(0xffffffff, s, o);
    __syncthreads();
    if ((tid & 31) == 0) red[tid >> 5] = s;
    __syncthreads();
    if (tid < 32) {
        float t = (tid < 8) ? red[tid] : 0.f;
        for (int o = 4; o > 0; o >>= 1) t += __shfl_xor_sync(0xffffffff, t, o);
        red[0] = t;
    }
    __syncthreads();
    float inv = 1.0f / red[0];
    __half2 h2[2];
    h2[0] = __floats2half2_rn(v.x * inv, v.y * inv);
    h2[1] = __floats2half2_rn(v.z * inv, v.w * inv);
    *(uint2*)(prow + tid * 4) = *(uint2*)h2;
}

// ---------------- fast 64x64 batched transpose (TS in -> half out) ------------
template <typename TS>
__device__ __forceinline__ void ld4h(const TS* p, __half* v);
template <>
__device__ __forceinline__ void ld4h<float>(const float* p, __half* v) {
    float4 f = *(const float4*)p;
    v[0] = __float2half(f.x); v[1] = __float2half(f.y);
    v[2] = __float2half(f.z); v[3] = __float2half(f.w);
}
template <>
__device__ __forceinline__ void ld4h<__half>(const __half* p, __half* v) {
    uint2 u = *(const uint2*)p;
    *(uint32_t*)&v[0] = u.x; *(uint32_t*)&v[2] = u.y;
}

template <typename TS>
__global__ void __launch_bounds__(256)
transpose64(const TS* __restrict__ srcb, __half* __restrict__ dstb,
            int lds, int ldd, long sSb, long sSh, long sDb, long sDh, int nh) {
    __shared__ __half tile[64][66];
    int z = blockIdx.z, b = z / nh, h = z - b * nh;
    const TS* src = srcb + (size_t)b * sSb + (size_t)h * sSh;
    __half* dst = dstb + (size_t)b * sDb + (size_t)h * sDh;
    int x0 = blockIdx.x * 64;
    int y0 = blockIdx.y * 64;
    int tx = threadIdx.x & 15, ty = threadIdx.x >> 4;
    #pragma unroll
    for (int i = 0; i < 4; i++) {
        int row = y0 + ty + i * 16;
        __half v[4];
        ld4h<TS>(src + (size_t)row * lds + x0 + tx * 4, v);
        tile[tx * 4 + 0][ty + i * 16] = v[0];
        tile[tx * 4 + 1][ty + i * 16] = v[1];
        tile[tx * 4 + 2][ty + i * 16] = v[2];
        tile[tx * 4 + 3][ty + i * 16] = v[3];
    }
    __syncthreads();
    #pragma unroll
    for (int i = 0; i < 4; i++) {
        int drow = x0 + ty + i * 16;
        __half2 p0, p1;
        p0.x = tile[ty + i * 16][tx * 4 + 0]; p0.y = tile[ty + i * 16][tx * 4 + 1];
        p1.x = tile[ty + i * 16][tx * 4 + 2]; p1.y = tile[ty + i * 16][tx * 4 + 3];
        uint2 o; o.x = *(uint32_t*)&p0; o.y = *(uint32_t*)&p1;
        *(uint2*)(dst + (size_t)drow * ldd + y0 + tx * 4) = o;
    }
}

// ================= flash self-attention: ping-pong K/V, 1 sync/iter =========
#define FROW 40
#define FQ_W   (128 * FROW)          // 5120 words
#define FT_W   (64 * FROW)           // 2560 words
#define FLASH_SMEM ((FQ_W + 4 * FT_W) * 4)   // 61440 B

__device__ __forceinline__ void sts_q40(uint32_t* stg, int row, int q, uint4 v) {
    int g = q >> 1, hh = q & 1;
    uint32_t* p = stg + row * FROW + g * 8 + hh;
    p[0] = v.x; p[2] = v.y; p[4] = v.z; p[6] = v.w;
}

__global__ void __launch_bounds__(256)
flash_self(const __half* __restrict__ qkvg, const __half* __restrict__ vtsg,
           __half* __restrict__ attng) {
    extern __shared__ uint32_t fsm[];
    uint32_t* Qs = fsm;
    uint32_t* Kb[2] = { fsm + FQ_W,            fsm + FQ_W + 2 * FT_W };
    uint32_t* Vb[2] = { fsm + FQ_W + FT_W,     fsm + FQ_W + 3 * FT_W };

    int tid = threadIdx.x, lane = tid & 31, warp = tid >> 5;
    int bh = blockIdx.y, b = bh >> 4, h = bh & 15;
    const __half* Qg = qkvg + (size_t)b * SEQ * 3 * D_MODEL
                     + (size_t)blockIdx.x * 128 * 3 * D_MODEL + h * HDIM;
    const __half* Kg = qkvg + (size_t)b * SEQ * 3 * D_MODEL + D_MODEL + h * HDIM;
    const __half* Vt = vtsg + (size_t)bh * HDIM * SEQ;
    __half* Og = attng + (size_t)b * SEQ * D_MODEL
               + (size_t)blockIdx.x * 128 * D_MODEL + h * HDIM;

    int frow = tid >> 3, fq = tid & 7;   // per-thread row/chunk for 64-row tiles (2 iters)

    // prologue: Q tile + K/V tile 0
    #pragma unroll
    for (int i = 0; i < 4; i++) {
        int f = i * 256 + tid, row = f >> 3, q = f & 7;
        sts_q40(Qs, row, q, *(const uint4*)(Qg + (size_t)row * 3 * D_MODEL + q * 8));
    }
    #pragma unroll
    for (int i = 0; i < 2; i++) {
        int row = frow + i * 32;
        sts_q40(Kb[0], row, fq, *(const uint4*)(Kg + (size_t)row * 3 * D_MODEL + fq * 8));
        sts_q40(Vb[0], row, fq, *(const uint4*)(Vt + (size_t)row * SEQ + fq * 8));
    }
    __syncthreads();

    uint32_t qa[4][4];
    {
        int r = warp * 16 + (lane >> 2);
        int co = 2 * (lane & 3);
        #pragma unroll
        for (int kk = 0; kk < 4; kk++) {
            uint2 lo = *(const uint2*)&Qs[r * FROW + kk * 8 + co];
            uint2 hi = *(const uint2*)&Qs[(r + 8) * FROW + kk * 8 + co];
            qa[kk][0] = lo.x; qa[kk][1] = hi.x; qa[kk][2] = lo.y; qa[kk][3] = hi.y;
        }
    }

    float oacc[8][4];
    #pragma unroll
    for (int ni = 0; ni < 8; ni++)
        #pragma unroll
        for (int c = 0; c < 4; c++) oacc[ni][c] = 0.f;
    float m0 = -1e30f, m1 = -1e30f, l0 = 0.f, l1 = 0.f;

    for (int kb = 0; kb < 16; kb++) {
        // prefetch next K/V tile into registers (latency hidden under compute)
        uint4 kr[2], vr[2];
        if (kb < 15) {
            #pragma unroll
            for (int i = 0; i < 2; i++) {
                int row = frow + i * 32;
                kr[i] = *(const uint4*)(Kg + (size_t)((kb + 1) * 64 + row) * 3 * D_MODEL + fq * 8);
                vr[i] = *(const uint4*)(Vt + (size_t)row * SEQ + (kb + 1) * 64 + fq * 8);
            }
        }
        const uint32_t* Ks = Kb[kb & 1];
        const uint32_t* Vs = Vb[kb & 1];

        // S = Q @ K^T
        float sacc[8][4];
        #pragma unroll
        for (int ni = 0; ni < 8; ni++)
            #pragma unroll
            for (int c = 0; c < 4; c++) sacc[ni][c] = 0.f;
        int co = 2 * (lane & 3);
        #pragma unroll
        for (int kk = 0; kk < 4; kk++) {
            #pragma unroll
            for (int ni = 0; ni < 8; ni++) {
                int rn = ni * 8 + (lane >> 2);
                uint2 bb = *(const uint2*)&Ks[rn * FROW + kk * 8 + co];
                uint32_t bfr[2] = { bb.x, bb.y };
                mma_f16(sacc[ni], qa[kk], bfr);
            }
        }

        // online softmax
        float mx0 = -1e30f, mx1 = -1e30f;
        #pragma unroll
        for (int ni = 0; ni < 8; ni++) {
            mx0 = fmaxf(mx0, fmaxf(sacc[ni][0], sacc[ni][1]));
            mx1 = fmaxf(mx1, fmaxf(sacc[ni][2], sacc[ni][3]));
        }
        mx0 = fmaxf(mx0, __shfl_xor_sync(0xffffffff, mx0, 1));
        mx0 = fmaxf(mx0, __shfl_xor_sync(0xffffffff, mx0, 2));
        mx1 = fmaxf(mx1, __shfl_xor_sync(0xffffffff, mx1, 1));
        mx1 = fmaxf(mx1, __shfl_xor_sync(0xffffffff, mx1, 2));
        float nm0 = fmaxf(m0, mx0 * 0.125f);
        float nm1 = fmaxf(m1, mx1 * 0.125f);
        float a0 = __expf(m0 - nm0);
        float a1 = __expf(m1 - nm1);
        m0 = nm0; m1 = nm1;

        uint32_t pw0[8], pw1[8];
        float s0 = 0.f, s1 = 0.f;
        #pragma unroll
        for (int ni = 0; ni < 8; ni++) {
            float p0 = __expf(sacc[ni][0] * 0.125f - nm0);
            float p1 = __expf(sacc[ni][1] * 0.125f - nm0);
            float p2 = __expf(sacc[ni][2] * 0.125f - nm1);
            float p3 = __expf(sacc[ni][3] * 0.125f - nm1);
            s0 += p0 + p1; s1 += p2 + p3;
            pw0[ni] = packh2(p0, p1);
            pw1[ni] = packh2(p2, p3);
        }
        s0 += __shfl_xor_sync(0xffffffff, s0, 1);
        s0 += __shfl_xor_sync(0xffffffff, s0, 2);
        s1 += __shfl_xor_sync(0xffffffff, s1, 1);
        s1 += __shfl_xor_sync(0xffffffff, s1, 2);
        l0 = l0 * a0 + s0;
        l1 = l1 * a1 + s1;
        #pragma unroll
        for (int ni = 0; ni < 8; ni++) {
            oacc[ni][0] *= a0; oacc[ni][1] *= a0;
            oacc[ni][2] *= a1; oacc[ni][3] *= a1;
        }

        // O += P @ V
        #pragma unroll
        for (int kp = 0; kp < 4; kp++) {
            uint32_t pa[4] = { pw0[2 * kp], pw1[2 * kp], pw0[2 * kp + 1], pw1[2 * kp + 1] };
            #pragma unroll
            for (int ni = 0; ni < 8; ni++) {
                int rn = ni * 8 + (lane >> 2);
                uint2 bb = *(const uint2*)&Vs[rn * FROW + kp * 8 + co];
                uint32_t bfr[2] = { bb.x, bb.y };
                mma_f16(oacc[ni], pa, bfr);
            }
        }

        // store prefetched tiles into the other buffer; single barrier per iter
        if (kb < 15) {
            int nxt = (kb + 1) & 1;
            #pragma unroll
            for (int i = 0; i < 2; i++) {
                int row = frow + i * 32;
                sts_q40(Kb[nxt], row, fq, kr[i]);
                sts_q40(Vb[nxt], row, fq, vr[i]);
            }
            __syncthreads();
        }
    }

    float i0 = 1.0f / l0, i1 = 1.0f / l1;
    int r = warp * 16 + (lane >> 2);
    #pragma unroll
    for (int ni = 0; ni < 8; ni++) {
        int col = ni * 8 + 2 * (lane & 3);
        store2(Og + (size_t)r * D_MODEL + col,       oacc[ni][0] * i0, oacc[ni][1] * i0);
        store2(Og + (size_t)(r + 8) * D_MODEL + col, oacc[ni][2] * i1, oacc[ni][3] * i1);
    }
}

// ============ fp16 GEMM: cp.async + swizzle + ldmatrix, 128x256 tile ============
#define NSTAGE 4
#define A_BYTES 16384
#define B_BYTES 32768
#define STAGEB (A_BYTES + B_BYTES)
#define SMEM2  (NSTAGE * STAGEB)

template <typename CT>
__global__ void __launch_bounds__(256)
mm2(const __half* __restrict__ Abase, const __half* __restrict__ Bbase,
    const float* __restrict__ bias, const float* __restrict__ resbase,
    CT* __restrict__ Cbase, int K, int lda, int ldb, int ldc,
    long sAb, long sBb, long sCb, float scale, int act) {
    extern __shared__ __align__(16) char smc[];
    uint32_t sb = smem_u32(smc);

    int tid = threadIdx.x, lane = tid & 31, warp = tid >> 5;
    int wy = warp & 1, wx = warp >> 1;
    int z = blockIdx.z;
    const __half* A = Abase + (size_t)z * sAb + (size_t)blockIdx.y * 128 * lda;
    const __half* B = Bbase + (size_t)z * sBb + (size_t)blockIdx.x * 256 * ldb;
    CT* C = Cbase + (size_t)z * sCb;
    const float* res = resbase ? resbase + (size_t)z * sCb : nullptr;
    int m0 = blockIdx.y * 128, n0 = blockIdx.x * 256;

    float acc[4][8][4];
    #pragma unroll
    for (int mi = 0; mi < 4; mi++)
        #pragma unroll
        for (int ni = 0; ni < 8; ni++)
            #pragma unroll
            for (int c = 0; c < 4; c++) acc[mi][ni][c] = 0.f;

    int lrow = tid >> 3;
    int lc   = tid & 7;
    auto issue_stage = [&](int kb, int stage) {
        uint32_t as = sb + stage * STAGEB;
        uint32_t bs = as + A_BYTES;
        int koff = kb * 64 + lc * 8;
        #pragma unroll
        for (int i = 0; i < 4; i++) {
            int row = lrow + i * 32;
            cp16(as + row * 128 + ((lc ^ (row & 7)) * 16),
                 A + (size_t)row * lda + koff);
        }
        #pragma unroll
        for (int i = 0; i < 8; i++) {
            int row = lrow + i * 32;
            cp16(bs + row * 128 + ((lc ^ (row & 7)) * 16),
                 B + (size_t)row * ldb + koff);
        }
        asm volatile("cp.async.commit_group;");
    };

    int nkb = K >> 6;
    issue_stage(0, 0);
    issue_stage(1, 1);
    if (nkb > 2) issue_stage(2, 2);
    else asm volatile("cp.async.commit_group;");

    int arow = wy * 64 + (lane & 15);
    int brow = wx * 64 + (lane & 15);
    int csel = lane >> 4;

    for (int kb = 0; kb < nkb; kb++) {
        asm volatile("cp.async.wait_group 2;");
        __syncthreads();
        int stage = kb % NSTAGE;
        if (kb + 3 < nkb) issue_stage(kb + 3, (kb + 3) % NSTAGE);
        else asm volatile("cp.async.commit_group;");

        uint32_t as = sb + stage * STAGEB;
        uint32_t bs = as + A_BYTES;
        #pragma unroll
        for (int kk = 0; kk < 4; kk++) {
            int ch = kk * 2 + csel;
            uint32_t afr[4][4], breg[4][4];
            #pragma unroll
            for (int mi = 0; mi < 4; mi++) {
                int r = arow + mi * 16;
                ldsm_x4(afr[mi][0], afr[mi][1], afr[mi][2], afr[mi][3],
                        as + r * 128 + ((ch ^ (r & 7)) * 16));
            }
            #pragma unroll
            for (int p = 0; p < 4; p++) {
                int r = brow + p * 16;
                ldsm_x4(breg[p][0], breg[p][1], breg[p][2], breg[p][3],
                        bs + r * 128 + ((ch ^ (r & 7)) * 16));
            }
            #pragma unroll
            for (int mi = 0; mi < 4; mi++)
                #pragma unroll
                for (int ni = 0; ni < 8; ni++) {
                    uint32_t bfr[2] = { breg[ni >> 1][ni & 1], breg[ni >> 1][(ni & 1) + 2] };
                    mma_f16(acc[mi][ni], afr[mi], bfr);
                }
        }
    }

    #pragma unroll
    for (int mi = 0; mi < 4; mi++) {
        #pragma unroll
        for (int ni = 0; ni < 8; ni++) {
            int col = n0 + wx * 64 + ni * 8 + 2 * (lane & 3);
            #pragma unroll
            for (int half = 0; half < 2; half++) {
                int row = m0 + wy * 64 + mi * 16 + (lane >> 2) + half * 8;
                float c0 = acc[mi][ni][2 * half]     * scale;
                float c1 = acc[mi][ni][2 * half + 1] * scale;
                if (bias) { c0 += bias[col]; c1 += bias[col + 1]; }
                if (act == 1) { c0 = gelu_tanh(c0); c1 = gelu_tanh(c1); }
                if (res) {
                    float2 rv = *(const float2*)(res + (size_t)row * ldc + col);
                    c0 += rv.x; c1 += rv.y;
                }
                store2(C + (size_t)row * ldc + col, c0, c1);
            }
        }
    }
}

// ---------------- host launch ----------------
extern "C" void kernel_launch(void* const* d_in, const int* in_sizes, int n_in,
                              void* d_out, int out_size) {
    const float* x     = (const float*)d_in[0];
    const float* zin   = (const float*)d_in[1];
    const float* g1    = (const float*)d_in[2];
    const float* b1    = (const float*)d_in[3];
    const float* w_qkv = (const float*)d_in[4];
    const float* b_qkv = (const float*)d_in[5];
    const float* w_o   = (const float*)d_in[6];
    const float* b_o   = (const float*)d_in[7];
    const float* w_kv  = (const float*)d_in[8];
    const float* b_kv  = (const float*)d_in[9];
    const float* g2    = (const float*)d_in[10];
    const float* b2    = (const float*)d_in[11];
    const float* w_m1  = (const float*)d_in[12];
    const float* b_m1  = (const float*)d_in[13];
    const float* w_m2  = (const float*)d_in[14];
    const float* b_m2  = (const float*)d_in[15];
    float* out = (float*)d_out;

    __half *ln, *qkv, *kv, *attn, *q, *mlp, *p, *z16;
    __half *wtqkv, *wto, *wtkv, *wtm1, *wtm2, *vts, *vtc;
    float *cross, *xs;
    cudaGetSymbolAddress((void**)&ln,     h_ln);
    cudaGetSymbolAddress((void**)&qkv,    h_qkv);
    cudaGetSymbolAddress((void**)&kv,     h_kv);
    cudaGetSymbolAddress((void**)&attn,   h_attn);
    cudaGetSymbolAddress((void**)&q,      h_q);
    cudaGetSymbolAddress((void**)&cross,  g_cross);
    cudaGetSymbolAddress((void**)&mlp,    h_mlp);
    cudaGetSymbolAddress((void**)&xs,     g_xs);
    cudaGetSymbolAddress((void**)&p,      h_p);
    cudaGetSymbolAddress((void**)&z16,    h_z);
    cudaGetSymbolAddress((void**)&wtqkv,  h_wt_qkv);
    cudaGetSymbolAddress((void**)&wto,    h_wt_o);
    cudaGetSymbolAddress((void**)&wtkv,   h_wt_kv);
    cudaGetSymbolAddress((void**)&wtm1,   h_wt_m1);
    cudaGetSymbolAddress((void**)&wtm2,   h_wt_m2);
    cudaGetSymbolAddress((void**)&vts,    h_vt_self);
    cudaGetSymbolAddress((void**)&vtc,    h_vt_cross);

    cudaFuncSetAttribute(mm2<__half>, cudaFuncAttributeMaxDynamicSharedMemorySize, SMEM2);
    cudaFuncSetAttribute(mm2<float>,  cudaFuncAttributeMaxDynamicSharedMemorySize, SMEM2);
    cudaFuncSetAttribute(flash_self,  cudaFuncAttributeMaxDynamicSharedMemorySize, FLASH_SMEM);

    // side stream + events for overlapping the independent kv/weight chain.
    // Created per call; kernel_launch runs only twice (correctness + capture),
    // and graph replays re-run the captured graph, not this function.
    cudaStream_t s2;
    cudaStreamCreateWithFlags(&s2, cudaStreamNonBlocking);
    cudaEvent_t evZ, evKV, evW;
    cudaEventCreateWithFlags(&evZ,  cudaEventDisableTiming);
    cudaEventCreateWithFlags(&evKV, cudaEventDisableTiming);
    cudaEventCreateWithFlags(&evW,  cudaEventDisableTiming);

    // ---- main stream: prerequisites for the q-chain ----
    transpose64<float><<<dim3(48, 16, 1), 256>>>(w_qkv, wtqkv, 3 * D_MODEL, D_MODEL, 0, 0, 0, 0, 1);
    transpose64<float><<<dim3(16, 16, 1), 256>>>(w_o, wto, D_MODEL, D_MODEL, 0, 0, 0, 0, 1);

    // ln1(x) -> fp16, fused z -> fp16
    ln_kernel<<<ROWS, 256>>>(x, g1, b1, ln, zin, z16);
    cudaEventRecord(evZ, 0);

    // ---- side stream: kv chain + mlp weight transposes ----
    cudaStreamWaitEvent(s2, evZ, 0);
    transpose64<float><<<dim3(32, 16, 1), 256, 0, s2>>>(w_kv, wtkv, 2 * D_MODEL, D_MODEL, 0, 0, 0, 0, 1);
    mm2<__half><<<dim3(8, 32, 1), 256, SMEM2, s2>>>(
        z16, wtkv, b_kv, nullptr, kv, D_MODEL, D_MODEL, D_MODEL, 2 * D_MODEL,
        0, 0, 0, 1.0f, 0);
    transpose64<__half><<<dim3(16, 16, BATCH), 256, 0, s2>>>(
        kv + D_MODEL, vtc, 2 * D_MODEL, SEQ,
        (long)SEQ * 2 * D_MODEL, 0, (long)D_MODEL * SEQ, 0, 1);
    cudaEventRecord(evKV, s2);
    transpose64<float><<<dim3(64, 16, 1), 256, 0, s2>>>(w_m1, wtm1, HMLP, D_MODEL, 0, 0, 0, 0, 1);
    transpose64<float><<<dim3(16, 64, 1), 256, 0, s2>>>(w_m2, wtm2, D_MODEL, HMLP, 0, 0, 0, 0, 1);
    cudaEventRecord(evW, s2);

    // ---- main stream: q chain ----
    mm2<__half><<<dim3(12, 32, 1), 256, SMEM2>>>(
        ln, wtqkv, b_qkv, nullptr, qkv, D_MODEL, D_MODEL, D_MODEL, 3 * D_MODEL,
        0, 0, 0, 1.0f, 0);

    transpose64<__half><<<dim3(1, 16, BATCH * NHEADS), 256>>>(
        qkv + 2 * D_MODEL, vts, 3 * D_MODEL, SEQ,
        (long)SEQ * 3 * D_MODEL, HDIM, (long)NHEADS * HDIM * SEQ, (long)HDIM * SEQ, NHEADS);

    flash_self<<<dim3(8, BATCH * NHEADS), 256, FLASH_SMEM>>>(qkv, vts, attn);

    mm2<__half><<<dim3(4, 32, 1), 256, SMEM2>>>(
        attn, wto, b_o, x, q, D_MODEL, D_MODEL, D_MODEL, D_MODEL,
        0, 0, 0, 1.0f, 0);

    // join: need kv + vtc
    cudaStreamWaitEvent(0, evKV, 0);

    // cross scores = q @ k^T / 32  (fp32 out)
    mm2<float><<<dim3(4, 8, BATCH), 256, SMEM2>>>(
        q, kv, nullptr, nullptr, xs, D_MODEL, D_MODEL, 2 * D_MODEL, SEQ,
        (long)SEQ * D_MODEL, (long)SEQ * 2 * D_MODEL, (long)SEQ * SEQ, 0.03125f, 0);

    softmax_f2h<<<BATCH * SEQ, 256>>>(xs, p);

    mm2<float><<<dim3(4, 8, BATCH), 256, SMEM2>>>(
        p, vtc, nullptr, nullptr, cross, SEQ, SEQ, SEQ, D_MODEL,
        (long)SEQ * SEQ, (long)D_MODEL * SEQ, (long)SEQ * D_MODEL, 1.0f, 0);

    ln_kernel<<<ROWS, 256>>>(cross, g2, b2, ln, nullptr, nullptr);

    // join: need mlp weights
    cudaStreamWaitEvent(0, evW, 0);

    mm2<__half><<<dim3(16, 32, 1), 256, SMEM2>>>(
        ln, wtm1, b_m1, nullptr, mlp, D_MODEL, D_MODEL, D_MODEL, HMLP,
        0, 0, 0, 1.0f, 1);

    mm2<float><<<dim3(4, 32, 1), 256, SMEM2>>>(
        mlp, wtm2, b_m2, cross, out, HMLP, HMLP, HMLP, D_MODEL,
        0, 0, 0, 1.0f, 0);
}

// round 13
// speedup vs baseline: 8.4934x; 1.0560x over previous
#include <cuda_runtime.h>
#include <cuda_fp16.h>
#include <math.h>
#include <stdint.h>

#define D_MODEL 1024
#define BATCH   4
#define SEQ     1024
#define NHEADS  16
#define HDIM    64
#define HMLP    4096
#define ROWS    (BATCH*SEQ)     // 4096

// ---------------- scratch (device globals; no allocs allowed) ----------------
__device__ __half h_ln   [ROWS * D_MODEL];
__device__ __half h_qkv  [ROWS * 3 * D_MODEL];
__device__ __half h_kv   [ROWS * 2 * D_MODEL];
__device__ __half h_attn [ROWS * D_MODEL];
__device__ __half h_q    [ROWS * D_MODEL];
__device__ float  g_cross[ROWS * D_MODEL];
__device__ __half h_mlp  [ROWS * HMLP];
__device__ float  g_xs   [(size_t)BATCH * SEQ * SEQ];
__device__ __half h_p    [(size_t)BATCH * SEQ * SEQ];
__device__ __half h_z    [ROWS * D_MODEL];
__device__ __half h_wt_qkv[3 * D_MODEL * D_MODEL];
__device__ __half h_wt_o  [D_MODEL * D_MODEL];
__device__ __half h_wt_kv [2 * D_MODEL * D_MODEL];
__device__ __half h_wt_m1 [HMLP * D_MODEL];
__device__ __half h_wt_m2 [D_MODEL * HMLP];
__device__ __half h_vt_self [BATCH * NHEADS * HDIM * SEQ];
__device__ __half h_vt_cross[(size_t)BATCH * D_MODEL * SEQ];

__device__ __forceinline__ float gelu_tanh(float c) {
    float t = 0.7978845608028654f * (c + 0.044715f * c * c * c);
    return 0.5f * c * (1.0f + tanhf(t));
}
__device__ __forceinline__ void mma_f16(float* d, const uint32_t* a, const uint32_t* b) {
    asm volatile("mma.sync.aligned.m16n8k16.row.col.f32.f16.f16.f32 "
        "{%0,%1,%2,%3}, {%4,%5,%6,%7}, {%8,%9}, {%0,%1,%2,%3};"
        : "+f"(d[0]), "+f"(d[1]), "+f"(d[2]), "+f"(d[3])
        : "r"(a[0]), "r"(a[1]), "r"(a[2]), "r"(a[3]), "r"(b[0]), "r"(b[1]));
}
__device__ __forceinline__ void ldsm_x4(uint32_t& r0, uint32_t& r1, uint32_t& r2, uint32_t& r3,
                                        uint32_t addr) {
    asm volatile("ldmatrix.sync.aligned.m8n8.x4.shared.b16 {%0,%1,%2,%3}, [%4];"
        : "=r"(r0), "=r"(r1), "=r"(r2), "=r"(r3) : "r"(addr));
}
__device__ __forceinline__ void cp16(uint32_t smem, const void* g) {
    asm volatile("cp.async.cg.shared.global [%0], [%1], 16;" :: "r"(smem), "l"(g));
}
__device__ __forceinline__ uint32_t smem_u32(const void* p) {
    return (uint32_t)__cvta_generic_to_shared(p);
}
__device__ __forceinline__ void store2(__half* p, float a, float b) {
    *(__half2*)p = __floats2half2_rn(a, b);
}
__device__ __forceinline__ void store2(float* p, float a, float b) {
    float2 v; v.x = a; v.y = b; *(float2*)p = v;
}
__device__ __forceinline__ uint32_t packh2(float a, float b) {
    __half2 h = __floats2half2_rn(a, b);
    return *(uint32_t*)&h;
}

// ------------- single-pass layernorm (fp32 in -> fp16 out) + optional z cvt ----
__global__ void ln_kernel(const float* __restrict__ x, const float* __restrict__ g,
                          const float* __restrict__ b, __half* __restrict__ out,
                          const float* __restrict__ zsrc, __half* __restrict__ zdst) {
    int row = blockIdx.x;
    int tid = threadIdx.x;
    const float* xr = x + (size_t)row * D_MODEL;
    float4 v = *(const float4*)(xr + tid * 4);
    if (zsrc) {
        const float* zr = zsrc + (size_t)row * D_MODEL;
        __half* zo = zdst + (size_t)row * D_MODEL;
        float4 a = *(const float4*)(zr + tid * 4);
        __half2 h[2];
        h[0] = __floats2half2_rn(a.x, a.y); h[1] = __floats2half2_rn(a.z, a.w);
        *(uint2*)(zo + tid * 4) = *(uint2*)h;
    }
    float s  = v.x + v.y + v.z + v.w;
    float s2 = v.x * v.x + v.y * v.y + v.z * v.z + v.w * v.w;
    __shared__ float rs[8], rs2[8];
    for (int o = 16; o > 0; o >>= 1) {
        s  += __shfl_xor_sync(0xffffffff, s,  o);
        s2 += __shfl_xor_sync(0xffffffff, s2, o);
    }
    if ((tid & 31) == 0) { rs[tid >> 5] = s; rs2[tid >> 5] = s2; }
    __syncthreads();
    if (tid < 32) {
        float a  = (tid < 8) ? rs[tid]  : 0.f;
        float a2 = (tid < 8) ? rs2[tid] : 0.f;
        for (int o = 4; o > 0; o >>= 1) {
            a  += __shfl_xor_sync(0xffffffff, a,  o);
            a2 += __shfl_xor_sync(0xffffffff, a2, o);
        }
        rs[0] = a; rs2[0] = a2;
    }
    __syncthreads();
    float mu  = rs[0]  * (1.0f / D_MODEL);
    float var = rs2[0] * (1.0f / D_MODEL) - mu * mu;
    float inv = rsqrtf(var + 1e-5f);
    float4 gg = *(const float4*)(g + tid * 4);
    float4 bb = *(const float4*)(b + tid * 4);
    __half2 h[2];
    h[0] = __floats2half2_rn((v.x - mu) * inv * gg.x + bb.x,
                             (v.y - mu) * inv * gg.y + bb.y);
    h[1] = __floats2half2_rn((v.z - mu) * inv * gg.z + bb.z,
                             (v.w - mu) * inv * gg.w + bb.w);
    *(uint2*)(out + (size_t)row * D_MODEL + tid * 4) = *(uint2*)h;
}

// ---------------- softmax fp32 in -> fp16 out (cross) ----------------
__global__ void softmax_f2h(const float* __restrict__ S, __half* __restrict__ P) {
    const float* row = S + (size_t)blockIdx.x * 1024;
    __half* prow = P + (size_t)blockIdx.x * 1024;
    int tid = threadIdx.x;
    float4 v = *(const float4*)(row + tid * 4);
    float mx = fmaxf(fmaxf(v.x, v.y), fmaxf(v.z, v.w));
    __shared__ float red[32];
    for (int o = 16; o > 0; o >>= 1) mx = fmaxf(mx, __shfl_xor_sync(0xffffffff, mx, o));
    if ((tid & 31) == 0) red[tid >> 5] = mx;
    __syncthreads();
    if (tid < 32) {
        float m = (tid < 8) ? red[tid] : -1e30f;
        for (int o = 4; o > 0; o >>= 1) m = fmaxf(m, __shfl_xor_sync(0xffffffff, m, o));
        red[0] = m;
    }
    __syncthreads();
    mx = red[0];
    v.x = expf(v.x - mx); v.y = expf(v.y - mx); v.z = expf(v.z - mx); v.w = expf(v.w - mx);
    float s = v.x + v.y + v.z + v.w;
    for (int o = 16; o > 0; o >>= 1) s += __shfl_xor_sync(0xffffffff, s, o);
    __syncthreads();
    if ((tid & 31) == 0) red[tid >> 5] = s;
    __syncthreads();
    if (tid < 32) {
        float t = (tid < 8) ? red[tid] : 0.f;
        for (int o = 4; o > 0; o >>= 1) t += __shfl_xor_sync(0xffffffff, t, o);
        red[0] = t;
    }
    __syncthreads();
    float inv = 1.0f / red[0];
    __half2 h2[2];
    h2[0] = __floats2half2_rn(v.x * inv, v.y * inv);
    h2[1] = __floats2half2_rn(v.z * inv, v.w * inv);
    *(uint2*)(prow + tid * 4) = *(uint2*)h2;
}

// ---------------- fast 64x64 batched transpose (TS in -> half out) ------------
template <typename TS>
__device__ __forceinline__ void ld4h(const TS* p, __half* v);
template <>
__device__ __forceinline__ void ld4h<float>(const float* p, __half* v) {
    float4 f = *(const float4*)p;
    v[0] = __float2half(f.x); v[1] = __float2half(f.y);
    v[2] = __float2half(f.z); v[3] = __float2half(f.w);
}
template <>
__device__ __forceinline__ void ld4h<__half>(const __half* p, __half* v) {
    uint2 u = *(const uint2*)p;
    *(uint32_t*)&v[0] = u.x; *(uint32_t*)&v[2] = u.y;
}

template <typename TS>
__global__ void __launch_bounds__(256)
transpose64(const TS* __restrict__ srcb, __half* __restrict__ dstb,
            int lds, int ldd, long sSb, long sSh, long sDb, long sDh, int nh) {
    __shared__ __half tile[64][66];
    int z = blockIdx.z, b = z / nh, h = z - b * nh;
    const TS* src = srcb + (size_t)b * sSb + (size_t)h * sSh;
    __half* dst = dstb + (size_t)b * sDb + (size_t)h * sDh;
    int x0 = blockIdx.x * 64;
    int y0 = blockIdx.y * 64;
    int tx = threadIdx.x & 15, ty = threadIdx.x >> 4;
    #pragma unroll
    for (int i = 0; i < 4; i++) {
        int row = y0 + ty + i * 16;
        __half v[4];
        ld4h<TS>(src + (size_t)row * lds + x0 + tx * 4, v);
        tile[tx * 4 + 0][ty + i * 16] = v[0];
        tile[tx * 4 + 1][ty + i * 16] = v[1];
        tile[tx * 4 + 2][ty + i * 16] = v[2];
        tile[tx * 4 + 3][ty + i * 16] = v[3];
    }
    __syncthreads();
    #pragma unroll
    for (int i = 0; i < 4; i++) {
        int drow = x0 + ty + i * 16;
        __half2 p0, p1;
        p0.x = tile[ty + i * 16][tx * 4 + 0]; p0.y = tile[ty + i * 16][tx * 4 + 1];
        p1.x = tile[ty + i * 16][tx * 4 + 2]; p1.y = tile[ty + i * 16][tx * 4 + 3];
        uint2 o; o.x = *(uint32_t*)&p0; o.y = *(uint32_t*)&p1;
        *(uint2*)(dst + (size_t)drow * ldd + y0 + tx * 4) = o;
    }
}

// ========== flash self-attention v2: cp.async 3-stage ring + ldmatrix ==========
// Q tile 128x64h (16KB, swizzled), K/V tiles 64x64h (8KB each), 3 KV stages.
#define FLASH_SMEM (16384 + 3 * 16384)   // 65536 B

__global__ void __launch_bounds__(256)
flash_self(const __half* __restrict__ qkvg, const __half* __restrict__ vtsg,
           __half* __restrict__ attng) {
    extern __shared__ __align__(16) char fsmc[];
    uint32_t sq = smem_u32(fsmc);

    int tid = threadIdx.x, lane = tid & 31, warp = tid >> 5;
    int bh = blockIdx.y, b = bh >> 4, h = bh & 15;
    const __half* Qg = qkvg + (size_t)b * SEQ * 3 * D_MODEL
                     + (size_t)blockIdx.x * 128 * 3 * D_MODEL + h * HDIM;
    const __half* Kg = qkvg + (size_t)b * SEQ * 3 * D_MODEL + D_MODEL + h * HDIM;
    const __half* Vt = vtsg + (size_t)bh * HDIM * SEQ;
    __half* Og = attng + (size_t)b * SEQ * D_MODEL
               + (size_t)blockIdx.x * 128 * D_MODEL + h * HDIM;

    auto issue_kv = [&](int kb) {
        uint32_t base = sq + 16384 + (kb % 3) * 16384;
        #pragma unroll
        for (int i = 0; i < 2; i++) {
            int f = i * 256 + tid, row = f >> 3, ch = f & 7;
            uint32_t sw = (ch ^ (row & 7)) * 16;
            cp16(base + row * 128 + sw,
                 Kg + (size_t)(kb * 64 + row) * 3 * D_MODEL + ch * 8);
            cp16(base + 8192 + row * 128 + sw,
                 Vt + (size_t)row * SEQ + kb * 64 + ch * 8);
        }
        asm volatile("cp.async.commit_group;");
    };

    // prologue: Q + KV0 (group 0), KV1 (group 1)
    #pragma unroll
    for (int i = 0; i < 4; i++) {
        int f = i * 256 + tid, row = f >> 3, ch = f & 7;
        cp16(sq + row * 128 + ((ch ^ (row & 7)) * 16),
             Qg + (size_t)row * 3 * D_MODEL + ch * 8);
    }
    issue_kv(0);     // commits Q + KV0 together
    issue_kv(1);

    uint32_t qa[4][4];
    float oacc[8][4];
    #pragma unroll
    for (int ni = 0; ni < 8; ni++)
        #pragma unroll
        for (int c = 0; c < 4; c++) oacc[ni][c] = 0.f;
    float m0 = -1e30f, m1 = -1e30f, l0 = 0.f, l1 = 0.f;

    int frag_r = lane & 15;          // row within 16-row ldsm block
    int csel = lane >> 4;            // chunk half
    int sw7 = frag_r & 7;

    for (int kb = 0; kb < 16; kb++) {
        if (kb < 15) asm volatile("cp.async.wait_group 1;");
        else         asm volatile("cp.async.wait_group 0;");
        __syncthreads();
        if (kb == 0) {
            int qr = warp * 16 + frag_r;
            #pragma unroll
            for (int kk = 0; kk < 4; kk++) {
                int ch = kk * 2 + csel;
                ldsm_x4(qa[kk][0], qa[kk][1], qa[kk][2], qa[kk][3],
                        sq + qr * 128 + ((ch ^ sw7) * 16));
            }
        }
        if (kb + 2 < 16) issue_kv(kb + 2);

        uint32_t kbase = sq + 16384 + (kb % 3) * 16384;
        uint32_t vbase = kbase + 8192;

        // S = Q @ K^T
        float sacc[8][4];
        #pragma unroll
        for (int ni = 0; ni < 8; ni++)
            #pragma unroll
            for (int c = 0; c < 4; c++) sacc[ni][c] = 0.f;
        #pragma unroll
        for (int kk = 0; kk < 4; kk++) {
            int ch = kk * 2 + csel;
            uint32_t breg[4][4];
            #pragma unroll
            for (int p = 0; p < 4; p++) {
                int r = p * 16 + frag_r;
                ldsm_x4(breg[p][0], breg[p][1], breg[p][2], breg[p][3],
                        kbase + r * 128 + ((ch ^ sw7) * 16));
            }
            #pragma unroll
            for (int ni = 0; ni < 8; ni++) {
                uint32_t bfr[2] = { breg[ni >> 1][ni & 1], breg[ni >> 1][(ni & 1) + 2] };
                mma_f16(sacc[ni], qa[kk], bfr);
            }
        }

        // online softmax
        float mx0 = -1e30f, mx1 = -1e30f;
        #pragma unroll
        for (int ni = 0; ni < 8; ni++) {
            mx0 = fmaxf(mx0, fmaxf(sacc[ni][0], sacc[ni][1]));
            mx1 = fmaxf(mx1, fmaxf(sacc[ni][2], sacc[ni][3]));
        }
        mx0 = fmaxf(mx0, __shfl_xor_sync(0xffffffff, mx0, 1));
        mx0 = fmaxf(mx0, __shfl_xor_sync(0xffffffff, mx0, 2));
        mx1 = fmaxf(mx1, __shfl_xor_sync(0xffffffff, mx1, 1));
        mx1 = fmaxf(mx1, __shfl_xor_sync(0xffffffff, mx1, 2));
        float nm0 = fmaxf(m0, mx0 * 0.125f);
        float nm1 = fmaxf(m1, mx1 * 0.125f);
        float a0 = __expf(m0 - nm0);
        float a1 = __expf(m1 - nm1);
        m0 = nm0; m1 = nm1;

        uint32_t pw0[8], pw1[8];
        float s0 = 0.f, s1 = 0.f;
        #pragma unroll
        for (int ni = 0; ni < 8; ni++) {
            float p0 = __expf(sacc[ni][0] * 0.125f - nm0);
            float p1 = __expf(sacc[ni][1] * 0.125f - nm0);
            float p2 = __expf(sacc[ni][2] * 0.125f - nm1);
            float p3 = __expf(sacc[ni][3] * 0.125f - nm1);
            s0 += p0 + p1; s1 += p2 + p3;
            pw0[ni] = packh2(p0, p1);
            pw1[ni] = packh2(p2, p3);
        }
        s0 += __shfl_xor_sync(0xffffffff, s0, 1);
        s0 += __shfl_xor_sync(0xffffffff, s0, 2);
        s1 += __shfl_xor_sync(0xffffffff, s1, 1);
        s1 += __shfl_xor_sync(0xffffffff, s1, 2);
        l0 = l0 * a0 + s0;
        l1 = l1 * a1 + s1;
        #pragma unroll
        for (int ni = 0; ni < 8; ni++) {
            oacc[ni][0] *= a0; oacc[ni][1] *= a0;
            oacc[ni][2] *= a1; oacc[ni][3] *= a1;
        }

        // O += P @ V   (B = V^T tile)
        #pragma unroll
        for (int kp = 0; kp < 4; kp++) {
            int ch = kp * 2 + csel;
            uint32_t pa[4] = { pw0[2 * kp], pw1[2 * kp], pw0[2 * kp + 1], pw1[2 * kp + 1] };
            uint32_t breg[4][4];
            #pragma unroll
            for (int p = 0; p < 4; p++) {
                int r = p * 16 + frag_r;
                ldsm_x4(breg[p][0], breg[p][1], breg[p][2], breg[p][3],
                        vbase + r * 128 + ((ch ^ sw7) * 16));
            }
            #pragma unroll
            for (int ni = 0; ni < 8; ni++) {
                uint32_t bfr[2] = { breg[ni >> 1][ni & 1], breg[ni >> 1][(ni & 1) + 2] };
                mma_f16(oacc[ni], pa, bfr);
            }
        }
    }

    float i0 = 1.0f / l0, i1 = 1.0f / l1;
    int r = warp * 16 + (lane >> 2);
    #pragma unroll
    for (int ni = 0; ni < 8; ni++) {
        int col = ni * 8 + 2 * (lane & 3);
        store2(Og + (size_t)r * D_MODEL + col,       oacc[ni][0] * i0, oacc[ni][1] * i0);
        store2(Og + (size_t)(r + 8) * D_MODEL + col, oacc[ni][2] * i1, oacc[ni][3] * i1);
    }
}

// ============ fp16 GEMM: cp.async + swizzle + ldmatrix, 128x256 tile ============
#define NSTAGE 4
#define A_BYTES 16384
#define B_BYTES 32768
#define STAGEB (A_BYTES + B_BYTES)
#define SMEM2  (NSTAGE * STAGEB)

template <typename CT>
__global__ void __launch_bounds__(256)
mm2(const __half* __restrict__ Abase, const __half* __restrict__ Bbase,
    const float* __restrict__ bias, const float* __restrict__ resbase,
    CT* __restrict__ Cbase, int K, int lda, int ldb, int ldc,
    long sAb, long sBb, long sCb, float scale, int act) {
    extern __shared__ __align__(16) char smc[];
    uint32_t sb = smem_u32(smc);

    int tid = threadIdx.x, lane = tid & 31, warp = tid >> 5;
    int wy = warp & 1, wx = warp >> 1;
    int z = blockIdx.z;
    const __half* A = Abase + (size_t)z * sAb + (size_t)blockIdx.y * 128 * lda;
    const __half* B = Bbase + (size_t)z * sBb + (size_t)blockIdx.x * 256 * ldb;
    CT* C = Cbase + (size_t)z * sCb;
    const float* res = resbase ? resbase + (size_t)z * sCb : nullptr;
    int m0 = blockIdx.y * 128, n0 = blockIdx.x * 256;

    float acc[4][8][4];
    #pragma unroll
    for (int mi = 0; mi < 4; mi++)
        #pragma unroll
        for (int ni = 0; ni < 8; ni++)
            #pragma unroll
            for (int c = 0; c < 4; c++) acc[mi][ni][c] = 0.f;

    int lrow = tid >> 3;
    int lc   = tid & 7;
    auto issue_stage = [&](int kb, int stage) {
        uint32_t as = sb + stage * STAGEB;
        uint32_t bs = as + A_BYTES;
        int koff = kb * 64 + lc * 8;
        #pragma unroll
        for (int i = 0; i < 4; i++) {
            int row = lrow + i * 32;
            cp16(as + row * 128 + ((lc ^ (row & 7)) * 16),
                 A + (size_t)row * lda + koff);
        }
        #pragma unroll
        for (int i = 0; i < 8; i++) {
            int row = lrow + i * 32;
            cp16(bs + row * 128 + ((lc ^ (row & 7)) * 16),
                 B + (size_t)row * ldb + koff);
        }
        asm volatile("cp.async.commit_group;");
    };

    int nkb = K >> 6;
    issue_stage(0, 0);
    issue_stage(1, 1);
    if (nkb > 2) issue_stage(2, 2);
    else asm volatile("cp.async.commit_group;");

    int arow = wy * 64 + (lane & 15);
    int brow = wx * 64 + (lane & 15);
    int csel = lane >> 4;

    for (int kb = 0; kb < nkb; kb++) {
        asm volatile("cp.async.wait_group 2;");
        __syncthreads();
        int stage = kb % NSTAGE;
        if (kb + 3 < nkb) issue_stage(kb + 3, (kb + 3) % NSTAGE);
        else asm volatile("cp.async.commit_group;");

        uint32_t as = sb + stage * STAGEB;
        uint32_t bs = as + A_BYTES;
        #pragma unroll
        for (int kk = 0; kk < 4; kk++) {
            int ch = kk * 2 + csel;
            uint32_t afr[4][4], breg[4][4];
            #pragma unroll
            for (int mi = 0; mi < 4; mi++) {
                int r = arow + mi * 16;
                ldsm_x4(afr[mi][0], afr[mi][1], afr[mi][2], afr[mi][3],
                        as + r * 128 + ((ch ^ (r & 7)) * 16));
            }
            #pragma unroll
            for (int p = 0; p < 4; p++) {
                int r = brow + p * 16;
                ldsm_x4(breg[p][0], breg[p][1], breg[p][2], breg[p][3],
                        bs + r * 128 + ((ch ^ (r & 7)) * 16));
            }
            #pragma unroll
            for (int mi = 0; mi < 4; mi++)
                #pragma unroll
                for (int ni = 0; ni < 8; ni++) {
                    uint32_t bfr[2] = { breg[ni >> 1][ni & 1], breg[ni >> 1][(ni & 1) + 2] };
                    mma_f16(acc[mi][ni], afr[mi], bfr);
                }
        }
    }

    #pragma unroll
    for (int mi = 0; mi < 4; mi++) {
        #pragma unroll
        for (int ni = 0; ni < 8; ni++) {
            int col = n0 + wx * 64 + ni * 8 + 2 * (lane & 3);
            #pragma unroll
            for (int half = 0; half < 2; half++) {
                int row = m0 + wy * 64 + mi * 16 + (lane >> 2) + half * 8;
                float c0 = acc[mi][ni][2 * half]     * scale;
                float c1 = acc[mi][ni][2 * half + 1] * scale;
                if (bias) { c0 += bias[col]; c1 += bias[col + 1]; }
                if (act == 1) { c0 = gelu_tanh(c0); c1 = gelu_tanh(c1); }
                if (res) {
                    float2 rv = *(const float2*)(res + (size_t)row * ldc + col);
                    c0 += rv.x; c1 += rv.y;
                }
                store2(C + (size_t)row * ldc + col, c0, c1);
            }
        }
    }
}

// ---------------- host launch ----------------
extern "C" void kernel_launch(void* const* d_in, const int* in_sizes, int n_in,
                              void* d_out, int out_size) {
    const float* x     = (const float*)d_in[0];
    const float* zin   = (const float*)d_in[1];
    const float* g1    = (const float*)d_in[2];
    const float* b1    = (const float*)d_in[3];
    const float* w_qkv = (const float*)d_in[4];
    const float* b_qkv = (const float*)d_in[5];
    const float* w_o   = (const float*)d_in[6];
    const float* b_o   = (const float*)d_in[7];
    const float* w_kv  = (const float*)d_in[8];
    const float* b_kv  = (const float*)d_in[9];
    const float* g2    = (const float*)d_in[10];
    const float* b2    = (const float*)d_in[11];
    const float* w_m1  = (const float*)d_in[12];
    const float* b_m1  = (const float*)d_in[13];
    const float* w_m2  = (const float*)d_in[14];
    const float* b_m2  = (const float*)d_in[15];
    float* out = (float*)d_out;

    __half *ln, *qkv, *kv, *attn, *q, *mlp, *p, *z16;
    __half *wtqkv, *wto, *wtkv, *wtm1, *wtm2, *vts, *vtc;
    float *cross, *xs;
    cudaGetSymbolAddress((void**)&ln,     h_ln);
    cudaGetSymbolAddress((void**)&qkv,    h_qkv);
    cudaGetSymbolAddress((void**)&kv,     h_kv);
    cudaGetSymbolAddress((void**)&attn,   h_attn);
    cudaGetSymbolAddress((void**)&q,      h_q);
    cudaGetSymbolAddress((void**)&cross,  g_cross);
    cudaGetSymbolAddress((void**)&mlp,    h_mlp);
    cudaGetSymbolAddress((void**)&xs,     g_xs);
    cudaGetSymbolAddress((void**)&p,      h_p);
    cudaGetSymbolAddress((void**)&z16,    h_z);
    cudaGetSymbolAddress((void**)&wtqkv,  h_wt_qkv);
    cudaGetSymbolAddress((void**)&wto,    h_wt_o);
    cudaGetSymbolAddress((void**)&wtkv,   h_wt_kv);
    cudaGetSymbolAddress((void**)&wtm1,   h_wt_m1);
    cudaGetSymbolAddress((void**)&wtm2,   h_wt_m2);
    cudaGetSymbolAddress((void**)&vts,    h_vt_self);
    cudaGetSymbolAddress((void**)&vtc,    h_vt_cross);

    cudaFuncSetAttribute(mm2<__half>, cudaFuncAttributeMaxDynamicSharedMemorySize, SMEM2);
    cudaFuncSetAttribute(mm2<float>,  cudaFuncAttributeMaxDynamicSharedMemorySize, SMEM2);
    cudaFuncSetAttribute(flash_self,  cudaFuncAttributeMaxDynamicSharedMemorySize, FLASH_SMEM);

    cudaStream_t s2;
    cudaStreamCreateWithFlags(&s2, cudaStreamNonBlocking);
    cudaEvent_t evStart, evZ, evWO, evKV, evW;
    cudaEventCreateWithFlags(&evStart, cudaEventDisableTiming);
    cudaEventCreateWithFlags(&evZ,  cudaEventDisableTiming);
    cudaEventCreateWithFlags(&evWO, cudaEventDisableTiming);
    cudaEventCreateWithFlags(&evKV, cudaEventDisableTiming);
    cudaEventCreateWithFlags(&evW,  cudaEventDisableTiming);

    // ---- fork: side stream must join capture via event-wait on origin stream ----
    cudaEventRecord(evStart, 0);
    cudaStreamWaitEvent(s2, evStart, 0);

    // ---- main: ln1 first (unblocks kv chain earliest) ----
    ln_kernel<<<ROWS, 256>>>(x, g1, b1, ln, zin, z16);
    cudaEventRecord(evZ, 0);
    transpose64<float><<<dim3(48, 16, 1), 256>>>(w_qkv, wtqkv, 3 * D_MODEL, D_MODEL, 0, 0, 0, 0, 1);

    // ---- side stream: independent weight transposes + kv chain ----
    transpose64<float><<<dim3(16, 16, 1), 256, 0, s2>>>(w_o, wto, D_MODEL, D_MODEL, 0, 0, 0, 0, 1);
    cudaEventRecord(evWO, s2);
    transpose64<float><<<dim3(32, 16, 1), 256, 0, s2>>>(w_kv, wtkv, 2 * D_MODEL, D_MODEL, 0, 0, 0, 0, 1);
    cudaStreamWaitEvent(s2, evZ, 0);
    mm2<__half><<<dim3(8, 32, 1), 256, SMEM2, s2>>>(
        z16, wtkv, b_kv, nullptr, kv, D_MODEL, D_MODEL, D_MODEL, 2 * D_MODEL,
        0, 0, 0, 1.0f, 0);
    transpose64<__half><<<dim3(16, 16, BATCH), 256, 0, s2>>>(
        kv + D_MODEL, vtc, 2 * D_MODEL, SEQ,
        (long)SEQ * 2 * D_MODEL, 0, (long)D_MODEL * SEQ, 0, 1);
    cudaEventRecord(evKV, s2);
    transpose64<float><<<dim3(64, 16, 1), 256, 0, s2>>>(w_m1, wtm1, HMLP, D_MODEL, 0, 0, 0, 0, 1);
    transpose64<float><<<dim3(16, 64, 1), 256, 0, s2>>>(w_m2, wtm2, D_MODEL, HMLP, 0, 0, 0, 0, 1);
    cudaEventRecord(evW, s2);

    // ---- main: q chain ----
    mm2<__half><<<dim3(12, 32, 1), 256, SMEM2>>>(
        ln, wtqkv, b_qkv, nullptr, qkv, D_MODEL, D_MODEL, D_MODEL, 3 * D_MODEL,
        0, 0, 0, 1.0f, 0);

    transpose64<__half><<<dim3(1, 16, BATCH * NHEADS), 256>>>(
        qkv + 2 * D_MODEL, vts, 3 * D_MODEL, SEQ,
        (long)SEQ * 3 * D_MODEL, HDIM, (long)NHEADS * HDIM * SEQ, (long)HDIM * SEQ, NHEADS);

    flash_self<<<dim3(8, BATCH * NHEADS), 256, FLASH_SMEM>>>(qkv, vts, attn);

    cudaStreamWaitEvent(0, evWO, 0);
    mm2<__half><<<dim3(4, 32, 1), 256, SMEM2>>>(
        attn, wto, b_o, x, q, D_MODEL, D_MODEL, D_MODEL, D_MODEL,
        0, 0, 0, 1.0f, 0);

    cudaStreamWaitEvent(0, evKV, 0);
    mm2<float><<<dim3(4, 8, BATCH), 256, SMEM2>>>(
        q, kv, nullptr, nullptr, xs, D_MODEL, D_MODEL, 2 * D_MODEL, SEQ,
        (long)SEQ * D_MODEL, (long)SEQ * 2 * D_MODEL, (long)SEQ * SEQ, 0.03125f, 0);

    softmax_f2h<<<BATCH * SEQ, 256>>>(xs, p);

    mm2<float><<<dim3(4, 8, BATCH), 256, SMEM2>>>(
        p, vtc, nullptr, nullptr, cross, SEQ, SEQ, SEQ, D_MODEL,
        (long)SEQ * SEQ, (long)D_MODEL * SEQ, (long)SEQ * D_MODEL, 1.0f, 0);

    ln_kernel<<<ROWS, 256>>>(cross, g2, b2, ln, nullptr, nullptr);

    cudaStreamWaitEvent(0, evW, 0);
    mm2<__half><<<dim3(16, 32, 1), 256, SMEM2>>>(
        ln, wtm1, b_m1, nullptr, mlp, D_MODEL, D_MODEL, D_MODEL, HMLP,
        0, 0, 0, 1.0f, 1);

    mm2<float><<<dim3(4, 32, 1), 256, SMEM2>>>(
        mlp, wtm2, b_m2, cross, out, HMLP, HMLP, HMLP, D_MODEL,
        0, 0, 0, 1.0f, 0);
}

// round 14
// speedup vs baseline: 8.9274x; 1.0511x over previous
#include <cuda_runtime.h>
#include <cuda_fp16.h>
#include <math.h>
#include <stdint.h>

#define D_MODEL 1024
#define BATCH   4
#define SEQ     1024
#define NHEADS  16
#define HDIM    64
#define HMLP    4096
#define ROWS    (BATCH*SEQ)     // 4096

// ---------------- scratch (device globals; no allocs allowed) ----------------
__device__ __half h_ln   [ROWS * D_MODEL];
__device__ __half h_qkv  [ROWS * 3 * D_MODEL];
__device__ __half h_kv   [ROWS * 2 * D_MODEL];
__device__ __half h_attn [ROWS * D_MODEL];
__device__ __half h_q    [ROWS * D_MODEL];
__device__ float  g_cross[ROWS * D_MODEL];
__device__ __half h_mlp  [ROWS * HMLP];
__device__ float  g_xs   [(size_t)BATCH * SEQ * SEQ];
__device__ __half h_p    [(size_t)BATCH * SEQ * SEQ];
__device__ __half h_z    [ROWS * D_MODEL];
__device__ __half h_wt_qkv[3 * D_MODEL * D_MODEL];
__device__ __half h_wt_o  [D_MODEL * D_MODEL];
__device__ __half h_wt_kv [2 * D_MODEL * D_MODEL];
__device__ __half h_wt_m1 [HMLP * D_MODEL];
__device__ __half h_wt_m2 [D_MODEL * HMLP];
__device__ __half h_vt_self [BATCH * NHEADS * HDIM * SEQ];
__device__ __half h_vt_cross[(size_t)BATCH * D_MODEL * SEQ];

__device__ __forceinline__ float gelu_tanh(float c) {
    float t = 0.7978845608028654f * (c + 0.044715f * c * c * c);
    return 0.5f * c * (1.0f + tanhf(t));
}
__device__ __forceinline__ void mma_f16(float* d, const uint32_t* a, const uint32_t* b) {
    asm volatile("mma.sync.aligned.m16n8k16.row.col.f32.f16.f16.f32 "
        "{%0,%1,%2,%3}, {%4,%5,%6,%7}, {%8,%9}, {%0,%1,%2,%3};"
        : "+f"(d[0]), "+f"(d[1]), "+f"(d[2]), "+f"(d[3])
        : "r"(a[0]), "r"(a[1]), "r"(a[2]), "r"(a[3]), "r"(b[0]), "r"(b[1]));
}
__device__ __forceinline__ void ldsm_x4(uint32_t& r0, uint32_t& r1, uint32_t& r2, uint32_t& r3,
                                        uint32_t addr) {
    asm volatile("ldmatrix.sync.aligned.m8n8.x4.shared.b16 {%0,%1,%2,%3}, [%4];"
        : "=r"(r0), "=r"(r1), "=r"(r2), "=r"(r3) : "r"(addr));
}
__device__ __forceinline__ void cp16(uint32_t smem, const void* g) {
    asm volatile("cp.async.cg.shared.global [%0], [%1], 16;" :: "r"(smem), "l"(g));
}
__device__ __forceinline__ uint32_t smem_u32(const void* p) {
    return (uint32_t)__cvta_generic_to_shared(p);
}
__device__ __forceinline__ void store2(__half* p, float a, float b) {
    *(__half2*)p = __floats2half2_rn(a, b);
}
__device__ __forceinline__ void store2(float* p, float a, float b) {
    float2 v; v.x = a; v.y = b; *(float2*)p = v;
}
__device__ __forceinline__ uint32_t packh2(float a, float b) {
    __half2 h = __floats2half2_rn(a, b);
    return *(uint32_t*)&h;
}

// ------------- single-pass layernorm (fp32 in -> fp16 out) + optional z cvt ----
__global__ void ln_kernel(const float* __restrict__ x, const float* __restrict__ g,
                          const float* __restrict__ b, __half* __restrict__ out,
                          const float* __restrict__ zsrc, __half* __restrict__ zdst) {
    int row = blockIdx.x;
    int tid = threadIdx.x;
    const float* xr = x + (size_t)row * D_MODEL;
    float4 v = *(const float4*)(xr + tid * 4);
    if (zsrc) {
        const float* zr = zsrc + (size_t)row * D_MODEL;
        __half* zo = zdst + (size_t)row * D_MODEL;
        float4 a = *(const float4*)(zr + tid * 4);
        __half2 h[2];
        h[0] = __floats2half2_rn(a.x, a.y); h[1] = __floats2half2_rn(a.z, a.w);
        *(uint2*)(zo + tid * 4) = *(uint2*)h;
    }
    float s  = v.x + v.y + v.z + v.w;
    float s2 = v.x * v.x + v.y * v.y + v.z * v.z + v.w * v.w;
    __shared__ float rs[8], rs2[8];
    for (int o = 16; o > 0; o >>= 1) {
        s  += __shfl_xor_sync(0xffffffff, s,  o);
        s2 += __shfl_xor_sync(0xffffffff, s2, o);
    }
    if ((tid & 31) == 0) { rs[tid >> 5] = s; rs2[tid >> 5] = s2; }
    __syncthreads();
    if (tid < 32) {
        float a  = (tid < 8) ? rs[tid]  : 0.f;
        float a2 = (tid < 8) ? rs2[tid] : 0.f;
        for (int o = 4; o > 0; o >>= 1) {
            a  += __shfl_xor_sync(0xffffffff, a,  o);
            a2 += __shfl_xor_sync(0xffffffff, a2, o);
        }
        rs[0] = a; rs2[0] = a2;
    }
    __syncthreads();
    float mu  = rs[0]  * (1.0f / D_MODEL);
    float var = rs2[0] * (1.0f / D_MODEL) - mu * mu;
    float inv = rsqrtf(var + 1e-5f);
    float4 gg = *(const float4*)(g + tid * 4);
    float4 bb = *(const float4*)(b + tid * 4);
    __half2 h[2];
    h[0] = __floats2half2_rn((v.x - mu) * inv * gg.x + bb.x,
                             (v.y - mu) * inv * gg.y + bb.y);
    h[1] = __floats2half2_rn((v.z - mu) * inv * gg.z + bb.z,
                             (v.w - mu) * inv * gg.w + bb.w);
    *(uint2*)(out + (size_t)row * D_MODEL + tid * 4) = *(uint2*)h;
}

// ---------------- softmax fp32 in -> fp16 out (cross) ----------------
__global__ void softmax_f2h(const float* __restrict__ S, __half* __restrict__ P) {
    const float* row = S + (size_t)blockIdx.x * 1024;
    __half* prow = P + (size_t)blockIdx.x * 1024;
    int tid = threadIdx.x;
    float4 v = *(const float4*)(row + tid * 4);
    float mx = fmaxf(fmaxf(v.x, v.y), fmaxf(v.z, v.w));
    __shared__ float red[32];
    for (int o = 16; o > 0; o >>= 1) mx = fmaxf(mx, __shfl_xor_sync(0xffffffff, mx, o));
    if ((tid & 31) == 0) red[tid >> 5] = mx;
    __syncthreads();
    if (tid < 32) {
        float m = (tid < 8) ? red[tid] : -1e30f;
        for (int o = 4; o > 0; o >>= 1) m = fmaxf(m, __shfl_xor_sync(0xffffffff, m, o));
        red[0] = m;
    }
    __syncthreads();
    mx = red[0];
    v.x = expf(v.x - mx); v.y = expf(v.y - mx); v.z = expf(v.z - mx); v.w = expf(v.w - mx);
    float s = v.x + v.y + v.z + v.w;
    for (int o = 16; o > 0; o >>= 1) s += __shfl_xor_sync(0xffffffff, s, o);
    __syncthreads();
    if ((tid & 31) == 0) red[tid >> 5] = s;
    __syncthreads();
    if (tid < 32) {
        float t = (tid < 8) ? red[tid] : 0.f;
        for (int o = 4; o > 0; o >>= 1) t += __shfl_xor_sync(0xffffffff, t, o);
        red[0] = t;
    }
    __syncthreads();
    float inv = 1.0f / red[0];
    __half2 h2[2];
    h2[0] = __floats2half2_rn(v.x * inv, v.y * inv);
    h2[1] = __floats2half2_rn(v.z * inv, v.w * inv);
    *(uint2*)(prow + tid * 4) = *(uint2*)h2;
}

// ---------------- fast 64x64 batched transpose (TS in -> half out) ------------
template <typename TS>
__device__ __forceinline__ void ld4h(const TS* p, __half* v);
template <>
__device__ __forceinline__ void ld4h<float>(const float* p, __half* v) {
    float4 f = *(const float4*)p;
    v[0] = __float2half(f.x); v[1] = __float2half(f.y);
    v[2] = __float2half(f.z); v[3] = __float2half(f.w);
}
template <>
__device__ __forceinline__ void ld4h<__half>(const __half* p, __half* v) {
    uint2 u = *(const uint2*)p;
    *(uint32_t*)&v[0] = u.x; *(uint32_t*)&v[2] = u.y;
}

template <typename TS>
__global__ void __launch_bounds__(256)
transpose64(const TS* __restrict__ srcb, __half* __restrict__ dstb,
            int lds, int ldd, long sSb, long sSh, long sDb, long sDh, int nh) {
    __shared__ __half tile[64][66];
    int z = blockIdx.z, b = z / nh, h = z - b * nh;
    const TS* src = srcb + (size_t)b * sSb + (size_t)h * sSh;
    __half* dst = dstb + (size_t)b * sDb + (size_t)h * sDh;
    int x0 = blockIdx.x * 64;
    int y0 = blockIdx.y * 64;
    int tx = threadIdx.x & 15, ty = threadIdx.x >> 4;
    #pragma unroll
    for (int i = 0; i < 4; i++) {
        int row = y0 + ty + i * 16;
        __half v[4];
        ld4h<TS>(src + (size_t)row * lds + x0 + tx * 4, v);
        tile[tx * 4 + 0][ty + i * 16] = v[0];
        tile[tx * 4 + 1][ty + i * 16] = v[1];
        tile[tx * 4 + 2][ty + i * 16] = v[2];
        tile[tx * 4 + 3][ty + i * 16] = v[3];
    }
    __syncthreads();
    #pragma unroll
    for (int i = 0; i < 4; i++) {
        int drow = x0 + ty + i * 16;
        __half2 p0, p1;
        p0.x = tile[ty + i * 16][tx * 4 + 0]; p0.y = tile[ty + i * 16][tx * 4 + 1];
        p1.x = tile[ty + i * 16][tx * 4 + 2]; p1.y = tile[ty + i * 16][tx * 4 + 3];
        uint2 o; o.x = *(uint32_t*)&p0; o.y = *(uint32_t*)&p1;
        *(uint2*)(dst + (size_t)drow * ldd + y0 + tx * 4) = o;
    }
}

// ========== flash self-attention v2: cp.async 3-stage ring + ldmatrix ==========
#define FLASH_SMEM (16384 + 3 * 16384)   // 65536 B

__global__ void __launch_bounds__(256)
flash_self(const __half* __restrict__ qkvg, const __half* __restrict__ vtsg,
           __half* __restrict__ attng) {
    extern __shared__ __align__(16) char fsmc[];
    uint32_t sq = smem_u32(fsmc);

    int tid = threadIdx.x, lane = tid & 31, warp = tid >> 5;
    int bh = blockIdx.y, b = bh >> 4, h = bh & 15;
    const __half* Qg = qkvg + (size_t)b * SEQ * 3 * D_MODEL
                     + (size_t)blockIdx.x * 128 * 3 * D_MODEL + h * HDIM;
    const __half* Kg = qkvg + (size_t)b * SEQ * 3 * D_MODEL + D_MODEL + h * HDIM;
    const __half* Vt = vtsg + (size_t)bh * HDIM * SEQ;
    __half* Og = attng + (size_t)b * SEQ * D_MODEL
               + (size_t)blockIdx.x * 128 * D_MODEL + h * HDIM;

    auto issue_kv = [&](int kb) {
        uint32_t base = sq + 16384 + (kb % 3) * 16384;
        #pragma unroll
        for (int i = 0; i < 2; i++) {
            int f = i * 256 + tid, row = f >> 3, ch = f & 7;
            uint32_t sw = (ch ^ (row & 7)) * 16;
            cp16(base + row * 128 + sw,
                 Kg + (size_t)(kb * 64 + row) * 3 * D_MODEL + ch * 8);
            cp16(base + 8192 + row * 128 + sw,
                 Vt + (size_t)row * SEQ + kb * 64 + ch * 8);
        }
        asm volatile("cp.async.commit_group;");
    };

    #pragma unroll
    for (int i = 0; i < 4; i++) {
        int f = i * 256 + tid, row = f >> 3, ch = f & 7;
        cp16(sq + row * 128 + ((ch ^ (row & 7)) * 16),
             Qg + (size_t)row * 3 * D_MODEL + ch * 8);
    }
    issue_kv(0);
    issue_kv(1);

    uint32_t qa[4][4];
    float oacc[8][4];
    #pragma unroll
    for (int ni = 0; ni < 8; ni++)
        #pragma unroll
        for (int c = 0; c < 4; c++) oacc[ni][c] = 0.f;
    float m0 = -1e30f, m1 = -1e30f, l0 = 0.f, l1 = 0.f;

    int frag_r = lane & 15;
    int csel = lane >> 4;
    int sw7 = frag_r & 7;

    for (int kb = 0; kb < 16; kb++) {
        if (kb < 15) asm volatile("cp.async.wait_group 1;");
        else         asm volatile("cp.async.wait_group 0;");
        __syncthreads();
        if (kb == 0) {
            int qr = warp * 16 + frag_r;
            #pragma unroll
            for (int kk = 0; kk < 4; kk++) {
                int ch = kk * 2 + csel;
                ldsm_x4(qa[kk][0], qa[kk][1], qa[kk][2], qa[kk][3],
                        sq + qr * 128 + ((ch ^ sw7) * 16));
            }
        }
        if (kb + 2 < 16) issue_kv(kb + 2);

        uint32_t kbase = sq + 16384 + (kb % 3) * 16384;
        uint32_t vbase = kbase + 8192;

        float sacc[8][4];
        #pragma unroll
        for (int ni = 0; ni < 8; ni++)
            #pragma unroll
            for (int c = 0; c < 4; c++) sacc[ni][c] = 0.f;
        #pragma unroll
        for (int kk = 0; kk < 4; kk++) {
            int ch = kk * 2 + csel;
            uint32_t breg[4][4];
            #pragma unroll
            for (int p = 0; p < 4; p++) {
                int r = p * 16 + frag_r;
                ldsm_x4(breg[p][0], breg[p][1], breg[p][2], breg[p][3],
                        kbase + r * 128 + ((ch ^ sw7) * 16));
            }
            #pragma unroll
            for (int ni = 0; ni < 8; ni++) {
                uint32_t bfr[2] = { breg[ni >> 1][ni & 1], breg[ni >> 1][(ni & 1) + 2] };
                mma_f16(sacc[ni], qa[kk], bfr);
            }
        }

        float mx0 = -1e30f, mx1 = -1e30f;
        #pragma unroll
        for (int ni = 0; ni < 8; ni++) {
            mx0 = fmaxf(mx0, fmaxf(sacc[ni][0], sacc[ni][1]));
            mx1 = fmaxf(mx1, fmaxf(sacc[ni][2], sacc[ni][3]));
        }
        mx0 = fmaxf(mx0, __shfl_xor_sync(0xffffffff, mx0, 1));
        mx0 = fmaxf(mx0, __shfl_xor_sync(0xffffffff, mx0, 2));
        mx1 = fmaxf(mx1, __shfl_xor_sync(0xffffffff, mx1, 1));
        mx1 = fmaxf(mx1, __shfl_xor_sync(0xffffffff, mx1, 2));
        float nm0 = fmaxf(m0, mx0 * 0.125f);
        float nm1 = fmaxf(m1, mx1 * 0.125f);
        float a0 = __expf(m0 - nm0);
        float a1 = __expf(m1 - nm1);
        m0 = nm0; m1 = nm1;

        uint32_t pw0[8], pw1[8];
        float s0 = 0.f, s1 = 0.f;
        #pragma unroll
        for (int ni = 0; ni < 8; ni++) {
            float p0 = __expf(sacc[ni][0] * 0.125f - nm0);
            float p1 = __expf(sacc[ni][1] * 0.125f - nm0);
            float p2 = __expf(sacc[ni][2] * 0.125f - nm1);
            float p3 = __expf(sacc[ni][3] * 0.125f - nm1);
            s0 += p0 + p1; s1 += p2 + p3;
            pw0[ni] = packh2(p0, p1);
            pw1[ni] = packh2(p2, p3);
        }
        s0 += __shfl_xor_sync(0xffffffff, s0, 1);
        s0 += __shfl_xor_sync(0xffffffff, s0, 2);
        s1 += __shfl_xor_sync(0xffffffff, s1, 1);
        s1 += __shfl_xor_sync(0xffffffff, s1, 2);
        l0 = l0 * a0 + s0;
        l1 = l1 * a1 + s1;
        #pragma unroll
        for (int ni = 0; ni < 8; ni++) {
            oacc[ni][0] *= a0; oacc[ni][1] *= a0;
            oacc[ni][2] *= a1; oacc[ni][3] *= a1;
        }

        #pragma unroll
        for (int kp = 0; kp < 4; kp++) {
            int ch = kp * 2 + csel;
            uint32_t pa[4] = { pw0[2 * kp], pw1[2 * kp], pw0[2 * kp + 1], pw1[2 * kp + 1] };
            uint32_t breg[4][4];
            #pragma unroll
            for (int p = 0; p < 4; p++) {
                int r = p * 16 + frag_r;
                ldsm_x4(breg[p][0], breg[p][1], breg[p][2], breg[p][3],
                        vbase + r * 128 + ((ch ^ sw7) * 16));
            }
            #pragma unroll
            for (int ni = 0; ni < 8; ni++) {
                uint32_t bfr[2] = { breg[ni >> 1][ni & 1], breg[ni >> 1][(ni & 1) + 2] };
                mma_f16(oacc[ni], pa, bfr);
            }
        }
    }

    float i0 = 1.0f / l0, i1 = 1.0f / l1;
    int r = warp * 16 + (lane >> 2);
    #pragma unroll
    for (int ni = 0; ni < 8; ni++) {
        int col = ni * 8 + 2 * (lane & 3);
        store2(Og + (size_t)r * D_MODEL + col,       oacc[ni][0] * i0, oacc[ni][1] * i0);
        store2(Og + (size_t)(r + 8) * D_MODEL + col, oacc[ni][2] * i1, oacc[ni][3] * i1);
    }
}

// ======= fp16 GEMM: cp.async + swizzle + ldmatrix, 128 x TN tile (TN=256|128) ==
#define NSTAGE 4
#define A_BYTES 16384

template <typename CT, int TN>
__global__ void __launch_bounds__(256)
mm2(const __half* __restrict__ Abase, const __half* __restrict__ Bbase,
    const float* __restrict__ bias, const float* __restrict__ resbase,
    CT* __restrict__ Cbase, int K, int lda, int ldb, int ldc,
    long sAb, long sBb, long sCb, float scale, int act) {
    constexpr int B_BYTES = TN * 128;
    constexpr int STAGEB  = A_BYTES + B_BYTES;
    constexpr int WNT = TN / 4;       // warp n-extent (64 or 32)
    constexpr int PB  = WNT / 16;     // ldsm B blocks per kk (4 or 2)
    constexpr int NI  = WNT / 8;      // mma n-tiles per warp (8 or 4)
    constexpr int NBLD = TN / 32;     // B cp16 per thread per stage

    extern __shared__ __align__(16) char smc[];
    uint32_t sb = smem_u32(smc);

    int tid = threadIdx.x, lane = tid & 31, warp = tid >> 5;
    int wy = warp & 1, wx = warp >> 1;
    int z = blockIdx.z;
    const __half* A = Abase + (size_t)z * sAb + (size_t)blockIdx.y * 128 * lda;
    const __half* B = Bbase + (size_t)z * sBb + (size_t)blockIdx.x * TN * ldb;
    CT* C = Cbase + (size_t)z * sCb;
    const float* res = resbase ? resbase + (size_t)z * sCb : nullptr;
    int m0 = blockIdx.y * 128, n0 = blockIdx.x * TN;

    float acc[4][NI][4];
    #pragma unroll
    for (int mi = 0; mi < 4; mi++)
        #pragma unroll
        for (int ni = 0; ni < NI; ni++)
            #pragma unroll
            for (int c = 0; c < 4; c++) acc[mi][ni][c] = 0.f;

    int lrow = tid >> 3;
    int lc   = tid & 7;
    auto issue_stage = [&](int kb, int stage) {
        uint32_t as = sb + stage * STAGEB;
        uint32_t bs = as + A_BYTES;
        int koff = kb * 64 + lc * 8;
        #pragma unroll
        for (int i = 0; i < 4; i++) {
            int row = lrow + i * 32;
            cp16(as + row * 128 + ((lc ^ (row & 7)) * 16),
                 A + (size_t)row * lda + koff);
        }
        #pragma unroll
        for (int i = 0; i < NBLD; i++) {
            int row = lrow + i * 32;
            cp16(bs + row * 128 + ((lc ^ (row & 7)) * 16),
                 B + (size_t)row * ldb + koff);
        }
        asm volatile("cp.async.commit_group;");
    };

    int nkb = K >> 6;
    issue_stage(0, 0);
    issue_stage(1, 1);
    if (nkb > 2) issue_stage(2, 2);
    else asm volatile("cp.async.commit_group;");

    int arow = wy * 64 + (lane & 15);
    int brow = wx * WNT + (lane & 15);
    int csel = lane >> 4;

    for (int kb = 0; kb < nkb; kb++) {
        asm volatile("cp.async.wait_group 2;");
        __syncthreads();
        int stage = kb % NSTAGE;
        if (kb + 3 < nkb) issue_stage(kb + 3, (kb + 3) % NSTAGE);
        else asm volatile("cp.async.commit_group;");

        uint32_t as = sb + stage * STAGEB;
        uint32_t bs = as + A_BYTES;
        #pragma unroll
        for (int kk = 0; kk < 4; kk++) {
            int ch = kk * 2 + csel;
            uint32_t afr[4][4], breg[PB][4];
            #pragma unroll
            for (int mi = 0; mi < 4; mi++) {
                int r = arow + mi * 16;
                ldsm_x4(afr[mi][0], afr[mi][1], afr[mi][2], afr[mi][3],
                        as + r * 128 + ((ch ^ (r & 7)) * 16));
            }
            #pragma unroll
            for (int p = 0; p < PB; p++) {
                int r = brow + p * 16;
                ldsm_x4(breg[p][0], breg[p][1], breg[p][2], breg[p][3],
                        bs + r * 128 + ((ch ^ (r & 7)) * 16));
            }
            #pragma unroll
            for (int mi = 0; mi < 4; mi++)
                #pragma unroll
                for (int ni = 0; ni < NI; ni++) {
                    uint32_t bfr[2] = { breg[ni >> 1][ni & 1], breg[ni >> 1][(ni & 1) + 2] };
                    mma_f16(acc[mi][ni], afr[mi], bfr);
                }
        }
    }

    #pragma unroll
    for (int mi = 0; mi < 4; mi++) {
        #pragma unroll
        for (int ni = 0; ni < NI; ni++) {
            int col = n0 + wx * WNT + ni * 8 + 2 * (lane & 3);
            #pragma unroll
            for (int half = 0; half < 2; half++) {
                int row = m0 + wy * 64 + mi * 16 + (lane >> 2) + half * 8;
                float c0 = acc[mi][ni][2 * half]     * scale;
                float c1 = acc[mi][ni][2 * half + 1] * scale;
                if (bias) { c0 += bias[col]; c1 += bias[col + 1]; }
                if (act == 1) { c0 = gelu_tanh(c0); c1 = gelu_tanh(c1); }
                if (res) {
                    float2 rv = *(const float2*)(res + (size_t)row * ldc + col);
                    c0 += rv.x; c1 += rv.y;
                }
                store2(C + (size_t)row * ldc + col, c0, c1);
            }
        }
    }
}

#define SMEM_T(TN) (NSTAGE * (A_BYTES + (TN) * 128))

// ---------------- host launch ----------------
extern "C" void kernel_launch(void* const* d_in, const int* in_sizes, int n_in,
                              void* d_out, int out_size) {
    const float* x     = (const float*)d_in[0];
    const float* zin   = (const float*)d_in[1];
    const float* g1    = (const float*)d_in[2];
    const float* b1    = (const float*)d_in[3];
    const float* w_qkv = (const float*)d_in[4];
    const float* b_qkv = (const float*)d_in[5];
    const float* w_o   = (const float*)d_in[6];
    const float* b_o   = (const float*)d_in[7];
    const float* w_kv  = (const float*)d_in[8];
    const float* b_kv  = (const float*)d_in[9];
    const float* g2    = (const float*)d_in[10];
    const float* b2    = (const float*)d_in[11];
    const float* w_m1  = (const float*)d_in[12];
    const float* b_m1  = (const float*)d_in[13];
    const float* w_m2  = (const float*)d_in[14];
    const float* b_m2  = (const float*)d_in[15];
    float* out = (float*)d_out;

    __half *ln, *qkv, *kv, *attn, *q, *mlp, *p, *z16;
    __half *wtqkv, *wto, *wtkv, *wtm1, *wtm2, *vts, *vtc;
    float *cross, *xs;
    cudaGetSymbolAddress((void**)&ln,     h_ln);
    cudaGetSymbolAddress((void**)&qkv,    h_qkv);
    cudaGetSymbolAddress((void**)&kv,     h_kv);
    cudaGetSymbolAddress((void**)&attn,   h_attn);
    cudaGetSymbolAddress((void**)&q,      h_q);
    cudaGetSymbolAddress((void**)&cross,  g_cross);
    cudaGetSymbolAddress((void**)&mlp,    h_mlp);
    cudaGetSymbolAddress((void**)&xs,     g_xs);
    cudaGetSymbolAddress((void**)&p,      h_p);
    cudaGetSymbolAddress((void**)&z16,    h_z);
    cudaGetSymbolAddress((void**)&wtqkv,  h_wt_qkv);
    cudaGetSymbolAddress((void**)&wto,    h_wt_o);
    cudaGetSymbolAddress((void**)&wtkv,   h_wt_kv);
    cudaGetSymbolAddress((void**)&wtm1,   h_wt_m1);
    cudaGetSymbolAddress((void**)&wtm2,   h_wt_m2);
    cudaGetSymbolAddress((void**)&vts,    h_vt_self);
    cudaGetSymbolAddress((void**)&vtc,    h_vt_cross);

    cudaFuncSetAttribute((const void*)mm2<__half, 256>, cudaFuncAttributeMaxDynamicSharedMemorySize, SMEM_T(256));
    cudaFuncSetAttribute((const void*)mm2<float, 256>,  cudaFuncAttributeMaxDynamicSharedMemorySize, SMEM_T(256));
    cudaFuncSetAttribute((const void*)mm2<__half, 128>, cudaFuncAttributeMaxDynamicSharedMemorySize, SMEM_T(128));
    cudaFuncSetAttribute((const void*)flash_self, cudaFuncAttributeMaxDynamicSharedMemorySize, FLASH_SMEM);

    cudaStream_t s2;
    cudaStreamCreateWithFlags(&s2, cudaStreamNonBlocking);
    cudaEvent_t evStart, evZ, evWQ, evWO, evKV, evW;
    cudaEventCreateWithFlags(&evStart, cudaEventDisableTiming);
    cudaEventCreateWithFlags(&evZ,  cudaEventDisableTiming);
    cudaEventCreateWithFlags(&evWQ, cudaEventDisableTiming);
    cudaEventCreateWithFlags(&evWO, cudaEventDisableTiming);
    cudaEventCreateWithFlags(&evKV, cudaEventDisableTiming);
    cudaEventCreateWithFlags(&evW,  cudaEventDisableTiming);

    // ---- fork: side stream joins capture via event-wait on origin stream ----
    cudaEventRecord(evStart, 0);
    cudaStreamWaitEvent(s2, evStart, 0);

    // ---- main: ln1 (overlaps wtqkv on s2) ----
    ln_kernel<<<ROWS, 256>>>(x, g1, b1, ln, zin, z16);
    cudaEventRecord(evZ, 0);

    // ---- side stream: wtqkv first (qkv prerequisite), then w_o, kv chain, mlp weights
    transpose64<float><<<dim3(48, 16, 1), 256, 0, s2>>>(w_qkv, wtqkv, 3 * D_MODEL, D_MODEL, 0, 0, 0, 0, 1);
    cudaEventRecord(evWQ, s2);
    transpose64<float><<<dim3(16, 16, 1), 256, 0, s2>>>(w_o, wto, D_MODEL, D_MODEL, 0, 0, 0, 0, 1);
    cudaEventRecord(evWO, s2);
    transpose64<float><<<dim3(32, 16, 1), 256, 0, s2>>>(w_kv, wtkv, 2 * D_MODEL, D_MODEL, 0, 0, 0, 0, 1);
    cudaStreamWaitEvent(s2, evZ, 0);
    mm2<__half, 256><<<dim3(8, 32, 1), 256, SMEM_T(256), s2>>>(
        z16, wtkv, b_kv, nullptr, kv, D_MODEL, D_MODEL, D_MODEL, 2 * D_MODEL,
        0, 0, 0, 1.0f, 0);
    transpose64<__half><<<dim3(16, 16, BATCH), 256, 0, s2>>>(
        kv + D_MODEL, vtc, 2 * D_MODEL, SEQ,
        (long)SEQ * 2 * D_MODEL, 0, (long)D_MODEL * SEQ, 0, 1);
    cudaEventRecord(evKV, s2);
    transpose64<float><<<dim3(64, 16, 1), 256, 0, s2>>>(w_m1, wtm1, HMLP, D_MODEL, 0, 0, 0, 0, 1);
    transpose64<float><<<dim3(16, 64, 1), 256, 0, s2>>>(w_m2, wtm2, D_MODEL, HMLP, 0, 0, 0, 0, 1);
    cudaEventRecord(evW, s2);

    // ---- main: q chain ----
    cudaStreamWaitEvent(0, evWQ, 0);
    mm2<__half, 256><<<dim3(12, 32, 1), 256, SMEM_T(256)>>>(
        ln, wtqkv, b_qkv, nullptr, qkv, D_MODEL, D_MODEL, D_MODEL, 3 * D_MODEL,
        0, 0, 0, 1.0f, 0);

    transpose64<__half><<<dim3(1, 16, BATCH * NHEADS), 256>>>(
        qkv + 2 * D_MODEL, vts, 3 * D_MODEL, SEQ,
        (long)SEQ * 3 * D_MODEL, HDIM, (long)NHEADS * HDIM * SEQ, (long)HDIM * SEQ, NHEADS);

    flash_self<<<dim3(8, BATCH * NHEADS), 256, FLASH_SMEM>>>(qkv, vts, attn);

    cudaStreamWaitEvent(0, evWO, 0);
    mm2<__half, 256><<<dim3(4, 32, 1), 256, SMEM_T(256)>>>(
        attn, wto, b_o, x, q, D_MODEL, D_MODEL, D_MODEL, D_MODEL,
        0, 0, 0, 1.0f, 0);

    cudaStreamWaitEvent(0, evKV, 0);
    mm2<float, 256><<<dim3(4, 8, BATCH), 256, SMEM_T(256)>>>(
        q, kv, nullptr, nullptr, xs, D_MODEL, D_MODEL, 2 * D_MODEL, SEQ,
        (long)SEQ * D_MODEL, (long)SEQ * 2 * D_MODEL, (long)SEQ * SEQ, 0.03125f, 0);

    softmax_f2h<<<BATCH * SEQ, 256>>>(xs, p);

    mm2<float, 256><<<dim3(4, 8, BATCH), 256, SMEM_T(256)>>>(
        p, vtc, nullptr, nullptr, cross, SEQ, SEQ, SEQ, D_MODEL,
        (long)SEQ * SEQ, (long)D_MODEL * SEQ, (long)SEQ * D_MODEL, 1.0f, 0);

    ln_kernel<<<ROWS, 256>>>(cross, g2, b2, ln, nullptr, nullptr);

    cudaStreamWaitEvent(0, evW, 0);
    // mlp1 with 128x128 tiles: 1024 tiles -> 6.92 waves (near-perfect quantization)
    mm2<__half, 128><<<dim3(32, 32, 1), 256, SMEM_T(128)>>>(
        ln, wtm1, b_m1, nullptr, mlp, D_MODEL, D_MODEL, D_MODEL, HMLP,
        0, 0, 0, 1.0f, 1);

    mm2<float, 256><<<dim3(4, 32, 1), 256, SMEM_T(256)>>>(
        mlp, wtm2, b_m2, cross, out, HMLP, HMLP, HMLP, D_MODEL,
        0, 0, 0, 1.0f, 0);
}

// round 15
// speedup vs baseline: 9.0612x; 1.0150x over previous
#include <cuda_runtime.h>
#include <cuda_fp16.h>
#include <math.h>
#include <stdint.h>

#define D_MODEL 1024
#define BATCH   4
#define SEQ     1024
#define NHEADS  16
#define HDIM    64
#define HMLP    4096
#define ROWS    (BATCH*SEQ)     // 4096

// ---------------- scratch (device globals; no allocs allowed) ----------------
__device__ __half h_ln   [ROWS * D_MODEL];
__device__ __half h_qkv  [ROWS * 3 * D_MODEL];
__device__ __half h_kv   [ROWS * 2 * D_MODEL];
__device__ __half h_attn [ROWS * D_MODEL];
__device__ __half h_q    [ROWS * D_MODEL];
__device__ float  g_cross[ROWS * D_MODEL];
__device__ __half h_mlp  [ROWS * HMLP];
__device__ float  g_xs   [(size_t)BATCH * SEQ * SEQ];
__device__ __half h_p    [(size_t)BATCH * SEQ * SEQ];
__device__ __half h_z    [ROWS * D_MODEL];
__device__ __half h_wt_qkv[3 * D_MODEL * D_MODEL];
__device__ __half h_wt_o  [D_MODEL * D_MODEL];
__device__ __half h_wt_kv [2 * D_MODEL * D_MODEL];
__device__ __half h_wt_m1 [HMLP * D_MODEL];
__device__ __half h_wt_m2 [D_MODEL * HMLP];
__device__ __half h_vt_self [BATCH * NHEADS * HDIM * SEQ];
__device__ __half h_vt_cross[(size_t)BATCH * D_MODEL * SEQ];

__device__ __forceinline__ float gelu_tanh(float c) {
    float t = 0.7978845608028654f * (c + 0.044715f * c * c * c);
    return 0.5f * c * (1.0f + tanhf(t));
}
__device__ __forceinline__ void mma_f16(float* d, const uint32_t* a, const uint32_t* b) {
    asm volatile("mma.sync.aligned.m16n8k16.row.col.f32.f16.f16.f32 "
        "{%0,%1,%2,%3}, {%4,%5,%6,%7}, {%8,%9}, {%0,%1,%2,%3};"
        : "+f"(d[0]), "+f"(d[1]), "+f"(d[2]), "+f"(d[3])
        : "r"(a[0]), "r"(a[1]), "r"(a[2]), "r"(a[3]), "r"(b[0]), "r"(b[1]));
}
__device__ __forceinline__ void ldsm_x4(uint32_t& r0, uint32_t& r1, uint32_t& r2, uint32_t& r3,
                                        uint32_t addr) {
    asm volatile("ldmatrix.sync.aligned.m8n8.x4.shared.b16 {%0,%1,%2,%3}, [%4];"
        : "=r"(r0), "=r"(r1), "=r"(r2), "=r"(r3) : "r"(addr));
}
__device__ __forceinline__ void cp16(uint32_t smem, const void* g) {
    asm volatile("cp.async.cg.shared.global [%0], [%1], 16;" :: "r"(smem), "l"(g));
}
__device__ __forceinline__ uint32_t smem_u32(const void* p) {
    return (uint32_t)__cvta_generic_to_shared(p);
}
__device__ __forceinline__ void store2(__half* p, float a, float b) {
    *(__half2*)p = __floats2half2_rn(a, b);
}
__device__ __forceinline__ void store2(float* p, float a, float b) {
    float2 v; v.x = a; v.y = b; *(float2*)p = v;
}
__device__ __forceinline__ uint32_t packh2(float a, float b) {
    __half2 h = __floats2half2_rn(a, b);
    return *(uint32_t*)&h;
}

// ------------- single-pass layernorm (fp32 in -> fp16 out) + optional z cvt ----
__global__ void ln_kernel(const float* __restrict__ x, const float* __restrict__ g,
                          const float* __restrict__ b, __half* __restrict__ out,
                          const float* __restrict__ zsrc, __half* __restrict__ zdst) {
    int row = blockIdx.x;
    int tid = threadIdx.x;
    const float* xr = x + (size_t)row * D_MODEL;
    float4 v = *(const float4*)(xr + tid * 4);
    if (zsrc) {
        const float* zr = zsrc + (size_t)row * D_MODEL;
        __half* zo = zdst + (size_t)row * D_MODEL;
        float4 a = *(const float4*)(zr + tid * 4);
        __half2 h[2];
        h[0] = __floats2half2_rn(a.x, a.y); h[1] = __floats2half2_rn(a.z, a.w);
        *(uint2*)(zo + tid * 4) = *(uint2*)h;
    }
    float s  = v.x + v.y + v.z + v.w;
    float s2 = v.x * v.x + v.y * v.y + v.z * v.z + v.w * v.w;
    __shared__ float rs[8], rs2[8];
    for (int o = 16; o > 0; o >>= 1) {
        s  += __shfl_xor_sync(0xffffffff, s,  o);
        s2 += __shfl_xor_sync(0xffffffff, s2, o);
    }
    if ((tid & 31) == 0) { rs[tid >> 5] = s; rs2[tid >> 5] = s2; }
    __syncthreads();
    if (tid < 32) {
        float a  = (tid < 8) ? rs[tid]  : 0.f;
        float a2 = (tid < 8) ? rs2[tid] : 0.f;
        for (int o = 4; o > 0; o >>= 1) {
            a  += __shfl_xor_sync(0xffffffff, a,  o);
            a2 += __shfl_xor_sync(0xffffffff, a2, o);
        }
        rs[0] = a; rs2[0] = a2;
    }
    __syncthreads();
    float mu  = rs[0]  * (1.0f / D_MODEL);
    float var = rs2[0] * (1.0f / D_MODEL) - mu * mu;
    float inv = rsqrtf(var + 1e-5f);
    float4 gg = *(const float4*)(g + tid * 4);
    float4 bb = *(const float4*)(b + tid * 4);
    __half2 h[2];
    h[0] = __floats2half2_rn((v.x - mu) * inv * gg.x + bb.x,
                             (v.y - mu) * inv * gg.y + bb.y);
    h[1] = __floats2half2_rn((v.z - mu) * inv * gg.z + bb.z,
                             (v.w - mu) * inv * gg.w + bb.w);
    *(uint2*)(out + (size_t)row * D_MODEL + tid * 4) = *(uint2*)h;
}

// ---------------- softmax fp32 in -> fp16 out (cross) ----------------
__global__ void softmax_f2h(const float* __restrict__ S, __half* __restrict__ P) {
    const float* row = S + (size_t)blockIdx.x * 1024;
    __half* prow = P + (size_t)blockIdx.x * 1024;
    int tid = threadIdx.x;
    float4 v = *(const float4*)(row + tid * 4);
    float mx = fmaxf(fmaxf(v.x, v.y), fmaxf(v.z, v.w));
    __shared__ float red[32];
    for (int o = 16; o > 0; o >>= 1) mx = fmaxf(mx, __shfl_xor_sync(0xffffffff, mx, o));
    if ((tid & 31) == 0) red[tid >> 5] = mx;
    __syncthreads();
    if (tid < 32) {
        float m = (tid < 8) ? red[tid] : -1e30f;
        for (int o = 4; o > 0; o >>= 1) m = fmaxf(m, __shfl_xor_sync(0xffffffff, m, o));
        red[0] = m;
    }
    __syncthreads();
    mx = red[0];
    v.x = expf(v.x - mx); v.y = expf(v.y - mx); v.z = expf(v.z - mx); v.w = expf(v.w - mx);
    float s = v.x + v.y + v.z + v.w;
    for (int o = 16; o > 0; o >>= 1) s += __shfl_xor_sync(0xffffffff, s, o);
    __syncthreads();
    if ((tid & 31) == 0) red[tid >> 5] = s;
    __syncthreads();
    if (tid < 32) {
        float t = (tid < 8) ? red[tid] : 0.f;
        for (int o = 4; o > 0; o >>= 1) t += __shfl_xor_sync(0xffffffff, t, o);
        red[0] = t;
    }
    __syncthreads();
    float inv = 1.0f / red[0];
    __half2 h2[2];
    h2[0] = __floats2half2_rn(v.x * inv, v.y * inv);
    h2[1] = __floats2half2_rn(v.z * inv, v.w * inv);
    *(uint2*)(prow + tid * 4) = *(uint2*)h2;
}

// ---------------- fast 64x64 batched transpose (TS in -> half out) ------------
template <typename TS>
__device__ __forceinline__ void ld4h(const TS* p, __half* v);
template <>
__device__ __forceinline__ void ld4h<float>(const float* p, __half* v) {
    float4 f = *(const float4*)p;
    v[0] = __float2half(f.x); v[1] = __float2half(f.y);
    v[2] = __float2half(f.z); v[3] = __float2half(f.w);
}
template <>
__device__ __forceinline__ void ld4h<__half>(const __half* p, __half* v) {
    uint2 u = *(const uint2*)p;
    *(uint32_t*)&v[0] = u.x; *(uint32_t*)&v[2] = u.y;
}

template <typename TS>
__global__ void __launch_bounds__(256)
transpose64(const TS* __restrict__ srcb, __half* __restrict__ dstb,
            int lds, int ldd, long sSb, long sSh, long sDb, long sDh, int nh) {
    __shared__ __half tile[64][66];
    int z = blockIdx.z, b = z / nh, h = z - b * nh;
    const TS* src = srcb + (size_t)b * sSb + (size_t)h * sSh;
    __half* dst = dstb + (size_t)b * sDb + (size_t)h * sDh;
    int x0 = blockIdx.x * 64;
    int y0 = blockIdx.y * 64;
    int tx = threadIdx.x & 15, ty = threadIdx.x >> 4;
    #pragma unroll
    for (int i = 0; i < 4; i++) {
        int row = y0 + ty + i * 16;
        __half v[4];
        ld4h<TS>(src + (size_t)row * lds + x0 + tx * 4, v);
        tile[tx * 4 + 0][ty + i * 16] = v[0];
        tile[tx * 4 + 1][ty + i * 16] = v[1];
        tile[tx * 4 + 2][ty + i * 16] = v[2];
        tile[tx * 4 + 3][ty + i * 16] = v[3];
    }
    __syncthreads();
    #pragma unroll
    for (int i = 0; i < 4; i++) {
        int drow = x0 + ty + i * 16;
        __half2 p0, p1;
        p0.x = tile[ty + i * 16][tx * 4 + 0]; p0.y = tile[ty + i * 16][tx * 4 + 1];
        p1.x = tile[ty + i * 16][tx * 4 + 2]; p1.y = tile[ty + i * 16][tx * 4 + 3];
        uint2 o; o.x = *(uint32_t*)&p0; o.y = *(uint32_t*)&p1;
        *(uint2*)(dst + (size_t)drow * ldd + y0 + tx * 4) = o;
    }
}

// ========== flash self-attention v2: cp.async 3-stage ring + ldmatrix ==========
#define FLASH_SMEM (16384 + 3 * 16384)   // 65536 B

__global__ void __launch_bounds__(256)
flash_self(const __half* __restrict__ qkvg, const __half* __restrict__ vtsg,
           __half* __restrict__ attng) {
    extern __shared__ __align__(16) char fsmc[];
    uint32_t sq = smem_u32(fsmc);

    int tid = threadIdx.x, lane = tid & 31, warp = tid >> 5;
    int bh = blockIdx.y, b = bh >> 4, h = bh & 15;
    const __half* Qg = qkvg + (size_t)b * SEQ * 3 * D_MODEL
                     + (size_t)blockIdx.x * 128 * 3 * D_MODEL + h * HDIM;
    const __half* Kg = qkvg + (size_t)b * SEQ * 3 * D_MODEL + D_MODEL + h * HDIM;
    const __half* Vt = vtsg + (size_t)bh * HDIM * SEQ;
    __half* Og = attng + (size_t)b * SEQ * D_MODEL
               + (size_t)blockIdx.x * 128 * D_MODEL + h * HDIM;

    auto issue_kv = [&](int kb) {
        uint32_t base = sq + 16384 + (kb % 3) * 16384;
        #pragma unroll
        for (int i = 0; i < 2; i++) {
            int f = i * 256 + tid, row = f >> 3, ch = f & 7;
            uint32_t sw = (ch ^ (row & 7)) * 16;
            cp16(base + row * 128 + sw,
                 Kg + (size_t)(kb * 64 + row) * 3 * D_MODEL + ch * 8);
            cp16(base + 8192 + row * 128 + sw,
                 Vt + (size_t)row * SEQ + kb * 64 + ch * 8);
        }
        asm volatile("cp.async.commit_group;");
    };

    #pragma unroll
    for (int i = 0; i < 4; i++) {
        int f = i * 256 + tid, row = f >> 3, ch = f & 7;
        cp16(sq + row * 128 + ((ch ^ (row & 7)) * 16),
             Qg + (size_t)row * 3 * D_MODEL + ch * 8);
    }
    issue_kv(0);
    issue_kv(1);

    uint32_t qa[4][4];
    float oacc[8][4];
    #pragma unroll
    for (int ni = 0; ni < 8; ni++)
        #pragma unroll
        for (int c = 0; c < 4; c++) oacc[ni][c] = 0.f;
    float m0 = -1e30f, m1 = -1e30f, l0 = 0.f, l1 = 0.f;

    int frag_r = lane & 15;
    int csel = lane >> 4;
    int sw7 = frag_r & 7;

    for (int kb = 0; kb < 16; kb++) {
        if (kb < 15) asm volatile("cp.async.wait_group 1;");
        else         asm volatile("cp.async.wait_group 0;");
        __syncthreads();
        if (kb == 0) {
            int qr = warp * 16 + frag_r;
            #pragma unroll
            for (int kk = 0; kk < 4; kk++) {
                int ch = kk * 2 + csel;
                ldsm_x4(qa[kk][0], qa[kk][1], qa[kk][2], qa[kk][3],
                        sq + qr * 128 + ((ch ^ sw7) * 16));
            }
        }
        if (kb + 2 < 16) issue_kv(kb + 2);

        uint32_t kbase = sq + 16384 + (kb % 3) * 16384;
        uint32_t vbase = kbase + 8192;

        float sacc[8][4];
        #pragma unroll
        for (int ni = 0; ni < 8; ni++)
            #pragma unroll
            for (int c = 0; c < 4; c++) sacc[ni][c] = 0.f;
        #pragma unroll
        for (int kk = 0; kk < 4; kk++) {
            int ch = kk * 2 + csel;
            uint32_t breg[4][4];
            #pragma unroll
            for (int p = 0; p < 4; p++) {
                int r = p * 16 + frag_r;
                ldsm_x4(breg[p][0], breg[p][1], breg[p][2], breg[p][3],
                        kbase + r * 128 + ((ch ^ sw7) * 16));
            }
            #pragma unroll
            for (int ni = 0; ni < 8; ni++) {
                uint32_t bfr[2] = { breg[ni >> 1][ni & 1], breg[ni >> 1][(ni & 1) + 2] };
                mma_f16(sacc[ni], qa[kk], bfr);
            }
        }

        float mx0 = -1e30f, mx1 = -1e30f;
        #pragma unroll
        for (int ni = 0; ni < 8; ni++) {
            mx0 = fmaxf(mx0, fmaxf(sacc[ni][0], sacc[ni][1]));
            mx1 = fmaxf(mx1, fmaxf(sacc[ni][2], sacc[ni][3]));
        }
        mx0 = fmaxf(mx0, __shfl_xor_sync(0xffffffff, mx0, 1));
        mx0 = fmaxf(mx0, __shfl_xor_sync(0xffffffff, mx0, 2));
        mx1 = fmaxf(mx1, __shfl_xor_sync(0xffffffff, mx1, 1));
        mx1 = fmaxf(mx1, __shfl_xor_sync(0xffffffff, mx1, 2));
        float nm0 = fmaxf(m0, mx0 * 0.125f);
        float nm1 = fmaxf(m1, mx1 * 0.125f);
        float a0 = __expf(m0 - nm0);
        float a1 = __expf(m1 - nm1);
        m0 = nm0; m1 = nm1;

        uint32_t pw0[8], pw1[8];
        float s0 = 0.f, s1 = 0.f;
        #pragma unroll
        for (int ni = 0; ni < 8; ni++) {
            float p0 = __expf(sacc[ni][0] * 0.125f - nm0);
            float p1 = __expf(sacc[ni][1] * 0.125f - nm0);
            float p2 = __expf(sacc[ni][2] * 0.125f - nm1);
            float p3 = __expf(sacc[ni][3] * 0.125f - nm1);
            s0 += p0 + p1; s1 += p2 + p3;
            pw0[ni] = packh2(p0, p1);
            pw1[ni] = packh2(p2, p3);
        }
        s0 += __shfl_xor_sync(0xffffffff, s0, 1);
        s0 += __shfl_xor_sync(0xffffffff, s0, 2);
        s1 += __shfl_xor_sync(0xffffffff, s1, 1);
        s1 += __shfl_xor_sync(0xffffffff, s1, 2);
        l0 = l0 * a0 + s0;
        l1 = l1 * a1 + s1;
        #pragma unroll
        for (int ni = 0; ni < 8; ni++) {
            oacc[ni][0] *= a0; oacc[ni][1] *= a0;
            oacc[ni][2] *= a1; oacc[ni][3] *= a1;
        }

        #pragma unroll
        for (int kp = 0; kp < 4; kp++) {
            int ch = kp * 2 + csel;
            uint32_t pa[4] = { pw0[2 * kp], pw1[2 * kp], pw0[2 * kp + 1], pw1[2 * kp + 1] };
            uint32_t breg[4][4];
            #pragma unroll
            for (int p = 0; p < 4; p++) {
                int r = p * 16 + frag_r;
                ldsm_x4(breg[p][0], breg[p][1], breg[p][2], breg[p][3],
                        vbase + r * 128 + ((ch ^ sw7) * 16));
            }
            #pragma unroll
            for (int ni = 0; ni < 8; ni++) {
                uint32_t bfr[2] = { breg[ni >> 1][ni & 1], breg[ni >> 1][(ni & 1) + 2] };
                mma_f16(oacc[ni], pa, bfr);
            }
        }
    }

    float i0 = 1.0f / l0, i1 = 1.0f / l1;
    int r = warp * 16 + (lane >> 2);
    #pragma unroll
    for (int ni = 0; ni < 8; ni++) {
        int col = ni * 8 + 2 * (lane & 3);
        store2(Og + (size_t)r * D_MODEL + col,       oacc[ni][0] * i0, oacc[ni][1] * i0);
        store2(Og + (size_t)(r + 8) * D_MODEL + col, oacc[ni][2] * i1, oacc[ni][3] * i1);
    }
}

// ======= fp16 GEMM: cp.async + swizzle + ldmatrix, 128 x TN tile (TN=256|128) ==
#define NSTAGE 4
#define A_BYTES 16384

template <typename CT, int TN>
__global__ void __launch_bounds__(256)
mm2(const __half* __restrict__ Abase, const __half* __restrict__ Bbase,
    const float* __restrict__ bias, const float* __restrict__ resbase,
    CT* __restrict__ Cbase, int K, int lda, int ldb, int ldc,
    long sAb, long sBb, long sCb, float scale, int act) {
    constexpr int B_BYTES = TN * 128;
    constexpr int STAGEB  = A_BYTES + B_BYTES;
    constexpr int WNT = TN / 4;
    constexpr int PB  = WNT / 16;
    constexpr int NI  = WNT / 8;
    constexpr int NBLD = TN / 32;

    extern __shared__ __align__(16) char smc[];
    uint32_t sb = smem_u32(smc);

    int tid = threadIdx.x, lane = tid & 31, warp = tid >> 5;
    int wy = warp & 1, wx = warp >> 1;
    int z = blockIdx.z;
    const __half* A = Abase + (size_t)z * sAb + (size_t)blockIdx.y * 128 * lda;
    const __half* B = Bbase + (size_t)z * sBb + (size_t)blockIdx.x * TN * ldb;
    CT* C = Cbase + (size_t)z * sCb;
    const float* res = resbase ? resbase + (size_t)z * sCb : nullptr;
    int m0 = blockIdx.y * 128, n0 = blockIdx.x * TN;

    float acc[4][NI][4];
    #pragma unroll
    for (int mi = 0; mi < 4; mi++)
        #pragma unroll
        for (int ni = 0; ni < NI; ni++)
            #pragma unroll
            for (int c = 0; c < 4; c++) acc[mi][ni][c] = 0.f;

    int lrow = tid >> 3;
    int lc   = tid & 7;
    auto issue_stage = [&](int kb, int stage) {
        uint32_t as = sb + stage * STAGEB;
        uint32_t bs = as + A_BYTES;
        int koff = kb * 64 + lc * 8;
        #pragma unroll
        for (int i = 0; i < 4; i++) {
            int row = lrow + i * 32;
            cp16(as + row * 128 + ((lc ^ (row & 7)) * 16),
                 A + (size_t)row * lda + koff);
        }
        #pragma unroll
        for (int i = 0; i < NBLD; i++) {
            int row = lrow + i * 32;
            cp16(bs + row * 128 + ((lc ^ (row & 7)) * 16),
                 B + (size_t)row * ldb + koff);
        }
        asm volatile("cp.async.commit_group;");
    };

    int nkb = K >> 6;
    issue_stage(0, 0);
    issue_stage(1, 1);
    if (nkb > 2) issue_stage(2, 2);
    else asm volatile("cp.async.commit_group;");

    int arow = wy * 64 + (lane & 15);
    int brow = wx * WNT + (lane & 15);
    int csel = lane >> 4;

    for (int kb = 0; kb < nkb; kb++) {
        asm volatile("cp.async.wait_group 2;");
        __syncthreads();
        int stage = kb % NSTAGE;
        if (kb + 3 < nkb) issue_stage(kb + 3, (kb + 3) % NSTAGE);
        else asm volatile("cp.async.commit_group;");

        uint32_t as = sb + stage * STAGEB;
        uint32_t bs = as + A_BYTES;
        #pragma unroll
        for (int kk = 0; kk < 4; kk++) {
            int ch = kk * 2 + csel;
            uint32_t afr[4][4], breg[PB][4];
            #pragma unroll
            for (int mi = 0; mi < 4; mi++) {
                int r = arow + mi * 16;
                ldsm_x4(afr[mi][0], afr[mi][1], afr[mi][2], afr[mi][3],
                        as + r * 128 + ((ch ^ (r & 7)) * 16));
            }
            #pragma unroll
            for (int p = 0; p < PB; p++) {
                int r = brow + p * 16;
                ldsm_x4(breg[p][0], breg[p][1], breg[p][2], breg[p][3],
                        bs + r * 128 + ((ch ^ (r & 7)) * 16));
            }
            #pragma unroll
            for (int mi = 0; mi < 4; mi++)
                #pragma unroll
                for (int ni = 0; ni < NI; ni++) {
                    uint32_t bfr[2] = { breg[ni >> 1][ni & 1], breg[ni >> 1][(ni & 1) + 2] };
                    mma_f16(acc[mi][ni], afr[mi], bfr);
                }
        }
    }

    #pragma unroll
    for (int mi = 0; mi < 4; mi++) {
        #pragma unroll
        for (int ni = 0; ni < NI; ni++) {
            int col = n0 + wx * WNT + ni * 8 + 2 * (lane & 3);
            #pragma unroll
            for (int half = 0; half < 2; half++) {
                int row = m0 + wy * 64 + mi * 16 + (lane >> 2) + half * 8;
                float c0 = acc[mi][ni][2 * half]     * scale;
                float c1 = acc[mi][ni][2 * half + 1] * scale;
                if (bias) { c0 += bias[col]; c1 += bias[col + 1]; }
                if (act == 1) { c0 = gelu_tanh(c0); c1 = gelu_tanh(c1); }
                if (res) {
                    float2 rv = *(const float2*)(res + (size_t)row * ldc + col);
                    c0 += rv.x; c1 += rv.y;
                }
                store2(C + (size_t)row * ldc + col, c0, c1);
            }
        }
    }
}

#define SMEM_T(TN) (NSTAGE * (A_BYTES + (TN) * 128))

// ======= mm3: 64x64 tile, 128 threads, 2x2 warps (warp tile 32x32) ===========
// For GEMMs whose tile count underfills the chip at 128x256 (wave quantization).
#define A3_BYTES 8192
#define STAGE3   (A3_BYTES + 8192)
#define SMEM3    (NSTAGE * STAGE3)   // 65536

template <typename CT>
__global__ void __launch_bounds__(128)
mm3(const __half* __restrict__ Abase, const __half* __restrict__ Bbase,
    const float* __restrict__ bias, const float* __restrict__ resbase,
    CT* __restrict__ Cbase, int K, int lda, int ldb, int ldc,
    long sAb, long sBb, long sCb, float scale, int act) {
    extern __shared__ __align__(16) char smc[];
    uint32_t sb = smem_u32(smc);

    int tid = threadIdx.x, lane = tid & 31, warp = tid >> 5;
    int wy = warp & 1, wx = warp >> 1;       // 2x2 warp grid; warp tile 32x32
    int z = blockIdx.z;
    const __half* A = Abase + (size_t)z * sAb + (size_t)blockIdx.y * 64 * lda;
    const __half* B = Bbase + (size_t)z * sBb + (size_t)blockIdx.x * 64 * ldb;
    CT* C = Cbase + (size_t)z * sCb;
    const float* res = resbase ? resbase + (size_t)z * sCb : nullptr;
    int m0 = blockIdx.y * 64, n0 = blockIdx.x * 64;

    float acc[2][4][4];
    #pragma unroll
    for (int mi = 0; mi < 2; mi++)
        #pragma unroll
        for (int ni = 0; ni < 4; ni++)
            #pragma unroll
            for (int c = 0; c < 4; c++) acc[mi][ni][c] = 0.f;

    int lrow = tid >> 3;          // 0..15
    int lc   = tid & 7;
    auto issue_stage = [&](int kb, int stage) {
        uint32_t as = sb + stage * STAGE3;
        uint32_t bs = as + A3_BYTES;
        int koff = kb * 64 + lc * 8;
        #pragma unroll
        for (int i = 0; i < 4; i++) {
            int row = lrow + i * 16;
            cp16(as + row * 128 + ((lc ^ (row & 7)) * 16),
                 A + (size_t)row * lda + koff);
        }
        #pragma unroll
        for (int i = 0; i < 4; i++) {
            int row = lrow + i * 16;
            cp16(bs + row * 128 + ((lc ^ (row & 7)) * 16),
                 B + (size_t)row * ldb + koff);
        }
        asm volatile("cp.async.commit_group;");
    };

    int nkb = K >> 6;
    issue_stage(0, 0);
    issue_stage(1, 1);
    if (nkb > 2) issue_stage(2, 2);
    else asm volatile("cp.async.commit_group;");

    int arow = wy * 32 + (lane & 15);
    int brow = wx * 32 + (lane & 15);
    int csel = lane >> 4;

    for (int kb = 0; kb < nkb; kb++) {
        asm volatile("cp.async.wait_group 2;");
        __syncthreads();
        int stage = kb % NSTAGE;
        if (kb + 3 < nkb) issue_stage(kb + 3, (kb + 3) % NSTAGE);
        else asm volatile("cp.async.commit_group;");

        uint32_t as = sb + stage * STAGE3;
        uint32_t bs = as + A3_BYTES;
        #pragma unroll
        for (int kk = 0; kk < 4; kk++) {
            int ch = kk * 2 + csel;
            uint32_t afr[2][4], breg[2][4];
            #pragma unroll
            for (int mi = 0; mi < 2; mi++) {
                int r = arow + mi * 16;
                ldsm_x4(afr[mi][0], afr[mi][1], afr[mi][2], afr[mi][3],
                        as + r * 128 + ((ch ^ (r & 7)) * 16));
            }
            #pragma unroll
            for (int p = 0; p < 2; p++) {
                int r = brow + p * 16;
                ldsm_x4(breg[p][0], breg[p][1], breg[p][2], breg[p][3],
                        bs + r * 128 + ((ch ^ (r & 7)) * 16));
            }
            #pragma unroll
            for (int mi = 0; mi < 2; mi++)
                #pragma unroll
                for (int ni = 0; ni < 4; ni++) {
                    uint32_t bfr[2] = { breg[ni >> 1][ni & 1], breg[ni >> 1][(ni & 1) + 2] };
                    mma_f16(acc[mi][ni], afr[mi], bfr);
                }
        }
    }

    #pragma unroll
    for (int mi = 0; mi < 2; mi++) {
        #pragma unroll
        for (int ni = 0; ni < 4; ni++) {
            int col = n0 + wx * 32 + ni * 8 + 2 * (lane & 3);
            #pragma unroll
            for (int half = 0; half < 2; half++) {
                int row = m0 + wy * 32 + mi * 16 + (lane >> 2) + half * 8;
                float c0 = acc[mi][ni][2 * half]     * scale;
                float c1 = acc[mi][ni][2 * half + 1] * scale;
                if (bias) { c0 += bias[col]; c1 += bias[col + 1]; }
                if (act == 1) { c0 = gelu_tanh(c0); c1 = gelu_tanh(c1); }
                if (res) {
                    float2 rv = *(const float2*)(res + (size_t)row * ldc + col);
                    c0 += rv.x; c1 += rv.y;
                }
                store2(C + (size_t)row * ldc + col, c0, c1);
            }
        }
    }
}

// ---------------- host launch ----------------
extern "C" void kernel_launch(void* const* d_in, const int* in_sizes, int n_in,
                              void* d_out, int out_size) {
    const float* x     = (const float*)d_in[0];
    const float* zin   = (const float*)d_in[1];
    const float* g1    = (const float*)d_in[2];
    const float* b1    = (const float*)d_in[3];
    const float* w_qkv = (const float*)d_in[4];
    const float* b_qkv = (const float*)d_in[5];
    const float* w_o   = (const float*)d_in[6];
    const float* b_o   = (const float*)d_in[7];
    const float* w_kv  = (const float*)d_in[8];
    const float* b_kv  = (const float*)d_in[9];
    const float* g2    = (const float*)d_in[10];
    const float* b2    = (const float*)d_in[11];
    const float* w_m1  = (const float*)d_in[12];
    const float* b_m1  = (const float*)d_in[13];
    const float* w_m2  = (const float*)d_in[14];
    const float* b_m2  = (const float*)d_in[15];
    float* out = (float*)d_out;

    __half *ln, *qkv, *kv, *attn, *q, *mlp, *p, *z16;
    __half *wtqkv, *wto, *wtkv, *wtm1, *wtm2, *vts, *vtc;
    float *cross, *xs;
    cudaGetSymbolAddress((void**)&ln,     h_ln);
    cudaGetSymbolAddress((void**)&qkv,    h_qkv);
    cudaGetSymbolAddress((void**)&kv,     h_kv);
    cudaGetSymbolAddress((void**)&attn,   h_attn);
    cudaGetSymbolAddress((void**)&q,      h_q);
    cudaGetSymbolAddress((void**)&cross,  g_cross);
    cudaGetSymbolAddress((void**)&mlp,    h_mlp);
    cudaGetSymbolAddress((void**)&xs,     g_xs);
    cudaGetSymbolAddress((void**)&p,      h_p);
    cudaGetSymbolAddress((void**)&z16,    h_z);
    cudaGetSymbolAddress((void**)&wtqkv,  h_wt_qkv);
    cudaGetSymbolAddress((void**)&wto,    h_wt_o);
    cudaGetSymbolAddress((void**)&wtkv,   h_wt_kv);
    cudaGetSymbolAddress((void**)&wtm1,   h_wt_m1);
    cudaGetSymbolAddress((void**)&wtm2,   h_wt_m2);
    cudaGetSymbolAddress((void**)&vts,    h_vt_self);
    cudaGetSymbolAddress((void**)&vtc,    h_vt_cross);

    cudaFuncSetAttribute((const void*)mm2<__half, 256>, cudaFuncAttributeMaxDynamicSharedMemorySize, SMEM_T(256));
    cudaFuncSetAttribute((const void*)mm2<__half, 128>, cudaFuncAttributeMaxDynamicSharedMemorySize, SMEM_T(128));
    cudaFuncSetAttribute((const void*)mm3<__half>, cudaFuncAttributeMaxDynamicSharedMemorySize, SMEM3);
    cudaFuncSetAttribute((const void*)mm3<float>,  cudaFuncAttributeMaxDynamicSharedMemorySize, SMEM3);
    cudaFuncSetAttribute((const void*)flash_self,  cudaFuncAttributeMaxDynamicSharedMemorySize, FLASH_SMEM);

    cudaStream_t s2;
    cudaStreamCreateWithFlags(&s2, cudaStreamNonBlocking);
    cudaEvent_t evStart, evZ, evWQ, evWO, evKV, evW;
    cudaEventCreateWithFlags(&evStart, cudaEventDisableTiming);
    cudaEventCreateWithFlags(&evZ,  cudaEventDisableTiming);
    cudaEventCreateWithFlags(&evWQ, cudaEventDisableTiming);
    cudaEventCreateWithFlags(&evWO, cudaEventDisableTiming);
    cudaEventCreateWithFlags(&evKV, cudaEventDisableTiming);
    cudaEventCreateWithFlags(&evW,  cudaEventDisableTiming);

    // ---- fork: side stream joins capture via event-wait on origin stream ----
    cudaEventRecord(evStart, 0);
    cudaStreamWaitEvent(s2, evStart, 0);

    // ---- main: ln1 (overlaps wtqkv on s2) ----
    ln_kernel<<<ROWS, 256>>>(x, g1, b1, ln, zin, z16);
    cudaEventRecord(evZ, 0);

    // ---- side stream: wtqkv first, then w_o, kv chain, mlp weights ----
    transpose64<float><<<dim3(48, 16, 1), 256, 0, s2>>>(w_qkv, wtqkv, 3 * D_MODEL, D_MODEL, 0, 0, 0, 0, 1);
    cudaEventRecord(evWQ, s2);
    transpose64<float><<<dim3(16, 16, 1), 256, 0, s2>>>(w_o, wto, D_MODEL, D_MODEL, 0, 0, 0, 0, 1);
    cudaEventRecord(evWO, s2);
    transpose64<float><<<dim3(32, 16, 1), 256, 0, s2>>>(w_kv, wtkv, 2 * D_MODEL, D_MODEL, 0, 0, 0, 0, 1);
    cudaStreamWaitEvent(s2, evZ, 0);
    mm2<__half, 256><<<dim3(8, 32, 1), 256, SMEM_T(256), s2>>>(
        z16, wtkv, b_kv, nullptr, kv, D_MODEL, D_MODEL, D_MODEL, 2 * D_MODEL,
        0, 0, 0, 1.0f, 0);
    transpose64<__half><<<dim3(16, 16, BATCH), 256, 0, s2>>>(
        kv + D_MODEL, vtc, 2 * D_MODEL, SEQ,
        (long)SEQ * 2 * D_MODEL, 0, (long)D_MODEL * SEQ, 0, 1);
    cudaEventRecord(evKV, s2);
    transpose64<float><<<dim3(64, 16, 1), 256, 0, s2>>>(w_m1, wtm1, HMLP, D_MODEL, 0, 0, 0, 0, 1);
    transpose64<float><<<dim3(16, 64, 1), 256, 0, s2>>>(w_m2, wtm2, D_MODEL, HMLP, 0, 0, 0, 0, 1);
    cudaEventRecord(evW, s2);

    // ---- main: q chain ----
    cudaStreamWaitEvent(0, evWQ, 0);
    mm2<__half, 256><<<dim3(12, 32, 1), 256, SMEM_T(256)>>>(
        ln, wtqkv, b_qkv, nullptr, qkv, D_MODEL, D_MODEL, D_MODEL, 3 * D_MODEL,
        0, 0, 0, 1.0f, 0);

    transpose64<__half><<<dim3(1, 16, BATCH * NHEADS), 256>>>(
        qkv + 2 * D_MODEL, vts, 3 * D_MODEL, SEQ,
        (long)SEQ * 3 * D_MODEL, HDIM, (long)NHEADS * HDIM * SEQ, (long)HDIM * SEQ, NHEADS);

    flash_self<<<dim3(8, BATCH * NHEADS), 256, FLASH_SMEM>>>(qkv, vts, attn);

    cudaStreamWaitEvent(0, evWO, 0);
    // w_o: 64x64 tiles -> 1024 tiles (6.92 waves)
    mm3<__half><<<dim3(16, 64, 1), 128, SMEM3>>>(
        attn, wto, b_o, x, q, D_MODEL, D_MODEL, D_MODEL, D_MODEL,
        0, 0, 0, 1.0f, 0);

    cudaStreamWaitEvent(0, evKV, 0);
    // cross scores: 64x64 tiles -> 1024 tiles
    mm3<float><<<dim3(16, 16, BATCH), 128, SMEM3>>>(
        q, kv, nullptr, nullptr, xs, D_MODEL, D_MODEL, 2 * D_MODEL, SEQ,
        (long)SEQ * D_MODEL, (long)SEQ * 2 * D_MODEL, (long)SEQ * SEQ, 0.03125f, 0);

    softmax_f2h<<<BATCH * SEQ, 256>>>(xs, p);

    // cross PV: 64x64 tiles -> 1024 tiles
    mm3<float><<<dim3(16, 16, BATCH), 128, SMEM3>>>(
        p, vtc, nullptr, nullptr, cross, SEQ, SEQ, SEQ, D_MODEL,
        (long)SEQ * SEQ, (long)D_MODEL * SEQ, (long)SEQ * D_MODEL, 1.0f, 0);

    ln_kernel<<<ROWS, 256>>>(cross, g2, b2, ln, nullptr, nullptr);

    cudaStreamWaitEvent(0, evW, 0);
    // mlp1: 128x128 tiles -> 1024 tiles (6.92 waves)
    mm2<__half, 128><<<dim3(32, 32, 1), 256, SMEM_T(128)>>>(
        ln, wtm1, b_m1, nullptr, mlp, D_MODEL, D_MODEL, D_MODEL, HMLP,
        0, 0, 0, 1.0f, 1);

    // mlp2: 64x64 tiles -> 1024 tiles (6.92 waves; kills the 128-tile underfill)
    mm3<float><<<dim3(16, 64, 1), 128, SMEM3>>>(
        mlp, wtm2, b_m2, cross, out, HMLP, HMLP, HMLP, D_MODEL,
        0, 0, 0, 1.0f, 0);
}